// round 3
// baseline (speedup 1.0000x reference)
#include <cuda_runtime.h>
#include <math.h>

#define NN 10
#define CC 512
#define HW 1600
#define OC 128
#define IMG 40
#define MROWS 1280   // 1152 folded-conv1 rows + 128 shortcut rows

// ---------------- scratch (device globals) ----------------
__device__ float g_NF[NN*CC*HW];
__device__ float g_Ag[NN*CC*HW];
__device__ float g_SIVraw[NN*CC];
__device__ float g_SIV[NN*CC];
__device__ float g_cm[NN*NN*HW];
__device__ float g_corr[NN*NN*NN];
__device__ float g_sv[NN*NN];
__device__ float g_wv[NN*NN];
__device__ float g_CSA[NN*HW];
__device__ int   g_idx[NN*HW];
__device__ float g_Wcat[MROWS*HW];      // rows 0..1151: w1 transposed [(o*9+t)][i]; rows 1152..1279: ws [o][i]
__device__ float g_W2t[OC*9*OC];        // [(o*9+t)][c]
__device__ float g_WtAll[NN*MROWS*CC];  // folded weights per image
__device__ float g_H1[NN*OC*HW];
__device__ float g_SC[NN*OC*HW];

// ---------------- helpers ----------------
__device__ __forceinline__ double blockReduceSumD(double v) {
    __shared__ double sh[32];
    int lane = threadIdx.x & 31, wid = threadIdx.x >> 5;
#pragma unroll
    for (int o = 16; o > 0; o >>= 1) v += __shfl_down_sync(0xffffffffu, v, o);
    if (lane == 0) sh[wid] = v;
    __syncthreads();
    if (wid == 0) {
        int nw = blockDim.x >> 5;
        v = (lane < nw) ? sh[lane] : 0.0;
#pragma unroll
        for (int o = 16; o > 0; o >>= 1) v += __shfl_down_sync(0xffffffffu, v, o);
    }
    return v;
}

__device__ __forceinline__ unsigned long long dup2(float x) {
    unsigned u = __float_as_uint(x);
    return ((unsigned long long)u << 32) | (unsigned long long)u;
}
#define FFMA2(d, a, b) asm("fma.rn.f32x2 %0, %1, %2, %0;" : "+l"(d) : "l"(a), "l"(b))
__device__ __forceinline__ float lo32(unsigned long long v) { return __uint_as_float((unsigned)v); }
__device__ __forceinline__ float hi32(unsigned long long v) { return __uint_as_float((unsigned)(v >> 32)); }

// ---------------- 1: per-pixel L2 norm over C (parallel over 4 c-groups) ----------
__global__ void k_norm(const float* __restrict__ feats) {
    int n = blockIdx.y;
    int tid = threadIdx.x;
    int cg = tid >> 6, kk = tid & 63;
    int hw = blockIdx.x * 64 + kk;
    const float* f = feats + (size_t)n * CC * HW + hw;
    double ss = 0.0;
    for (int c = cg * 128; c < cg * 128 + 128; c++) {
        float v = f[(size_t)c * HW];
        float sq = v * v;
        ss += (double)sq;
    }
    __shared__ double sh[4][64];
    __shared__ float sd[64];
    sh[cg][kk] = ss;
    __syncthreads();
    if (tid < 64) {
        double S = sh[0][tid] + sh[1][tid] + sh[2][tid] + sh[3][tid];
        sd[tid] = fmaxf(sqrtf((float)S), 1e-12f);
    }
    __syncthreads();
    float d = sd[kk];
    float* o = g_NF + (size_t)n * CC * HW + hw;
    for (int c = cg * 128; c < cg * 128 + 128; c++)
        o[(size_t)c * HW] = f[(size_t)c * HW] / d;
}

// ---------------- 2: SIV raw = mean over hw of NF*SISM ----------------
__global__ void k_siv_raw(const float* __restrict__ sisms) {
    int b = blockIdx.x;              // n*CC + c
    int n = b >> 9;
    double s = 0.0;
    for (int k = threadIdx.x; k < HW; k += 256) {
        float pm = g_NF[(size_t)b * HW + k] * sisms[n * HW + k];
        s += (double)pm;
    }
    s = blockReduceSumD(s);
    if (threadIdx.x == 0) g_SIVraw[b] = ((float)s) / 1600.0f;
}

// ---------------- 3: SIV l2 norm over C ----------------
__global__ void k_siv_norm() {
    int n = blockIdx.x, t = threadIdx.x;
    float v = g_SIVraw[n * CC + t];
    float sq = v * v;
    double s = blockReduceSumD((double)sq);
    __shared__ float s_d;
    if (t == 0) s_d = fmaxf(sqrtf((float)s), 1e-12f);
    __syncthreads();
    g_SIV[n * CC + t] = v / s_d;
}

// ---------------- 4: cm[n][m][k] = sum_c NF[n,c,k]*SIV[m,c] (fp64, 4-way split) ---
__global__ void k_cm() {
    __shared__ float s_siv[NN * CC];
    __shared__ double sh[4][64][NN];
    int n = blockIdx.y;
    int tid = threadIdx.x;
    for (int q = tid; q < NN * CC; q += 256) s_siv[q] = g_SIV[q];
    int cg = tid >> 6, kk = tid & 63;
    int k = blockIdx.x * 64 + kk;
    const float* nfp = g_NF + (size_t)n * CC * HW + k;
    __syncthreads();
    double acc[NN];
#pragma unroll
    for (int m = 0; m < NN; m++) acc[m] = 0.0;
    for (int c = cg * 128; c < cg * 128 + 128; c++) {
        double nf = (double)nfp[(size_t)c * HW];
#pragma unroll
        for (int m = 0; m < NN; m++) acc[m] += nf * (double)s_siv[m * CC + c];
    }
#pragma unroll
    for (int m = 0; m < NN; m++) sh[cg][kk][m] = acc[m];
    __syncthreads();
    for (int e = tid; e < 64 * NN; e += 256) {
        int kk2 = e / NN, m = e % NN;
        double s = sh[0][kk2][m] + sh[1][kk2][m] + sh[2][kk2][m] + sh[3][kk2][m];
        g_cm[(size_t)(n * NN + m) * HW + blockIdx.x * 64 + kk2] = (float)s;
    }
}

// ---------------- 5: l2-normalize each cm row over k ----------------
__global__ void k_cm_norm() {
    int row = blockIdx.x;
    size_t base = (size_t)row * HW;
    double ss = 0.0;
    for (int k = threadIdx.x; k < HW; k += 256) {
        float v = g_cm[base + k];
        float sq = v * v;
        ss += (double)sq;
    }
    ss = blockReduceSumD(ss);
    __shared__ float s_d;
    if (threadIdx.x == 0) s_d = fmaxf(sqrtf((float)ss), 1e-12f);
    __syncthreads();
    for (int k = threadIdx.x; k < HW; k += 256) g_cm[base + k] = g_cm[base + k] / s_d;
}

// ---------------- 6: corr[n][m][p] = dot(cm[n][m], cm[n][p]) ----------------
__global__ void k_corr() {
    int b = blockIdx.x;            // n*100 + m*10 + p
    int p = b % NN;
    int m = (b / NN) % NN;
    int n = b / (NN * NN);
    double s = 0.0;
    for (int k = threadIdx.x; k < HW; k += 256)
        s += (double)g_cm[(size_t)(n * NN + m) * HW + k] * (double)g_cm[(size_t)(n * NN + p) * HW + k];
    s = blockReduceSumD(s);
    if (threadIdx.x == 0) g_corr[b] = (float)s;
}

// ---------------- 7: sv[n][m] = sum_p corr ----------------
__global__ void k_sv() {
    int t = threadIdx.x;
    if (t >= NN * NN) return;
    double s = 0.0;
#pragma unroll
    for (int p = 0; p < NN; p++) s += (double)g_corr[t * NN + p];
    g_sv[t] = (float)s;
}

// ---------------- 8: softmax over m ----------------
__global__ void k_softmax() {
    int n = threadIdx.x;
    if (n >= NN) return;
    float mx = -1e30f;
    for (int m = 0; m < NN; m++) mx = fmaxf(mx, g_sv[n * NN + m]);
    float e[NN];
    double sum = 0.0;
    for (int m = 0; m < NN; m++) {
        float t = g_sv[n * NN + m] - mx;
        e[m] = (float)exp((double)t);
        sum += (double)e[m];
    }
    float S = (float)sum;
    for (int m = 0; m < NN; m++) g_wv[n * NN + m] = e[m] / S;
}

// ---------------- 9: CSA + min-max normalize ----------------
__global__ void k_csa() {
    int n = blockIdx.x, tid = threadIdx.x;
    __shared__ float s_wv[NN];
    __shared__ float sc[HW];
    __shared__ float red[512];
    if (tid < NN) s_wv[tid] = g_wv[n * NN + tid];
    __syncthreads();
    float lmin = 1e30f, lmax = -1e30f;
    for (int k = tid; k < HW; k += 512) {
        double a = 0.0;
#pragma unroll
        for (int m = 0; m < NN; m++) {
            float pm = g_cm[(size_t)(n * NN + m) * HW + k] * s_wv[m];
            a += (double)pm;
        }
        float raw = (float)a;
        sc[k] = raw;
        lmin = fminf(lmin, raw); lmax = fmaxf(lmax, raw);
    }
    red[tid] = lmin; __syncthreads();
    for (int s = 256; s > 0; s >>= 1) { if (tid < s) red[tid] = fminf(red[tid], red[tid + s]); __syncthreads(); }
    float mn = red[0]; __syncthreads();
    red[tid] = lmax; __syncthreads();
    for (int s = 256; s > 0; s >>= 1) { if (tid < s) red[tid] = fmaxf(red[tid], red[tid + s]); __syncthreads(); }
    float mx = red[0]; __syncthreads();
    float den = (mx - mn) + 1e-12f;
    for (int k = tid; k < HW; k += 512) {
        float num = sc[k] - mn;
        g_CSA[n * HW + k] = num / den;
    }
}

// ---------------- 10: stable argsort descending (bitonic 2048) ----------------
__global__ void k_sort() {
    __shared__ float key[2048];
    __shared__ int   idv[2048];
    int n = blockIdx.x, tid = threadIdx.x;
    for (int e = tid; e < 2048; e += 1024) {
        if (e < HW) { key[e] = g_CSA[n * HW + e]; idv[e] = e; }
        else        { key[e] = -1e30f;            idv[e] = e; }
    }
    __syncthreads();
    for (int k = 2; k <= 2048; k <<= 1) {
        for (int j = k >> 1; j > 0; j >>= 1) {
            for (int e = tid; e < 2048; e += 1024) {
                int ix = e ^ j;
                if (ix > e) {
                    float ka = key[e], kb = key[ix];
                    int ia = idv[e], ib = idv[ix];
                    bool up = ((e & k) == 0);
                    bool b_before_a = (kb > ka) || (kb == ka && ib < ia);
                    bool dosw = up ? b_before_a : !b_before_a;
                    if (dosw) { key[e] = kb; key[ix] = ka; idv[e] = ib; idv[ix] = ia; }
                }
            }
            __syncthreads();
        }
    }
    for (int e = tid; e < HW; e += 1024) g_idx[n * HW + e] = idv[e];
}

// ---------------- 11: gather Ag[n][c][i] = NF[n][c][idx[n][i]] ----------------
__global__ void k_gather() {
    int b = blockIdx.x;       // n*CC+c
    int n = b >> 9;
    for (int i = threadIdx.x; i < HW; i += 256)
        g_Ag[(size_t)b * HW + i] = g_NF[(size_t)b * HW + g_idx[n * HW + i]];
}

// ---------------- 12: build concatenated weight matrix [1280 x 1600] -----------
__global__ void k_wcat(const float* __restrict__ w1, const float* __restrict__ ws) {
    int q = blockIdx.x * 256 + threadIdx.x;
    if (q >= MROWS * HW) return;
    int i = q % HW, r = q / HW;
    if (r < OC * 9) {
        int o = r / 9, t = r % 9;
        g_Wcat[q] = w1[(o * HW + i) * 9 + t];
    } else {
        g_Wcat[q] = ws[(r - OC * 9) * HW + i];
    }
}
__global__ void k_w2t(const float* __restrict__ w2) {
    int q = blockIdx.x * 256 + threadIdx.x;
    if (q >= OC * 9 * OC) return;
    int c = q % OC; int ot = q / OC; int o = ot / 9; int t = ot % 9;
    g_W2t[q] = w2[(o * OC + c) * 9 + t];
}

// ---------------- 13: fold GEMM  C[1280 x 512] = Wcat[1280 x 1600] * Ag^T -------
// 128x128 tile, 256 threads, 8x8 micro via f32x2 packed FMA.
__global__ __launch_bounds__(256, 1) void k_gemm() {
    int n = blockIdx.z;
    const float* A = g_Wcat;
    const float* B = g_Ag + (size_t)n * CC * HW;
    float* C = g_WtAll + (size_t)n * MROWS * CC;
    int m0 = blockIdx.x * 128, n0 = blockIdx.y * 128;
    __shared__ __align__(16) float Asd[16 * 256];   // [kk][2*row] duplicated pairs
    __shared__ __align__(16) float Bs[16 * 128];    // [kk][col]
    int tid = threadIdx.x, ty = tid >> 4, tx = tid & 15;
    unsigned long long acc[8][4];
#pragma unroll
    for (int i = 0; i < 8; i++)
#pragma unroll
        for (int j = 0; j < 4; j++) acc[i][j] = 0ull;

    int qrow = tid >> 2, qk4 = (tid & 3) * 4;
    const float* Ap0 = A + (size_t)(m0 + qrow) * HW + qk4;
    const float* Ap1 = A + (size_t)(m0 + qrow + 64) * HW + qk4;
    const float* Bp0 = B + (size_t)(n0 + qrow) * HW + qk4;
    const float* Bp1 = B + (size_t)(n0 + qrow + 64) * HW + qk4;
    float4 pa0 = *(const float4*)Ap0;
    float4 pa1 = *(const float4*)Ap1;
    float4 pb0 = *(const float4*)Bp0;
    float4 pb1 = *(const float4*)Bp1;

    for (int k0 = 0; k0 < HW; k0 += 16) {
        float va0[4] = { pa0.x, pa0.y, pa0.z, pa0.w };
        float va1[4] = { pa1.x, pa1.y, pa1.z, pa1.w };
        float vb0[4] = { pb0.x, pb0.y, pb0.z, pb0.w };
        float vb1[4] = { pb1.x, pb1.y, pb1.z, pb1.w };
#pragma unroll
        for (int j = 0; j < 4; j++) {
            *(unsigned long long*)&Asd[(qk4 + j) * 256 + qrow * 2] = dup2(va0[j]);
            *(unsigned long long*)&Asd[(qk4 + j) * 256 + (qrow + 64) * 2] = dup2(va1[j]);
            Bs[(qk4 + j) * 128 + qrow] = vb0[j];
            Bs[(qk4 + j) * 128 + qrow + 64] = vb1[j];
        }
        __syncthreads();
        if (k0 + 16 < HW) {
            pa0 = *(const float4*)(Ap0 + k0 + 16);
            pa1 = *(const float4*)(Ap1 + k0 + 16);
            pb0 = *(const float4*)(Bp0 + k0 + 16);
            pb1 = *(const float4*)(Bp1 + k0 + 16);
        }
#pragma unroll
        for (int kk = 0; kk < 16; kk++) {
            const float* ab = &Asd[kk * 256 + ty * 16];
            ulonglong2 a01 = *(const ulonglong2*)(ab);
            ulonglong2 a23 = *(const ulonglong2*)(ab + 4);
            ulonglong2 a45 = *(const ulonglong2*)(ab + 8);
            ulonglong2 a67 = *(const ulonglong2*)(ab + 12);
            const float* bb = &Bs[kk * 128 + tx * 8];
            ulonglong2 b01 = *(const ulonglong2*)(bb);
            ulonglong2 b23 = *(const ulonglong2*)(bb + 4);
            unsigned long long a[8] = { a01.x, a01.y, a23.x, a23.y, a45.x, a45.y, a67.x, a67.y };
            unsigned long long b[4] = { b01.x, b01.y, b23.x, b23.y };
#pragma unroll
            for (int i = 0; i < 8; i++)
#pragma unroll
                for (int j = 0; j < 4; j++) FFMA2(acc[i][j], a[i], b[j]);
        }
        __syncthreads();
    }
#pragma unroll
    for (int i = 0; i < 8; i++)
#pragma unroll
        for (int j = 0; j < 4; j++) {
            unsigned long long v = acc[i][j];
            float2 r = make_float2(lo32(v), hi32(v));
            *(float2*)&C[(size_t)(m0 + ty * 8 + i) * CC + n0 + tx * 8 + j * 2] = r;
        }
}

// ---------------- 14: implicit-GEMM 3x3 conv (128o x 64p tile, 4x8 micro, f32x2) -
// mode 0: conv1 on X=NF*CSA with folded weights g_WtAll (+1x1 shortcut rows) -> g_H1(relu), g_SC
// mode 1: conv2 on g_H1 with g_W2t, + g_SC + bias, relu -> dout
__global__ __launch_bounds__(256, 1) void k_conv(int mode, const float* __restrict__ bias,
                                                 const float* __restrict__ bsc, float* __restrict__ dout) {
    int n = blockIdx.z;
    int p0 = blockIdx.y * 64;
    int Cin = mode ? OC : CC;
    const float* W = mode ? g_W2t : (g_WtAll + (size_t)n * MROWS * CC);
    const float* X = mode ? (g_H1 + (size_t)n * OC * HW) : (g_NF + (size_t)n * CC * HW);
    __shared__ __align__(16) float sWd[16 * 256];   // [cc][2*o] duplicated
    __shared__ __align__(16) float sB[16 * 64];     // [cc][pp]
    __shared__ float sCSA[160];                     // CSA window p0-48 .. p0+111

    int tid = threadIdx.x, ty = tid >> 3, tx = tid & 7;
    unsigned long long acc[4][4], accs[4][4];
#pragma unroll
    for (int i = 0; i < 4; i++)
#pragma unroll
        for (int j = 0; j < 4; j++) { acc[i][j] = 0ull; accs[i][j] = 0ull; }

    if (!mode) {
        for (int e = tid; e < 160; e += 256) {
            int p = p0 - 48 + e;
            sCSA[e] = (p >= 0 && p < HW) ? g_CSA[n * HW + p] : 0.f;
        }
    }
    int qrow = tid >> 2, qk4 = (tid & 3) * 4;     // W loads: rows qrow, qrow+64
    int bpp = tid & 63, bcg = tid >> 6;           // X loads: pp fixed, 4 cc's
    int bp = p0 + bpp;
    int px = bp % IMG, py = bp / IMG;
    __syncthreads();

    for (int t = 0; t < 9; t++) {
        int dy = t / 3 - 1, dx = t % 3 - 1, off = dy * IMG + dx;
        bool vmask = ((unsigned)(px + dx) < (unsigned)IMG) && ((unsigned)(py + dy) < (unsigned)IMG);
        float csa = (!mode && vmask) ? sCSA[bpp + off + 48] : 1.0f;
        int wr1 = (qrow) * 9 + t, wr2 = (qrow + 64) * 9 + t;
        for (int c0 = 0; c0 < Cin; c0 += 16) {
            float4 w1v = *(const float4*)&W[(size_t)wr1 * Cin + c0 + qk4];
            float4 w2v = *(const float4*)&W[(size_t)wr2 * Cin + c0 + qk4];
            float wa[4] = { w1v.x, w1v.y, w1v.z, w1v.w };
            float wb[4] = { w2v.x, w2v.y, w2v.z, w2v.w };
#pragma unroll
            for (int j = 0; j < 4; j++) {
                *(unsigned long long*)&sWd[(qk4 + j) * 256 + qrow * 2] = dup2(wa[j]);
                *(unsigned long long*)&sWd[(qk4 + j) * 256 + (qrow + 64) * 2] = dup2(wb[j]);
            }
#pragma unroll
            for (int l = 0; l < 4; l++) {
                int cc = bcg * 4 + l;
                float v = 0.f;
                if (vmask) v = X[(size_t)(c0 + cc) * HW + bp + off];
                if (!mode) v *= csa;
                sB[cc * 64 + bpp] = v;
            }
            __syncthreads();
#pragma unroll
            for (int kk = 0; kk < 16; kk++) {
                const float* ab = &sWd[kk * 256 + ty * 8];
                ulonglong2 a01 = *(const ulonglong2*)(ab);
                ulonglong2 a23 = *(const ulonglong2*)(ab + 4);
                const float* bb = &sB[kk * 64 + tx * 8];
                ulonglong2 b01 = *(const ulonglong2*)(bb);
                ulonglong2 b23 = *(const ulonglong2*)(bb + 4);
                unsigned long long a[4] = { a01.x, a01.y, a23.x, a23.y };
                unsigned long long b[4] = { b01.x, b01.y, b23.x, b23.y };
#pragma unroll
                for (int i = 0; i < 4; i++)
#pragma unroll
                    for (int j = 0; j < 4; j++) FFMA2(acc[i][j], a[i], b[j]);
            }
            __syncthreads();
        }
    }
    if (!mode) {
        // 1x1 shortcut: weight rows 1152+o, off=0, always valid
        float csa0 = sCSA[bpp + 48];
        int wr1 = OC * 9 + qrow, wr2 = OC * 9 + qrow + 64;
        for (int c0 = 0; c0 < CC; c0 += 16) {
            float4 w1v = *(const float4*)&W[(size_t)wr1 * CC + c0 + qk4];
            float4 w2v = *(const float4*)&W[(size_t)wr2 * CC + c0 + qk4];
            float wa[4] = { w1v.x, w1v.y, w1v.z, w1v.w };
            float wb[4] = { w2v.x, w2v.y, w2v.z, w2v.w };
#pragma unroll
            for (int j = 0; j < 4; j++) {
                *(unsigned long long*)&sWd[(qk4 + j) * 256 + qrow * 2] = dup2(wa[j]);
                *(unsigned long long*)&sWd[(qk4 + j) * 256 + (qrow + 64) * 2] = dup2(wb[j]);
            }
#pragma unroll
            for (int l = 0; l < 4; l++) {
                int cc = bcg * 4 + l;
                sB[cc * 64 + bpp] = X[(size_t)(c0 + cc) * HW + bp] * csa0;
            }
            __syncthreads();
#pragma unroll
            for (int kk = 0; kk < 16; kk++) {
                const float* ab = &sWd[kk * 256 + ty * 8];
                ulonglong2 a01 = *(const ulonglong2*)(ab);
                ulonglong2 a23 = *(const ulonglong2*)(ab + 4);
                const float* bb = &sB[kk * 64 + tx * 8];
                ulonglong2 b01 = *(const ulonglong2*)(bb);
                ulonglong2 b23 = *(const ulonglong2*)(bb + 4);
                unsigned long long a[4] = { a01.x, a01.y, a23.x, a23.y };
                unsigned long long b[4] = { b01.x, b01.y, b23.x, b23.y };
#pragma unroll
                for (int i = 0; i < 4; i++)
#pragma unroll
                    for (int j = 0; j < 4; j++) FFMA2(accs[i][j], a[i], b[j]);
            }
            __syncthreads();
        }
    }
    // epilogue
#pragma unroll
    for (int i = 0; i < 4; i++) {
        int o = ty * 4 + i;
        float bo = bias[o];
#pragma unroll
        for (int j = 0; j < 4; j++) {
            int p = p0 + tx * 8 + j * 2;
            unsigned long long v = acc[i][j];
            float v0 = lo32(v) + bo, v1 = hi32(v) + bo;
            if (mode) {
                float2 sc = *(const float2*)&g_SC[(size_t)(n * OC + o) * HW + p];
                v0 += sc.x; v1 += sc.y;
                float2 r = make_float2(fmaxf(v0, 0.f), fmaxf(v1, 0.f));
                *(float2*)&dout[(size_t)(n * OC + o) * HW + p] = r;
            } else {
                float2 r = make_float2(fmaxf(v0, 0.f), fmaxf(v1, 0.f));
                *(float2*)&g_H1[(size_t)(n * OC + o) * HW + p] = r;
                unsigned long long vs = accs[i][j];
                float bso = bsc[o];
                float2 rs = make_float2(lo32(vs) + bso, hi32(vs) + bso);
                *(float2*)&g_SC[(size_t)(n * OC + o) * HW + p] = rs;
            }
        }
    }
}

// ---------------- launch ----------------
extern "C" void kernel_launch(void* const* d_in, const int* in_sizes, int n_in,
                              void* d_out, int out_size) {
    const float *feats = nullptr, *sisms = nullptr, *w1 = nullptr, *w2 = nullptr, *ws = nullptr;
    const float *b1 = nullptr, *b2 = nullptr, *bs = nullptr;
    for (int i = 0; i < n_in; i++) {
        int s = in_sizes[i];
        const float* p = (const float*)d_in[i];
        if (s == NN * CC * HW) feats = p;
        else if (s == NN * HW) sisms = p;
        else if (s == OC * HW * 9) w1 = p;
        else if (s == OC * OC * 9) w2 = p;
        else if (s == OC * HW) ws = p;
        else if (s == OC) { if (!b1) b1 = p; else if (!b2) b2 = p; else bs = p; }
    }
    float* out = (float*)d_out;

    k_norm<<<dim3(25, NN), 256>>>(feats);
    k_siv_raw<<<NN * CC, 256>>>(sisms);
    k_siv_norm<<<NN, CC>>>();
    k_cm<<<dim3(25, NN), 256>>>();
    k_cm_norm<<<NN * NN, 256>>>();
    k_corr<<<NN * NN * NN, 256>>>();
    k_sv<<<1, 128>>>();
    k_softmax<<<1, 16>>>();
    k_csa<<<NN, 512>>>();
    k_sort<<<NN, 1024>>>();
    k_gather<<<NN * CC, 256>>>();
    k_wcat<<<(MROWS * HW + 255) / 256, 256>>>(w1, ws);
    k_w2t<<<(OC * 9 * OC + 255) / 256, 256>>>(w2);
    k_gemm<<<dim3(MROWS / 128, CC / 128, NN), 256>>>();
    k_conv<<<dim3(1, HW / 64, NN), 256>>>(0, b1, bs, nullptr);
    k_conv<<<dim3(1, HW / 64, NN), 256>>>(1, b2, nullptr, out);
    (void)out_size; (void)n_in;
}

// round 5
// speedup vs baseline: 1.4862x; 1.4862x over previous
#include <cuda_runtime.h>
#include <math.h>

#define NN 10
#define CC 512
#define HW 1600
#define OC 128
#define IMG 40
#define MROWS 1280   // 1152 folded-conv1 rows + 128 shortcut rows

// ---------------- scratch (device globals) ----------------
__device__ float g_NF[NN*CC*HW];
__device__ float g_M [NN*CC*HW];
__device__ float g_Ag[NN*CC*HW];
__device__ float g_SIVraw[NN*CC];
__device__ float g_SIV[NN*CC];
__device__ float g_cm[NN*NN*HW];
__device__ float g_corr[NN*NN*NN];
__device__ float g_sv[NN*NN];
__device__ float g_wv[NN*NN];
__device__ float g_CSA[NN*HW];
__device__ int   g_idx[NN*HW];
__device__ float g_Wcat[MROWS*HW];    // rows 0..1151 = w1 [(o*9+t)][i]; 1152..1279 = ws [o][i]
__device__ float g_W2t[OC*9*OC];      // [(o*9+t)][c]
__device__ float g_Wt [NN*OC*9*CC];   // folded conv1 weights [n][(o*9+t)][c]
__device__ float g_Wts[NN*OC*CC];     // folded shortcut weights [n][o][c]
__device__ float g_H1[NN*OC*HW];
__device__ float g_SC[NN*OC*HW];

// ---------------- helpers ----------------
__device__ __forceinline__ double blockReduceSumD(double v) {
    __shared__ double sh[32];
    int lane = threadIdx.x & 31, wid = threadIdx.x >> 5;
#pragma unroll
    for (int o = 16; o > 0; o >>= 1) v += __shfl_down_sync(0xffffffffu, v, o);
    if (lane == 0) sh[wid] = v;
    __syncthreads();
    if (wid == 0) {
        int nw = blockDim.x >> 5;
        v = (lane < nw) ? sh[lane] : 0.0;
#pragma unroll
        for (int o = 16; o > 0; o >>= 1) v += __shfl_down_sync(0xffffffffu, v, o);
    }
    return v;
}

// Kahan add, contraction-proof
__device__ __forceinline__ void kadd(float& s, float& c, float p) {
    float y = __fsub_rn(p, c);
    float t = __fadd_rn(s, y);
    c = __fsub_rn(__fsub_rn(t, s), y);
    s = t;
}

// ---------------- 1: per-pixel L2 norm over C (Kahan fp32 + fp64 combine) --------
__global__ void k_norm(const float* __restrict__ feats) {
    int n = blockIdx.y;
    int tid = threadIdx.x;
    int cg = tid >> 6, kk = tid & 63;
    int hw = blockIdx.x * 64 + kk;
    const float* f = feats + (size_t)n * CC * HW + hw;
    float s = 0.f, comp = 0.f;
    for (int c = cg * 128; c < cg * 128 + 128; c++) {
        float v = f[(size_t)c * HW];
        kadd(s, comp, __fmul_rn(v, v));
    }
    __shared__ double sh[4][64];
    __shared__ float sd[64];
    sh[cg][kk] = (double)s + (double)comp;
    __syncthreads();
    if (tid < 64) {
        double S = sh[0][tid] + sh[1][tid] + sh[2][tid] + sh[3][tid];
        sd[tid] = fmaxf(sqrtf((float)S), 1e-12f);
    }
    __syncthreads();
    float d = sd[kk];
    float* o = g_NF + (size_t)n * CC * HW + hw;
    for (int c = cg * 128; c < cg * 128 + 128; c++)
        o[(size_t)c * HW] = f[(size_t)c * HW] / d;
}

// ---------------- 2: SIV raw = mean over hw of NF*SISM ----------------
__global__ void k_siv_raw(const float* __restrict__ sisms) {
    int b = blockIdx.x;              // n*CC + c
    int n = b >> 9;
    double s = 0.0;
    for (int k = threadIdx.x; k < HW; k += 256) {
        float pm = g_NF[(size_t)b * HW + k] * sisms[n * HW + k];
        s += (double)pm;
    }
    s = blockReduceSumD(s);
    if (threadIdx.x == 0) g_SIVraw[b] = ((float)s) / 1600.0f;
}

// ---------------- 3: SIV l2 norm over C ----------------
__global__ void k_siv_norm() {
    int n = blockIdx.x, t = threadIdx.x;
    float v = g_SIVraw[n * CC + t];
    float sq = v * v;
    double s = blockReduceSumD((double)sq);
    __shared__ float s_d;
    if (t == 0) s_d = fmaxf(sqrtf((float)s), 1e-12f);
    __syncthreads();
    g_SIV[n * CC + t] = v / s_d;
}

// ---------------- 4: cm[n][m][k] = sum_c NF*SIV (Kahan fp32 + fp64 combine) ------
__global__ void k_cm() {
    __shared__ float s_siv[NN * CC];
    __shared__ double sh[4][64][NN];
    int n = blockIdx.y;
    int tid = threadIdx.x;
    for (int q = tid; q < NN * CC; q += 256) s_siv[q] = g_SIV[q];
    int cg = tid >> 6, kk = tid & 63;
    int k = blockIdx.x * 64 + kk;
    const float* nfp = g_NF + (size_t)n * CC * HW + k;
    __syncthreads();
    float s[NN], comp[NN];
#pragma unroll
    for (int m = 0; m < NN; m++) { s[m] = 0.f; comp[m] = 0.f; }
    for (int c = cg * 128; c < cg * 128 + 128; c++) {
        float nf = nfp[(size_t)c * HW];
#pragma unroll
        for (int m = 0; m < NN; m++) kadd(s[m], comp[m], __fmul_rn(nf, s_siv[m * CC + c]));
    }
#pragma unroll
    for (int m = 0; m < NN; m++) sh[cg][kk][m] = (double)s[m] + (double)comp[m];
    __syncthreads();
    for (int e = tid; e < 64 * NN; e += 256) {
        int kk2 = e / NN, m = e % NN;
        double v = sh[0][kk2][m] + sh[1][kk2][m] + sh[2][kk2][m] + sh[3][kk2][m];
        g_cm[(size_t)(n * NN + m) * HW + blockIdx.x * 64 + kk2] = (float)v;
    }
}

// ---------------- 5: l2-normalize each cm row over k ----------------
__global__ void k_cm_norm() {
    int row = blockIdx.x;
    size_t base = (size_t)row * HW;
    double ss = 0.0;
    for (int k = threadIdx.x; k < HW; k += 256) {
        float v = g_cm[base + k];
        float sq = v * v;
        ss += (double)sq;
    }
    ss = blockReduceSumD(ss);
    __shared__ float s_d;
    if (threadIdx.x == 0) s_d = fmaxf(sqrtf((float)ss), 1e-12f);
    __syncthreads();
    for (int k = threadIdx.x; k < HW; k += 256) g_cm[base + k] = g_cm[base + k] / s_d;
}

// ---------------- 6: corr[n][m][p] = dot(cm[n][m], cm[n][p]) ----------------
__global__ void k_corr() {
    int b = blockIdx.x;
    int p = b % NN;
    int m = (b / NN) % NN;
    int n = b / (NN * NN);
    double s = 0.0;
    for (int k = threadIdx.x; k < HW; k += 256)
        s += (double)g_cm[(size_t)(n * NN + m) * HW + k] * (double)g_cm[(size_t)(n * NN + p) * HW + k];
    s = blockReduceSumD(s);
    if (threadIdx.x == 0) g_corr[b] = (float)s;
}

// ---------------- 7: sv[n][m] = sum_p corr ----------------
__global__ void k_sv() {
    int t = threadIdx.x;
    if (t >= NN * NN) return;
    double s = 0.0;
#pragma unroll
    for (int p = 0; p < NN; p++) s += (double)g_corr[t * NN + p];
    g_sv[t] = (float)s;
}

// ---------------- 8: softmax over m ----------------
__global__ void k_softmax() {
    int n = threadIdx.x;
    if (n >= NN) return;
    float mx = -1e30f;
    for (int m = 0; m < NN; m++) mx = fmaxf(mx, g_sv[n * NN + m]);
    float e[NN];
    double sum = 0.0;
    for (int m = 0; m < NN; m++) {
        float t = g_sv[n * NN + m] - mx;
        e[m] = (float)exp((double)t);
        sum += (double)e[m];
    }
    float S = (float)sum;
    for (int m = 0; m < NN; m++) g_wv[n * NN + m] = e[m] / S;
}

// ---------------- 9: CSA + min-max normalize ----------------
__global__ void k_csa() {
    int n = blockIdx.x, tid = threadIdx.x;
    __shared__ float s_wv[NN];
    __shared__ float sc[HW];
    __shared__ float red[512];
    if (tid < NN) s_wv[tid] = g_wv[n * NN + tid];
    __syncthreads();
    float lmin = 1e30f, lmax = -1e30f;
    for (int k = tid; k < HW; k += 512) {
        double a = 0.0;
#pragma unroll
        for (int m = 0; m < NN; m++) {
            float pm = g_cm[(size_t)(n * NN + m) * HW + k] * s_wv[m];
            a += (double)pm;
        }
        float raw = (float)a;
        sc[k] = raw;
        lmin = fminf(lmin, raw); lmax = fmaxf(lmax, raw);
    }
    red[tid] = lmin; __syncthreads();
    for (int s = 256; s > 0; s >>= 1) { if (tid < s) red[tid] = fminf(red[tid], red[tid + s]); __syncthreads(); }
    float mn = red[0]; __syncthreads();
    red[tid] = lmax; __syncthreads();
    for (int s = 256; s > 0; s >>= 1) { if (tid < s) red[tid] = fmaxf(red[tid], red[tid + s]); __syncthreads(); }
    float mx = red[0]; __syncthreads();
    float den = (mx - mn) + 1e-12f;
    for (int k = tid; k < HW; k += 512) {
        float num = sc[k] - mn;
        g_CSA[n * HW + k] = num / den;
    }
}

// ---------------- 10: stable argsort descending (bitonic 2048) ----------------
__global__ void k_sort() {
    __shared__ float key[2048];
    __shared__ int   idv[2048];
    int n = blockIdx.x, tid = threadIdx.x;
    for (int e = tid; e < 2048; e += 1024) {
        if (e < HW) { key[e] = g_CSA[n * HW + e]; idv[e] = e; }
        else        { key[e] = -1e30f;            idv[e] = e; }
    }
    __syncthreads();
    for (int k = 2; k <= 2048; k <<= 1) {
        for (int j = k >> 1; j > 0; j >>= 1) {
            for (int e = tid; e < 2048; e += 1024) {
                int ix = e ^ j;
                if (ix > e) {
                    float ka = key[e], kb = key[ix];
                    int ia = idv[e], ib = idv[ix];
                    bool up = ((e & k) == 0);
                    bool b_before_a = (kb > ka) || (kb == ka && ib < ia);
                    bool dosw = up ? b_before_a : !b_before_a;
                    if (dosw) { key[e] = kb; key[ix] = ka; idv[e] = ib; idv[ix] = ia; }
                }
            }
            __syncthreads();
        }
    }
    for (int e = tid; e < HW; e += 1024) g_idx[n * HW + e] = idv[e];
}

// ---------------- 11: M = NF * CSA ----------------
__global__ void k_scaleM() {
    int i = blockIdx.x * 256 + threadIdx.x;
    if (i >= NN * CC * HW) return;
    int j = i % HW;
    int n = i / (CC * HW);
    g_M[i] = g_NF[i] * g_CSA[n * HW + j];
}

// ---------------- 12: gather Ag[n][c][i] = NF[n][c][idx[n][i]] ----------------
__global__ void k_gather() {
    int b = blockIdx.x;       // n*CC+c
    int n = b >> 9;
    for (int i = threadIdx.x; i < HW; i += 256)
        g_Ag[(size_t)b * HW + i] = g_NF[(size_t)b * HW + g_idx[n * HW + i]];
}

// ---------------- 13: weight concat + w2 transpose ----------------
__global__ void k_wcat(const float* __restrict__ w1, const float* __restrict__ ws) {
    int q = blockIdx.x * 256 + threadIdx.x;
    if (q >= MROWS * HW) return;
    int i = q % HW, r = q / HW;
    if (r < OC * 9) {
        int o = r / 9, t = r % 9;
        g_Wcat[q] = w1[(o * HW + i) * 9 + t];
    } else {
        g_Wcat[q] = ws[(r - OC * 9) * HW + i];
    }
}
__global__ void k_w2t(const float* __restrict__ w2) {
    int q = blockIdx.x * 256 + threadIdx.x;
    if (q >= OC * 9 * OC) return;
    int c = q % OC; int ot = q / OC; int o = ot / 9; int t = ot % 9;
    g_W2t[q] = w2[(o * OC + c) * 9 + t];
}

// ---------------- 14: fold GEMM  C[1280 x 512] = Wcat * Ag[n]^T (proven R2 core) --
__global__ void k_gemm() {
    const int K = HW;
    int n = blockIdx.z;
    const float* A = g_Wcat;
    const float* B = g_Ag + (size_t)n * CC * HW;
    int m0 = blockIdx.x * 64, n0 = blockIdx.y * 64;
    __shared__ float As[32 * 68];
    __shared__ float Bs[32 * 68];
    int tid = threadIdx.x, ty = tid / 16, tx = tid % 16;
    float acc[4][4] = {};
    for (int k0 = 0; k0 < K; k0 += 32) {
#pragma unroll
        for (int l = 0; l < 8; l++) {
            int e = tid + l * 256;
            int r = e >> 5, kk = e & 31;
            As[kk * 68 + r] = A[(size_t)(m0 + r) * K + k0 + kk];
            Bs[kk * 68 + r] = B[(size_t)(n0 + r) * K + k0 + kk];
        }
        __syncthreads();
#pragma unroll
        for (int kk = 0; kk < 32; kk++) {
            float4 a4 = *(const float4*)&As[kk * 68 + ty * 4];
            float4 b4 = *(const float4*)&Bs[kk * 68 + tx * 4];
            float av[4] = { a4.x, a4.y, a4.z, a4.w };
            float bv[4] = { b4.x, b4.y, b4.z, b4.w };
#pragma unroll
            for (int i = 0; i < 4; i++)
#pragma unroll
                for (int j = 0; j < 4; j++) acc[i][j] += av[i] * bv[j];
        }
        __syncthreads();
    }
#pragma unroll
    for (int i = 0; i < 4; i++) {
        int row = m0 + ty * 4 + i;
        float* dst = (row < OC * 9)
            ? (g_Wt  + ((size_t)n * OC * 9 + row) * CC)
            : (g_Wts + ((size_t)n * OC + (row - OC * 9)) * CC);
#pragma unroll
        for (int j = 0; j < 4; j++)
            dst[n0 + tx * 4 + j] = acc[i][j];
    }
}

// ---------------- 15/16: implicit-GEMM 3x3 conv (proven R2 version) --------------
__global__ void k_conv(int mode, const float* __restrict__ bias,
                       const float* __restrict__ bsc, float* __restrict__ dout) {
    int n = blockIdx.z;
    const float *X, *Wt, *Wsc = nullptr, *add = nullptr;
    float *o1, *o2 = nullptr;
    int Cin;
    if (mode == 0) {
        X = g_M + (size_t)n * CC * HW; Wt = g_Wt + (size_t)n * OC * 9 * CC; Cin = CC;
        Wsc = g_Wts + (size_t)n * OC * CC;
        o1 = g_H1 + (size_t)n * OC * HW; o2 = g_SC + (size_t)n * OC * HW;
    } else {
        X = g_H1 + (size_t)n * OC * HW; Wt = g_W2t; Cin = OC;
        add = g_SC + (size_t)n * OC * HW;
        o1 = dout + (size_t)n * OC * HW;
    }
    int o0 = blockIdx.x * 64, p0 = blockIdx.y * 64;
    int tid = threadIdx.x, ty = tid / 16, tx = tid % 16;
    __shared__ float sW[16 * 68];
    __shared__ float sB[16 * 68];
    float acc[4][4] = {};
    float accs[4][4] = {};

    for (int t = 0; t < 9; t++) {
        int dy = t / 3 - 1, dx = t % 3 - 1, off = dy * IMG + dx;
        for (int c0 = 0; c0 < Cin; c0 += 16) {
#pragma unroll
            for (int l = 0; l < 4; l++) {
                int e = tid + l * 256;
                int r = e >> 4, cc = e & 15;
                sW[cc * 68 + r] = Wt[(size_t)((o0 + r) * 9 + t) * Cin + c0 + cc];
                int pp = e & 63, cc2 = e >> 6;
                int p = p0 + pp;
                int px = p % IMG, py = p / IMG;
                int xs = px + dx, ysr = py + dy;
                float v = 0.f;
                if ((unsigned)xs < (unsigned)IMG && (unsigned)ysr < (unsigned)IMG)
                    v = X[(size_t)(c0 + cc2) * HW + p + off];
                sB[cc2 * 68 + pp] = v;
            }
            __syncthreads();
#pragma unroll
            for (int kk = 0; kk < 16; kk++) {
                float4 a4 = *(const float4*)&sW[kk * 68 + ty * 4];
                float4 b4 = *(const float4*)&sB[kk * 68 + tx * 4];
                float av[4] = { a4.x, a4.y, a4.z, a4.w };
                float bv[4] = { b4.x, b4.y, b4.z, b4.w };
#pragma unroll
                for (int i = 0; i < 4; i++)
#pragma unroll
                    for (int j = 0; j < 4; j++) acc[i][j] += av[i] * bv[j];
            }
            __syncthreads();
        }
    }
    if (mode == 0) {
        for (int c0 = 0; c0 < Cin; c0 += 16) {
#pragma unroll
            for (int l = 0; l < 4; l++) {
                int e = tid + l * 256;
                int r = e >> 4, cc = e & 15;
                sW[cc * 68 + r] = Wsc[(size_t)(o0 + r) * Cin + c0 + cc];
                int pp = e & 63, cc2 = e >> 6;
                sB[cc2 * 68 + pp] = X[(size_t)(c0 + cc2) * HW + p0 + pp];
            }
            __syncthreads();
#pragma unroll
            for (int kk = 0; kk < 16; kk++) {
                float4 a4 = *(const float4*)&sW[kk * 68 + ty * 4];
                float4 b4 = *(const float4*)&sB[kk * 68 + tx * 4];
                float av[4] = { a4.x, a4.y, a4.z, a4.w };
                float bv[4] = { b4.x, b4.y, b4.z, b4.w };
#pragma unroll
                for (int i = 0; i < 4; i++)
#pragma unroll
                    for (int j = 0; j < 4; j++) accs[i][j] += av[i] * bv[j];
            }
            __syncthreads();
        }
    }
#pragma unroll
    for (int i = 0; i < 4; i++) {
#pragma unroll
        for (int j = 0; j < 4; j++) {
            int o = o0 + ty * 4 + i, p = p0 + tx * 4 + j;
            float v = acc[i][j] + bias[o];
            if (mode == 1) {
                v += add[(size_t)o * HW + p];
                o1[(size_t)o * HW + p] = fmaxf(v, 0.f);
            } else {
                o1[(size_t)o * HW + p] = fmaxf(v, 0.f);
                o2[(size_t)o * HW + p] = accs[i][j] + bsc[o];
            }
        }
    }
}

// ---------------- launch ----------------
extern "C" void kernel_launch(void* const* d_in, const int* in_sizes, int n_in,
                              void* d_out, int out_size) {
    const float *feats = nullptr, *sisms = nullptr, *w1 = nullptr, *w2 = nullptr, *ws = nullptr;
    const float *b1 = nullptr, *b2 = nullptr, *bs = nullptr;
    for (int i = 0; i < n_in; i++) {
        int s = in_sizes[i];
        const float* p = (const float*)d_in[i];
        if (s == NN * CC * HW) feats = p;
        else if (s == NN * HW) sisms = p;
        else if (s == OC * HW * 9) w1 = p;
        else if (s == OC * OC * 9) w2 = p;
        else if (s == OC * HW) ws = p;
        else if (s == OC) { if (!b1) b1 = p; else if (!b2) b2 = p; else bs = p; }
    }
    float* out = (float*)d_out;

    k_norm<<<dim3(25, NN), 256>>>(feats);
    k_siv_raw<<<NN * CC, 256>>>(sisms);
    k_siv_norm<<<NN, CC>>>();
    k_cm<<<dim3(25, NN), 256>>>();
    k_cm_norm<<<NN * NN, 256>>>();
    k_corr<<<NN * NN * NN, 256>>>();
    k_sv<<<1, 128>>>();
    k_softmax<<<1, 16>>>();
    k_csa<<<NN, 512>>>();
    k_sort<<<NN, 1024>>>();
    k_scaleM<<<(NN * CC * HW + 255) / 256, 256>>>();
    k_gather<<<NN * CC, 256>>>();
    k_wcat<<<(MROWS * HW + 255) / 256, 256>>>(w1, ws);
    k_w2t<<<(OC * 9 * OC + 255) / 256, 256>>>(w2);
    k_gemm<<<dim3(MROWS / 64, CC / 64, NN), 256>>>();
    k_conv<<<dim3(OC / 64, HW / 64, NN), 256>>>(0, b1, bs, nullptr);
    k_conv<<<dim3(OC / 64, HW / 64, NN), 256>>>(1, b2, nullptr, out);
    (void)out_size; (void)n_in;
}

// round 7
// speedup vs baseline: 1.9360x; 1.3027x over previous
#include <cuda_runtime.h>
#include <cuda_bf16.h>
#include <math.h>
#include <stdint.h>

#define NN 10
#define CC 512
#define HW 1600
#define OC 128
#define IMG 40
#define MROWS 1280   // 1152 folded-conv1 rows + 128 shortcut rows

// ---------------- scratch (device globals) ----------------
__device__ float g_NF[NN*CC*HW];
__device__ float g_M [NN*CC*HW];
__device__ float g_SIVraw[NN*CC];
__device__ float g_SIV[NN*CC];
__device__ float g_cm[NN*NN*HW];
__device__ float g_corr[NN*NN*NN];
__device__ float g_sv[NN*NN];
__device__ float g_wv[NN*NN];
__device__ float g_CSA[NN*HW];
__device__ int   g_idx[NN*HW];
__device__ __align__(16) __nv_bfloat16 g_Wc_hi[MROWS*HW]; // rows 0..1151=w1[(o*9+t)][i]; 1152..1279=ws[o][i]
__device__ __align__(16) __nv_bfloat16 g_Wc_lo[MROWS*HW];
__device__ __align__(16) __nv_bfloat16 g_Ag_hi[NN*CC*HW]; // gathered NF bf16 hi [n][c][i]
__device__ __align__(16) __nv_bfloat16 g_Ag_lo[NN*CC*HW];
__device__ float g_W2t[OC*9*OC];      // [(o*9+t)][c]
__device__ float g_Wt [NN*OC*9*CC];   // folded conv1 weights [n][(o*9+t)][c]
__device__ float g_Wts[NN*OC*CC];     // folded shortcut weights [n][o][c]
__device__ float g_H1[NN*OC*HW];
__device__ float g_SC[NN*OC*HW];

// ---------------- helpers ----------------
__device__ __forceinline__ double blockReduceSumD(double v) {
    __shared__ double sh[32];
    int lane = threadIdx.x & 31, wid = threadIdx.x >> 5;
#pragma unroll
    for (int o = 16; o > 0; o >>= 1) v += __shfl_down_sync(0xffffffffu, v, o);
    if (lane == 0) sh[wid] = v;
    __syncthreads();
    if (wid == 0) {
        int nw = blockDim.x >> 5;
        v = (lane < nw) ? sh[lane] : 0.0;
#pragma unroll
        for (int o = 16; o > 0; o >>= 1) v += __shfl_down_sync(0xffffffffu, v, o);
    }
    return v;
}

// Kahan add, contraction-proof
__device__ __forceinline__ void kadd(float& s, float& c, float p) {
    float y = __fsub_rn(p, c);
    float t = __fadd_rn(s, y);
    c = __fsub_rn(__fsub_rn(t, s), y);
    s = t;
}

__device__ __forceinline__ uint32_t smem_u32(const void* p) {
    uint32_t a;
    asm("{ .reg .u64 t; cvta.to.shared.u64 t, %1; cvt.u32.u64 %0, t; }" : "=r"(a) : "l"(p));
    return a;
}
__device__ __forceinline__ void ldsm_x4(uint32_t& r0, uint32_t& r1, uint32_t& r2, uint32_t& r3, uint32_t a) {
    asm volatile("ldmatrix.sync.aligned.m8n8.x4.shared.b16 {%0,%1,%2,%3}, [%4];"
                 : "=r"(r0), "=r"(r1), "=r"(r2), "=r"(r3) : "r"(a));
}
__device__ __forceinline__ void ldsm_x2(uint32_t& r0, uint32_t& r1, uint32_t a) {
    asm volatile("ldmatrix.sync.aligned.m8n8.x2.shared.b16 {%0,%1}, [%2];"
                 : "=r"(r0), "=r"(r1) : "r"(a));
}
__device__ __forceinline__ void hmma(float* c, const uint32_t* a, uint32_t b0, uint32_t b1) {
    asm volatile("mma.sync.aligned.m16n8k16.row.col.f32.bf16.bf16.f32 "
                 "{%0,%1,%2,%3},{%4,%5,%6,%7},{%8,%9},{%0,%1,%2,%3};"
                 : "+f"(c[0]), "+f"(c[1]), "+f"(c[2]), "+f"(c[3])
                 : "r"(a[0]), "r"(a[1]), "r"(a[2]), "r"(a[3]), "r"(b0), "r"(b1));
}

// ---------------- 1: per-pixel L2 norm over C (Kahan fp32 + fp64 combine) --------
__global__ void k_norm(const float* __restrict__ feats) {
    int n = blockIdx.y;
    int tid = threadIdx.x;
    int cg = tid >> 6, kk = tid & 63;
    int hw = blockIdx.x * 64 + kk;
    const float* f = feats + (size_t)n * CC * HW + hw;
    float s = 0.f, comp = 0.f;
    for (int c = cg * 128; c < cg * 128 + 128; c++) {
        float v = f[(size_t)c * HW];
        kadd(s, comp, __fmul_rn(v, v));
    }
    __shared__ double sh[4][64];
    __shared__ float sd[64];
    sh[cg][kk] = (double)s + (double)comp;
    __syncthreads();
    if (tid < 64) {
        double S = sh[0][tid] + sh[1][tid] + sh[2][tid] + sh[3][tid];
        sd[tid] = fmaxf(sqrtf((float)S), 1e-12f);
    }
    __syncthreads();
    float d = sd[kk];
    float* o = g_NF + (size_t)n * CC * HW + hw;
    for (int c = cg * 128; c < cg * 128 + 128; c++)
        o[(size_t)c * HW] = f[(size_t)c * HW] / d;
}

// ---------------- 2: SIV raw = mean over hw of NF*SISM ----------------
__global__ void k_siv_raw(const float* __restrict__ sisms) {
    int b = blockIdx.x;              // n*CC + c
    int n = b >> 9;
    double s = 0.0;
    for (int k = threadIdx.x; k < HW; k += 256) {
        float pm = g_NF[(size_t)b * HW + k] * sisms[n * HW + k];
        s += (double)pm;
    }
    s = blockReduceSumD(s);
    if (threadIdx.x == 0) g_SIVraw[b] = ((float)s) / 1600.0f;
}

// ---------------- 3: SIV l2 norm over C ----------------
__global__ void k_siv_norm() {
    int n = blockIdx.x, t = threadIdx.x;
    float v = g_SIVraw[n * CC + t];
    float sq = v * v;
    double s = blockReduceSumD((double)sq);
    __shared__ float s_d;
    if (t == 0) s_d = fmaxf(sqrtf((float)s), 1e-12f);
    __syncthreads();
    g_SIV[n * CC + t] = v / s_d;
}

// ---------------- 4: cm[n][m][k] = sum_c NF*SIV (Kahan fp32 + fp64 combine) ------
__global__ void k_cm() {
    __shared__ float s_siv[NN * CC];
    __shared__ double sh[4][64][NN];
    int n = blockIdx.y;
    int tid = threadIdx.x;
    for (int q = tid; q < NN * CC; q += 256) s_siv[q] = g_SIV[q];
    int cg = tid >> 6, kk = tid & 63;
    int k = blockIdx.x * 64 + kk;
    const float* nfp = g_NF + (size_t)n * CC * HW + k;
    __syncthreads();
    float s[NN], comp[NN];
#pragma unroll
    for (int m = 0; m < NN; m++) { s[m] = 0.f; comp[m] = 0.f; }
    for (int c = cg * 128; c < cg * 128 + 128; c++) {
        float nf = nfp[(size_t)c * HW];
#pragma unroll
        for (int m = 0; m < NN; m++) kadd(s[m], comp[m], __fmul_rn(nf, s_siv[m * CC + c]));
    }
#pragma unroll
    for (int m = 0; m < NN; m++) sh[cg][kk][m] = (double)s[m] + (double)comp[m];
    __syncthreads();
    for (int e = tid; e < 64 * NN; e += 256) {
        int kk2 = e / NN, m = e % NN;
        double v = sh[0][kk2][m] + sh[1][kk2][m] + sh[2][kk2][m] + sh[3][kk2][m];
        g_cm[(size_t)(n * NN + m) * HW + blockIdx.x * 64 + kk2] = (float)v;
    }
}

// ---------------- 5: l2-normalize each cm row over k ----------------
__global__ void k_cm_norm() {
    int row = blockIdx.x;
    size_t base = (size_t)row * HW;
    double ss = 0.0;
    for (int k = threadIdx.x; k < HW; k += 256) {
        float v = g_cm[base + k];
        float sq = v * v;
        ss += (double)sq;
    }
    ss = blockReduceSumD(ss);
    __shared__ float s_d;
    if (threadIdx.x == 0) s_d = fmaxf(sqrtf((float)ss), 1e-12f);
    __syncthreads();
    for (int k = threadIdx.x; k < HW; k += 256) g_cm[base + k] = g_cm[base + k] / s_d;
}

// ---------------- 6: corr[n][m][p] = dot(cm[n][m], cm[n][p]) ----------------
__global__ void k_corr() {
    int b = blockIdx.x;
    int p = b % NN;
    int m = (b / NN) % NN;
    int n = b / (NN * NN);
    double s = 0.0;
    for (int k = threadIdx.x; k < HW; k += 256)
        s += (double)g_cm[(size_t)(n * NN + m) * HW + k] * (double)g_cm[(size_t)(n * NN + p) * HW + k];
    s = blockReduceSumD(s);
    if (threadIdx.x == 0) g_corr[b] = (float)s;
}

// ---------------- 7: sv[n][m] = sum_p corr ----------------
__global__ void k_sv() {
    int t = threadIdx.x;
    if (t >= NN * NN) return;
    double s = 0.0;
#pragma unroll
    for (int p = 0; p < NN; p++) s += (double)g_corr[t * NN + p];
    g_sv[t] = (float)s;
}

// ---------------- 8: softmax over m ----------------
__global__ void k_softmax() {
    int n = threadIdx.x;
    if (n >= NN) return;
    float mx = -1e30f;
    for (int m = 0; m < NN; m++) mx = fmaxf(mx, g_sv[n * NN + m]);
    float e[NN];
    double sum = 0.0;
    for (int m = 0; m < NN; m++) {
        float t = g_sv[n * NN + m] - mx;
        e[m] = (float)exp((double)t);
        sum += (double)e[m];
    }
    float S = (float)sum;
    for (int m = 0; m < NN; m++) g_wv[n * NN + m] = e[m] / S;
}

// ---------------- 9: CSA + min-max normalize ----------------
__global__ void k_csa() {
    int n = blockIdx.x, tid = threadIdx.x;
    __shared__ float s_wv[NN];
    __shared__ float sc[HW];
    __shared__ float red[512];
    if (tid < NN) s_wv[tid] = g_wv[n * NN + tid];
    __syncthreads();
    float lmin = 1e30f, lmax = -1e30f;
    for (int k = tid; k < HW; k += 512) {
        double a = 0.0;
#pragma unroll
        for (int m = 0; m < NN; m++) {
            float pm = g_cm[(size_t)(n * NN + m) * HW + k] * s_wv[m];
            a += (double)pm;
        }
        float raw = (float)a;
        sc[k] = raw;
        lmin = fminf(lmin, raw); lmax = fmaxf(lmax, raw);
    }
    red[tid] = lmin; __syncthreads();
    for (int s = 256; s > 0; s >>= 1) { if (tid < s) red[tid] = fminf(red[tid], red[tid + s]); __syncthreads(); }
    float mn = red[0]; __syncthreads();
    red[tid] = lmax; __syncthreads();
    for (int s = 256; s > 0; s >>= 1) { if (tid < s) red[tid] = fmaxf(red[tid], red[tid + s]); __syncthreads(); }
    float mx = red[0]; __syncthreads();
    float den = (mx - mn) + 1e-12f;
    for (int k = tid; k < HW; k += 512) {
        float num = sc[k] - mn;
        g_CSA[n * HW + k] = num / den;
    }
}

// ---------------- 10: stable argsort descending (bitonic 2048) ----------------
__global__ void k_sort() {
    __shared__ float key[2048];
    __shared__ int   idv[2048];
    int n = blockIdx.x, tid = threadIdx.x;
    for (int e = tid; e < 2048; e += 1024) {
        if (e < HW) { key[e] = g_CSA[n * HW + e]; idv[e] = e; }
        else        { key[e] = -1e30f;            idv[e] = e; }
    }
    __syncthreads();
    for (int k = 2; k <= 2048; k <<= 1) {
        for (int j = k >> 1; j > 0; j >>= 1) {
            for (int e = tid; e < 2048; e += 1024) {
                int ix = e ^ j;
                if (ix > e) {
                    float ka = key[e], kb = key[ix];
                    int ia = idv[e], ib = idv[ix];
                    bool up = ((e & k) == 0);
                    bool b_before_a = (kb > ka) || (kb == ka && ib < ia);
                    bool dosw = up ? b_before_a : !b_before_a;
                    if (dosw) { key[e] = kb; key[ix] = ka; idv[e] = ib; idv[ix] = ia; }
                }
            }
            __syncthreads();
        }
    }
    for (int e = tid; e < HW; e += 1024) g_idx[n * HW + e] = idv[e];
}

// ---------------- 11: M = NF * CSA ----------------
__global__ void k_scaleM() {
    int i = blockIdx.x * 256 + threadIdx.x;
    if (i >= NN * CC * HW) return;
    int j = i % HW;
    int n = i / (CC * HW);
    g_M[i] = g_NF[i] * g_CSA[n * HW + j];
}

// ---------------- 12: gather + bf16 hi/lo split ----------------
__global__ void k_gather_split() {
    int b = blockIdx.x;       // n*CC+c
    int n = b >> 9;
    for (int i = threadIdx.x; i < HW; i += 256) {
        float v = g_NF[(size_t)b * HW + g_idx[n * HW + i]];
        __nv_bfloat16 h = __float2bfloat16(v);
        __nv_bfloat16 l = __float2bfloat16(v - __bfloat162float(h));
        g_Ag_hi[(size_t)b * HW + i] = h;
        g_Ag_lo[(size_t)b * HW + i] = l;
    }
}

// ---------------- 13: weight concat + bf16 split / w2 transpose ----------------
__global__ void k_wsplit(const float* __restrict__ w1, const float* __restrict__ ws) {
    int q = blockIdx.x * 256 + threadIdx.x;
    if (q >= MROWS * HW) return;
    int i = q % HW, r = q / HW;
    float f;
    if (r < OC * 9) {
        int o = r / 9, t = r % 9;
        f = w1[(o * HW + i) * 9 + t];
    } else {
        f = ws[(r - OC * 9) * HW + i];
    }
    __nv_bfloat16 h = __float2bfloat16(f);
    __nv_bfloat16 l = __float2bfloat16(f - __bfloat162float(h));
    g_Wc_hi[q] = h;
    g_Wc_lo[q] = l;
}
__global__ void k_w2t(const float* __restrict__ w2) {
    int q = blockIdx.x * 256 + threadIdx.x;
    if (q >= OC * 9 * OC) return;
    int c = q % OC; int ot = q / OC; int o = ot / 9; int t = ot % 9;
    g_W2t[q] = w2[(o * OC + c) * 9 + t];
}

// ---------------- 14: fold GEMM via mma.sync bf16x3 ------------------------------
// C[n](1280x512) = Wc(1280x1600) * Ag[n](512x1600)^T, near-fp32 via hi/lo split.
// Block 128x128, 8 warps (warp tile 32x64), K-slab 32.
#define LDT 40   // smem row stride in bf16 (conflict-free ldmatrix)

__global__ __launch_bounds__(256) void k_gemm_mma() {
    __shared__ __nv_bfloat16 sAh[128 * LDT], sAl[128 * LDT];
    __shared__ __nv_bfloat16 sBh[128 * LDT], sBl[128 * LDT];
    int n = blockIdx.z;
    int m0 = blockIdx.x * 128, n0 = blockIdx.y * 128;
    const __nv_bfloat16* Bh = g_Ag_hi + (size_t)n * CC * HW;
    const __nv_bfloat16* Bl = g_Ag_lo + (size_t)n * CC * HW;
    int tid = threadIdx.x, lane = tid & 31, wid = tid >> 5;
    int wm = wid & 3, wn = wid >> 2;     // warp tile: rows 32*wm, cols 64*wn

    float c[2][8][4];
#pragma unroll
    for (int i = 0; i < 2; i++)
#pragma unroll
        for (int j = 0; j < 8; j++)
#pragma unroll
            for (int q = 0; q < 4; q++) c[i][j][q] = 0.f;

    int lrow = tid >> 1, lk = (tid & 1) * 16;     // global loads: 16 bf16 per thread per buf
    uint32_t uAh = smem_u32(sAh), uAl = smem_u32(sAl);
    uint32_t uBh = smem_u32(sBh), uBl = smem_u32(sBl);
    // ldmatrix lane addressing
    int arow = (lane & 15), akoff = 8 * (lane >> 4);
    int brow = (lane & 7),  bkoff = 8 * ((lane >> 3) & 1);

    for (int k0 = 0; k0 < HW; k0 += 32) {
        size_t gA = (size_t)(m0 + lrow) * HW + k0 + lk;
        size_t gB = (size_t)(n0 + lrow) * HW + k0 + lk;
        uint32_t so = (uint32_t)(lrow * LDT + lk) * 2;
        *(uint4*)((char*)sAh + so)      = *(const uint4*)(g_Wc_hi + gA);
        *(uint4*)((char*)sAh + so + 16) = *(const uint4*)(g_Wc_hi + gA + 8);
        *(uint4*)((char*)sAl + so)      = *(const uint4*)(g_Wc_lo + gA);
        *(uint4*)((char*)sAl + so + 16) = *(const uint4*)(g_Wc_lo + gA + 8);
        *(uint4*)((char*)sBh + so)      = *(const uint4*)(Bh + gB);
        *(uint4*)((char*)sBh + so + 16) = *(const uint4*)(Bh + gB + 8);
        *(uint4*)((char*)sBl + so)      = *(const uint4*)(Bl + gB);
        *(uint4*)((char*)sBl + so + 16) = *(const uint4*)(Bl + gB + 8);
        __syncthreads();
#pragma unroll
        for (int kk = 0; kk < 32; kk += 16) {
            uint32_t ah[2][4], al[2][4];
#pragma unroll
            for (int i = 0; i < 2; i++) {
                uint32_t ao = (uint32_t)((32 * wm + 16 * i + arow) * LDT + kk + akoff) * 2;
                ldsm_x4(ah[i][0], ah[i][1], ah[i][2], ah[i][3], uAh + ao);
                ldsm_x4(al[i][0], al[i][1], al[i][2], al[i][3], uAl + ao);
            }
#pragma unroll
            for (int j = 0; j < 8; j++) {
                uint32_t bo = (uint32_t)((64 * wn + 8 * j + brow) * LDT + kk + bkoff) * 2;
                uint32_t bh0, bh1, bl0, bl1;
                ldsm_x2(bh0, bh1, uBh + bo);
                ldsm_x2(bl0, bl1, uBl + bo);
#pragma unroll
                for (int i = 0; i < 2; i++) {
                    hmma(c[i][j], ah[i], bh0, bh1);
                    hmma(c[i][j], ah[i], bl0, bl1);
                    hmma(c[i][j], al[i], bh0, bh1);
                }
            }
        }
        __syncthreads();
    }
    // epilogue
#pragma unroll
    for (int i = 0; i < 2; i++) {
        int row = m0 + 32 * wm + 16 * i + (lane >> 2);
#pragma unroll
        for (int half = 0; half < 2; half++) {
            int r = row + half * 8;
            float* dst = (r < OC * 9)
                ? (g_Wt  + ((size_t)n * OC * 9 + r) * CC)
                : (g_Wts + ((size_t)n * OC + (r - OC * 9)) * CC);
#pragma unroll
            for (int j = 0; j < 8; j++) {
                int col = n0 + 64 * wn + 8 * j + (lane & 3) * 2;
                *(float2*)(dst + col) = make_float2(c[i][j][half * 2], c[i][j][half * 2 + 1]);
            }
        }
    }
}

// ---------------- 15/16: implicit-GEMM 3x3 conv (proven R2 version) --------------
__global__ void k_conv(int mode, const float* __restrict__ bias,
                       const float* __restrict__ bsc, float* __restrict__ dout) {
    int n = blockIdx.z;
    const float *X, *Wt, *Wsc = nullptr, *add = nullptr;
    float *o1, *o2 = nullptr;
    int Cin;
    if (mode == 0) {
        X = g_M + (size_t)n * CC * HW; Wt = g_Wt + (size_t)n * OC * 9 * CC; Cin = CC;
        Wsc = g_Wts + (size_t)n * OC * CC;
        o1 = g_H1 + (size_t)n * OC * HW; o2 = g_SC + (size_t)n * OC * HW;
    } else {
        X = g_H1 + (size_t)n * OC * HW; Wt = g_W2t; Cin = OC;
        add = g_SC + (size_t)n * OC * HW;
        o1 = dout + (size_t)n * OC * HW;
    }
    int o0 = blockIdx.x * 64, p0 = blockIdx.y * 64;
    int tid = threadIdx.x, ty = tid / 16, tx = tid % 16;
    __shared__ float sW[16 * 68];
    __shared__ float sB[16 * 68];
    float acc[4][4] = {};
    float accs[4][4] = {};

    for (int t = 0; t < 9; t++) {
        int dy = t / 3 - 1, dx = t % 3 - 1, off = dy * IMG + dx;
        for (int c0 = 0; c0 < Cin; c0 += 16) {
#pragma unroll
            for (int l = 0; l < 4; l++) {
                int e = tid + l * 256;
                int r = e >> 4, cc = e & 15;
                sW[cc * 68 + r] = Wt[(size_t)((o0 + r) * 9 + t) * Cin + c0 + cc];
                int pp = e & 63, cc2 = e >> 6;
                int p = p0 + pp;
                int px = p % IMG, py = p / IMG;
                int xs = px + dx, ysr = py + dy;
                float v = 0.f;
                if ((unsigned)xs < (unsigned)IMG && (unsigned)ysr < (unsigned)IMG)
                    v = X[(size_t)(c0 + cc2) * HW + p + off];
                sB[cc2 * 68 + pp] = v;
            }
            __syncthreads();
#pragma unroll
            for (int kk = 0; kk < 16; kk++) {
                float4 a4 = *(const float4*)&sW[kk * 68 + ty * 4];
                float4 b4 = *(const float4*)&sB[kk * 68 + tx * 4];
                float av[4] = { a4.x, a4.y, a4.z, a4.w };
                float bv[4] = { b4.x, b4.y, b4.z, b4.w };
#pragma unroll
                for (int i = 0; i < 4; i++)
#pragma unroll
                    for (int j = 0; j < 4; j++) acc[i][j] += av[i] * bv[j];
            }
            __syncthreads();
        }
    }
    if (mode == 0) {
        for (int c0 = 0; c0 < Cin; c0 += 16) {
#pragma unroll
            for (int l = 0; l < 4; l++) {
                int e = tid + l * 256;
                int r = e >> 4, cc = e & 15;
                sW[cc * 68 + r] = Wsc[(size_t)(o0 + r) * Cin + c0 + cc];
                int pp = e & 63, cc2 = e >> 6;
                sB[cc2 * 68 + pp] = X[(size_t)(c0 + cc2) * HW + p0 + pp];
            }
            __syncthreads();
#pragma unroll
            for (int kk = 0; kk < 16; kk++) {
                float4 a4 = *(const float4*)&sW[kk * 68 + ty * 4];
                float4 b4 = *(const float4*)&sB[kk * 68 + tx * 4];
                float av[4] = { a4.x, a4.y, a4.z, a4.w };
                float bv[4] = { b4.x, b4.y, b4.z, b4.w };
#pragma unroll
                for (int i = 0; i < 4; i++)
#pragma unroll
                    for (int j = 0; j < 4; j++) accs[i][j] += av[i] * bv[j];
            }
            __syncthreads();
        }
    }
#pragma unroll
    for (int i = 0; i < 4; i++) {
#pragma unroll
        for (int j = 0; j < 4; j++) {
            int o = o0 + ty * 4 + i, p = p0 + tx * 4 + j;
            float v = acc[i][j] + bias[o];
            if (mode == 1) {
                v += add[(size_t)o * HW + p];
                o1[(size_t)o * HW + p] = fmaxf(v, 0.f);
            } else {
                o1[(size_t)o * HW + p] = fmaxf(v, 0.f);
                o2[(size_t)o * HW + p] = accs[i][j] + bsc[o];
            }
        }
    }
}

// ---------------- launch ----------------
extern "C" void kernel_launch(void* const* d_in, const int* in_sizes, int n_in,
                              void* d_out, int out_size) {
    const float *feats = nullptr, *sisms = nullptr, *w1 = nullptr, *w2 = nullptr, *ws = nullptr;
    const float *b1 = nullptr, *b2 = nullptr, *bs = nullptr;
    for (int i = 0; i < n_in; i++) {
        int s = in_sizes[i];
        const float* p = (const float*)d_in[i];
        if (s == NN * CC * HW) feats = p;
        else if (s == NN * HW) sisms = p;
        else if (s == OC * HW * 9) w1 = p;
        else if (s == OC * OC * 9) w2 = p;
        else if (s == OC * HW) ws = p;
        else if (s == OC) { if (!b1) b1 = p; else if (!b2) b2 = p; else bs = p; }
    }
    float* out = (float*)d_out;

    k_norm<<<dim3(25, NN), 256>>>(feats);
    k_siv_raw<<<NN * CC, 256>>>(sisms);
    k_siv_norm<<<NN, CC>>>();
    k_cm<<<dim3(25, NN), 256>>>();
    k_cm_norm<<<NN * NN, 256>>>();
    k_corr<<<NN * NN * NN, 256>>>();
    k_sv<<<1, 128>>>();
    k_softmax<<<1, 16>>>();
    k_csa<<<NN, 512>>>();
    k_sort<<<NN, 1024>>>();
    k_scaleM<<<(NN * CC * HW + 255) / 256, 256>>>();
    k_gather_split<<<NN * CC, 256>>>();
    k_wsplit<<<(MROWS * HW + 255) / 256, 256>>>(w1, ws);
    k_w2t<<<(OC * 9 * OC + 255) / 256, 256>>>(w2);
    k_gemm_mma<<<dim3(MROWS / 128, CC / 128, NN), 256>>>();
    k_conv<<<dim3(OC / 64, HW / 64, NN), 256>>>(0, b1, bs, nullptr);
    k_conv<<<dim3(OC / 64, HW / 64, NN), 256>>>(1, b2, nullptr, out);
    (void)out_size; (void)n_in;
}

// round 8
// speedup vs baseline: 3.0936x; 1.5979x over previous
#include <cuda_runtime.h>
#include <cuda_bf16.h>
#include <math.h>
#include <stdint.h>

#define NN 10
#define CC 512
#define HW 1600
#define OC 128
#define IMG 40
#define MROWS 1280   // 1152 folded-conv1 rows + 128 shortcut rows
#define K1 4608      // conv1 K = 9*512
#define K2 1152      // conv2 K = 9*128

// ---------------- scratch (device globals) ----------------
__device__ float g_NF[NN*CC*HW];
__device__ float g_SIVraw[NN*CC];
__device__ float g_SIV[NN*CC];
__device__ float g_cm[NN*NN*HW];
__device__ float g_corr[NN*NN*NN];
__device__ float g_sv[NN*NN];
__device__ float g_wv[NN*NN];
__device__ float g_CSA[NN*HW];
__device__ int   g_idx[NN*HW];
__device__ __align__(16) __nv_bfloat16 g_Wc_hi[MROWS*HW];
__device__ __align__(16) __nv_bfloat16 g_Wc_lo[MROWS*HW];
__device__ __align__(16) __nv_bfloat16 g_Ag_hi[NN*CC*HW];
__device__ __align__(16) __nv_bfloat16 g_Ag_lo[NN*CC*HW];
__device__ __align__(16) __nv_bfloat16 g_Wk1_hi[NN*OC*K1];  // folded conv1 w [n][o][t*512+c]
__device__ __align__(16) __nv_bfloat16 g_Wk1_lo[NN*OC*K1];
__device__ __align__(16) __nv_bfloat16 g_Wsc_hi[NN*OC*CC];  // folded shortcut w [n][o][c]
__device__ __align__(16) __nv_bfloat16 g_Wsc_lo[NN*OC*CC];
__device__ __align__(16) __nv_bfloat16 g_W2k_hi[OC*K2];     // w2 [o][t*128+c]
__device__ __align__(16) __nv_bfloat16 g_W2k_lo[OC*K2];
__device__ __align__(16) __nv_bfloat16 g_Xt_hi[NN*HW*CC];   // (NF*CSA)^T [n][p][c]
__device__ __align__(16) __nv_bfloat16 g_Xt_lo[NN*HW*CC];
__device__ __align__(16) __nv_bfloat16 g_H1t_hi[NN*HW*OC];  // H1^T [n][p][o]
__device__ __align__(16) __nv_bfloat16 g_H1t_lo[NN*HW*OC];
__device__ float g_H1[NN*OC*HW];
__device__ float g_SC[NN*OC*HW];

// ---------------- helpers ----------------
__device__ __forceinline__ double blockReduceSumD(double v) {
    __shared__ double sh[32];
    int lane = threadIdx.x & 31, wid = threadIdx.x >> 5;
#pragma unroll
    for (int o = 16; o > 0; o >>= 1) v += __shfl_down_sync(0xffffffffu, v, o);
    if (lane == 0) sh[wid] = v;
    __syncthreads();
    if (wid == 0) {
        int nw = blockDim.x >> 5;
        v = (lane < nw) ? sh[lane] : 0.0;
#pragma unroll
        for (int o = 16; o > 0; o >>= 1) v += __shfl_down_sync(0xffffffffu, v, o);
    }
    return v;
}
__device__ __forceinline__ void kadd(float& s, float& c, float p) {
    float y = __fsub_rn(p, c);
    float t = __fadd_rn(s, y);
    c = __fsub_rn(__fsub_rn(t, s), y);
    s = t;
}
__device__ __forceinline__ uint32_t smem_u32(const void* p) {
    uint32_t a;
    asm("{ .reg .u64 t; cvta.to.shared.u64 t, %1; cvt.u32.u64 %0, t; }" : "=r"(a) : "l"(p));
    return a;
}
__device__ __forceinline__ void ldsm_x4(uint32_t& r0, uint32_t& r1, uint32_t& r2, uint32_t& r3, uint32_t a) {
    asm volatile("ldmatrix.sync.aligned.m8n8.x4.shared.b16 {%0,%1,%2,%3}, [%4];"
                 : "=r"(r0), "=r"(r1), "=r"(r2), "=r"(r3) : "r"(a));
}
__device__ __forceinline__ void ldsm_x2(uint32_t& r0, uint32_t& r1, uint32_t a) {
    asm volatile("ldmatrix.sync.aligned.m8n8.x2.shared.b16 {%0,%1}, [%2];"
                 : "=r"(r0), "=r"(r1) : "r"(a));
}
__device__ __forceinline__ void hmma(float* c, const uint32_t* a, uint32_t b0, uint32_t b1) {
    asm volatile("mma.sync.aligned.m16n8k16.row.col.f32.bf16.bf16.f32 "
                 "{%0,%1,%2,%3},{%4,%5,%6,%7},{%8,%9},{%0,%1,%2,%3};"
                 : "+f"(c[0]), "+f"(c[1]), "+f"(c[2]), "+f"(c[3])
                 : "r"(a[0]), "r"(a[1]), "r"(a[2]), "r"(a[3]), "r"(b0), "r"(b1));
}
__device__ __forceinline__ uint32_t pack_hi2(float a, float b) {
    __nv_bfloat162 h = __floats2bfloat162_rn(a, b);
    // need truncation-free split: do manually
    __nv_bfloat16 ha = __float2bfloat16(a), hb = __float2bfloat16(b);
    uint32_t r = (uint32_t)__bfloat16_as_ushort(ha) | ((uint32_t)__bfloat16_as_ushort(hb) << 16);
    (void)h;
    return r;
}
__device__ __forceinline__ uint32_t pack_lo2(float a, float b) {
    __nv_bfloat16 ha = __float2bfloat16(a), hb = __float2bfloat16(b);
    __nv_bfloat16 la = __float2bfloat16(a - __bfloat162float(ha));
    __nv_bfloat16 lb = __float2bfloat16(b - __bfloat162float(hb));
    return (uint32_t)__bfloat16_as_ushort(la) | ((uint32_t)__bfloat16_as_ushort(lb) << 16);
}

// ---------------- 1: per-pixel L2 norm over C ----------------
__global__ void k_norm(const float* __restrict__ feats) {
    int n = blockIdx.y;
    int tid = threadIdx.x;
    int cg = tid >> 6, kk = tid & 63;
    int hw = blockIdx.x * 64 + kk;
    const float* f = feats + (size_t)n * CC * HW + hw;
    float s = 0.f, comp = 0.f;
    for (int c = cg * 128; c < cg * 128 + 128; c++) {
        float v = f[(size_t)c * HW];
        kadd(s, comp, __fmul_rn(v, v));
    }
    __shared__ double sh[4][64];
    __shared__ float sd[64];
    sh[cg][kk] = (double)s + (double)comp;
    __syncthreads();
    if (tid < 64) {
        double S = sh[0][tid] + sh[1][tid] + sh[2][tid] + sh[3][tid];
        sd[tid] = fmaxf(sqrtf((float)S), 1e-12f);
    }
    __syncthreads();
    float d = sd[kk];
    float* o = g_NF + (size_t)n * CC * HW + hw;
    for (int c = cg * 128; c < cg * 128 + 128; c++)
        o[(size_t)c * HW] = f[(size_t)c * HW] / d;
}

// ---------------- 2: SIV raw ----------------
__global__ void k_siv_raw(const float* __restrict__ sisms) {
    int b = blockIdx.x;
    int n = b >> 9;
    double s = 0.0;
    for (int k = threadIdx.x; k < HW; k += 256) {
        float pm = g_NF[(size_t)b * HW + k] * sisms[n * HW + k];
        s += (double)pm;
    }
    s = blockReduceSumD(s);
    if (threadIdx.x == 0) g_SIVraw[b] = ((float)s) / 1600.0f;
}

// ---------------- 3: SIV l2 norm ----------------
__global__ void k_siv_norm() {
    int n = blockIdx.x, t = threadIdx.x;
    float v = g_SIVraw[n * CC + t];
    float sq = v * v;
    double s = blockReduceSumD((double)sq);
    __shared__ float s_d;
    if (t == 0) s_d = fmaxf(sqrtf((float)s), 1e-12f);
    __syncthreads();
    g_SIV[n * CC + t] = v / s_d;
}

// ---------------- 4: cm ----------------
__global__ void k_cm() {
    __shared__ float s_siv[NN * CC];
    __shared__ double sh[4][64][NN];
    int n = blockIdx.y;
    int tid = threadIdx.x;
    for (int q = tid; q < NN * CC; q += 256) s_siv[q] = g_SIV[q];
    int cg = tid >> 6, kk = tid & 63;
    int k = blockIdx.x * 64 + kk;
    const float* nfp = g_NF + (size_t)n * CC * HW + k;
    __syncthreads();
    float s[NN], comp[NN];
#pragma unroll
    for (int m = 0; m < NN; m++) { s[m] = 0.f; comp[m] = 0.f; }
    for (int c = cg * 128; c < cg * 128 + 128; c++) {
        float nf = nfp[(size_t)c * HW];
#pragma unroll
        for (int m = 0; m < NN; m++) kadd(s[m], comp[m], __fmul_rn(nf, s_siv[m * CC + c]));
    }
#pragma unroll
    for (int m = 0; m < NN; m++) sh[cg][kk][m] = (double)s[m] + (double)comp[m];
    __syncthreads();
    for (int e = tid; e < 64 * NN; e += 256) {
        int kk2 = e / NN, m = e % NN;
        double v = sh[0][kk2][m] + sh[1][kk2][m] + sh[2][kk2][m] + sh[3][kk2][m];
        g_cm[(size_t)(n * NN + m) * HW + blockIdx.x * 64 + kk2] = (float)v;
    }
}

// ---------------- 5: cm row norm ----------------
__global__ void k_cm_norm() {
    int row = blockIdx.x;
    size_t base = (size_t)row * HW;
    double ss = 0.0;
    for (int k = threadIdx.x; k < HW; k += 256) {
        float v = g_cm[base + k];
        float sq = v * v;
        ss += (double)sq;
    }
    ss = blockReduceSumD(ss);
    __shared__ float s_d;
    if (threadIdx.x == 0) s_d = fmaxf(sqrtf((float)ss), 1e-12f);
    __syncthreads();
    for (int k = threadIdx.x; k < HW; k += 256) g_cm[base + k] = g_cm[base + k] / s_d;
}

// ---------------- 6: corr ----------------
__global__ void k_corr() {
    int b = blockIdx.x;
    int p = b % NN;
    int m = (b / NN) % NN;
    int n = b / (NN * NN);
    double s = 0.0;
    for (int k = threadIdx.x; k < HW; k += 256)
        s += (double)g_cm[(size_t)(n * NN + m) * HW + k] * (double)g_cm[(size_t)(n * NN + p) * HW + k];
    s = blockReduceSumD(s);
    if (threadIdx.x == 0) g_corr[b] = (float)s;
}

// ---------------- 7: sv ----------------
__global__ void k_sv() {
    int t = threadIdx.x;
    if (t >= NN * NN) return;
    double s = 0.0;
#pragma unroll
    for (int p = 0; p < NN; p++) s += (double)g_corr[t * NN + p];
    g_sv[t] = (float)s;
}

// ---------------- 8: softmax ----------------
__global__ void k_softmax() {
    int n = threadIdx.x;
    if (n >= NN) return;
    float mx = -1e30f;
    for (int m = 0; m < NN; m++) mx = fmaxf(mx, g_sv[n * NN + m]);
    float e[NN];
    double sum = 0.0;
    for (int m = 0; m < NN; m++) {
        float t = g_sv[n * NN + m] - mx;
        e[m] = (float)exp((double)t);
        sum += (double)e[m];
    }
    float S = (float)sum;
    for (int m = 0; m < NN; m++) g_wv[n * NN + m] = e[m] / S;
}

// ---------------- 9: CSA ----------------
__global__ void k_csa() {
    int n = blockIdx.x, tid = threadIdx.x;
    __shared__ float s_wv[NN];
    __shared__ float sc[HW];
    __shared__ float red[512];
    if (tid < NN) s_wv[tid] = g_wv[n * NN + tid];
    __syncthreads();
    float lmin = 1e30f, lmax = -1e30f;
    for (int k = tid; k < HW; k += 512) {
        double a = 0.0;
#pragma unroll
        for (int m = 0; m < NN; m++) {
            float pm = g_cm[(size_t)(n * NN + m) * HW + k] * s_wv[m];
            a += (double)pm;
        }
        float raw = (float)a;
        sc[k] = raw;
        lmin = fminf(lmin, raw); lmax = fmaxf(lmax, raw);
    }
    red[tid] = lmin; __syncthreads();
    for (int s = 256; s > 0; s >>= 1) { if (tid < s) red[tid] = fminf(red[tid], red[tid + s]); __syncthreads(); }
    float mn = red[0]; __syncthreads();
    red[tid] = lmax; __syncthreads();
    for (int s = 256; s > 0; s >>= 1) { if (tid < s) red[tid] = fmaxf(red[tid], red[tid + s]); __syncthreads(); }
    float mx = red[0]; __syncthreads();
    float den = (mx - mn) + 1e-12f;
    for (int k = tid; k < HW; k += 512) {
        float num = sc[k] - mn;
        g_CSA[n * HW + k] = num / den;
    }
}

// ---------------- 10: argsort ----------------
__global__ void k_sort() {
    __shared__ float key[2048];
    __shared__ int   idv[2048];
    int n = blockIdx.x, tid = threadIdx.x;
    for (int e = tid; e < 2048; e += 1024) {
        if (e < HW) { key[e] = g_CSA[n * HW + e]; idv[e] = e; }
        else        { key[e] = -1e30f;            idv[e] = e; }
    }
    __syncthreads();
    for (int k = 2; k <= 2048; k <<= 1) {
        for (int j = k >> 1; j > 0; j >>= 1) {
            for (int e = tid; e < 2048; e += 1024) {
                int ix = e ^ j;
                if (ix > e) {
                    float ka = key[e], kb = key[ix];
                    int ia = idv[e], ib = idv[ix];
                    bool up = ((e & k) == 0);
                    bool b_before_a = (kb > ka) || (kb == ka && ib < ia);
                    bool dosw = up ? b_before_a : !b_before_a;
                    if (dosw) { key[e] = kb; key[ix] = ka; idv[e] = ib; idv[ix] = ia; }
                }
            }
            __syncthreads();
        }
    }
    for (int e = tid; e < HW; e += 1024) g_idx[n * HW + e] = idv[e];
}

// ---------------- 11: gather + bf16 split ----------------
__global__ void k_gather_split() {
    int b = blockIdx.x;
    int n = b >> 9;
    for (int i = threadIdx.x; i < HW; i += 256) {
        float v = g_NF[(size_t)b * HW + g_idx[n * HW + i]];
        __nv_bfloat16 h = __float2bfloat16(v);
        __nv_bfloat16 l = __float2bfloat16(v - __bfloat162float(h));
        g_Ag_hi[(size_t)b * HW + i] = h;
        g_Ag_lo[(size_t)b * HW + i] = l;
    }
}

// ---------------- 12: weight concat + split ----------------
__global__ void k_wsplit(const float* __restrict__ w1, const float* __restrict__ ws) {
    int q = blockIdx.x * 256 + threadIdx.x;
    if (q >= MROWS * HW) return;
    int i = q % HW, r = q / HW;
    float f;
    if (r < OC * 9) {
        int o = r / 9, t = r % 9;
        f = w1[(o * HW + i) * 9 + t];
    } else {
        f = ws[(r - OC * 9) * HW + i];
    }
    __nv_bfloat16 h = __float2bfloat16(f);
    __nv_bfloat16 l = __float2bfloat16(f - __bfloat162float(h));
    g_Wc_hi[q] = h;
    g_Wc_lo[q] = l;
}
// w2 -> [o][t*128+c] bf16 hi/lo
__global__ void k_w2split(const float* __restrict__ w2) {
    int q = blockIdx.x * 256 + threadIdx.x;
    if (q >= OC * K2) return;
    int k = q % K2, o = q / K2;
    int t = k / OC, c = k % OC;
    float f = w2[(o * OC + c) * 9 + t];
    __nv_bfloat16 h = __float2bfloat16(f);
    __nv_bfloat16 l = __float2bfloat16(f - __bfloat162float(h));
    g_W2k_hi[q] = h;
    g_W2k_lo[q] = l;
}

// ---------------- 13: fold GEMM via mma.sync bf16x3 -> bf16 hi/lo weights --------
#define LDT 40

__global__ __launch_bounds__(256) void k_gemm_mma() {
    __shared__ __nv_bfloat16 sAh[128 * LDT], sAl[128 * LDT];
    __shared__ __nv_bfloat16 sBh[128 * LDT], sBl[128 * LDT];
    int n = blockIdx.z;
    int m0 = blockIdx.x * 128, n0 = blockIdx.y * 128;
    const __nv_bfloat16* Bh = g_Ag_hi + (size_t)n * CC * HW;
    const __nv_bfloat16* Bl = g_Ag_lo + (size_t)n * CC * HW;
    int tid = threadIdx.x, lane = tid & 31, wid = tid >> 5;
    int wm = wid & 3, wn = wid >> 2;

    float c[2][8][4];
#pragma unroll
    for (int i = 0; i < 2; i++)
#pragma unroll
        for (int j = 0; j < 8; j++)
#pragma unroll
            for (int q = 0; q < 4; q++) c[i][j][q] = 0.f;

    int lrow = tid >> 1, lk = (tid & 1) * 16;
    uint32_t uAh = smem_u32(sAh), uAl = smem_u32(sAl);
    uint32_t uBh = smem_u32(sBh), uBl = smem_u32(sBl);
    int arow = (lane & 15), akoff = 8 * (lane >> 4);
    int brow = (lane & 7),  bkoff = 8 * ((lane >> 3) & 1);

    for (int k0 = 0; k0 < HW; k0 += 32) {
        size_t gA = (size_t)(m0 + lrow) * HW + k0 + lk;
        size_t gB = (size_t)(n0 + lrow) * HW + k0 + lk;
        uint32_t so = (uint32_t)(lrow * LDT + lk) * 2;
        *(uint4*)((char*)sAh + so)      = *(const uint4*)(g_Wc_hi + gA);
        *(uint4*)((char*)sAh + so + 16) = *(const uint4*)(g_Wc_hi + gA + 8);
        *(uint4*)((char*)sAl + so)      = *(const uint4*)(g_Wc_lo + gA);
        *(uint4*)((char*)sAl + so + 16) = *(const uint4*)(g_Wc_lo + gA + 8);
        *(uint4*)((char*)sBh + so)      = *(const uint4*)(Bh + gB);
        *(uint4*)((char*)sBh + so + 16) = *(const uint4*)(Bh + gB + 8);
        *(uint4*)((char*)sBl + so)      = *(const uint4*)(Bl + gB);
        *(uint4*)((char*)sBl + so + 16) = *(const uint4*)(Bl + gB + 8);
        __syncthreads();
#pragma unroll
        for (int kk = 0; kk < 32; kk += 16) {
            uint32_t ah[2][4], al[2][4];
#pragma unroll
            for (int i = 0; i < 2; i++) {
                uint32_t ao = (uint32_t)((32 * wm + 16 * i + arow) * LDT + kk + akoff) * 2;
                ldsm_x4(ah[i][0], ah[i][1], ah[i][2], ah[i][3], uAh + ao);
                ldsm_x4(al[i][0], al[i][1], al[i][2], al[i][3], uAl + ao);
            }
#pragma unroll
            for (int j = 0; j < 8; j++) {
                uint32_t bo = (uint32_t)((64 * wn + 8 * j + brow) * LDT + kk + bkoff) * 2;
                uint32_t bh0, bh1, bl0, bl1;
                ldsm_x2(bh0, bh1, uBh + bo);
                ldsm_x2(bl0, bl1, uBl + bo);
#pragma unroll
                for (int i = 0; i < 2; i++) {
                    hmma(c[i][j], ah[i], bh0, bh1);
                    hmma(c[i][j], ah[i], bl0, bl1);
                    hmma(c[i][j], al[i], bh0, bh1);
                }
            }
        }
        __syncthreads();
    }
    // epilogue: split to bf16 hi/lo, route into conv-ready layouts
#pragma unroll
    for (int i = 0; i < 2; i++) {
        int rb = m0 + 32 * wm + 16 * i + (lane >> 2);
#pragma unroll
        for (int half = 0; half < 2; half++) {
            int r = rb + half * 8;
#pragma unroll
            for (int j = 0; j < 8; j++) {
                int col = n0 + 64 * wn + 8 * j + (lane & 3) * 2;
                float v0 = c[i][j][half * 2], v1 = c[i][j][half * 2 + 1];
                size_t off;
                __nv_bfloat16 *dh, *dl;
                if (r < OC * 9) {
                    int o = r / 9, t = r % 9;
                    off = ((size_t)n * OC + o) * K1 + t * CC + col;
                    dh = g_Wk1_hi; dl = g_Wk1_lo;
                } else {
                    int o = r - OC * 9;
                    off = ((size_t)n * OC + o) * CC + col;
                    dh = g_Wsc_hi; dl = g_Wsc_lo;
                }
                *(uint32_t*)(dh + off) = pack_hi2(v0, v1);
                *(uint32_t*)(dl + off) = pack_lo2(v0, v1);
            }
        }
    }
}

// ---------------- 14: Xt = (NF*CSA)^T split (tiled transpose) ----------------
// grid (50, Cdim/32, NN); 256 threads; 32x32 tiles
__global__ void k_xt() {
    __shared__ float sT[32][33];
    int n = blockIdx.z;
    int p0 = blockIdx.x * 32, c0 = blockIdx.y * 32;
    int tid = threadIdx.x;
    int tc = tid >> 5, tp = tid & 31;
#pragma unroll
    for (int r = 0; r < 4; r++) {
        int c = c0 + tc + r * 8;
        sT[tc + r * 8][tp] = g_NF[((size_t)n * CC + c) * HW + p0 + tp] * g_CSA[n * HW + p0 + tp];
    }
    __syncthreads();
#pragma unroll
    for (int r = 0; r < 4; r++) {
        int p = p0 + tc + r * 8;
        float v = sT[tp][tc + r * 8];
        __nv_bfloat16 h = __float2bfloat16(v);
        __nv_bfloat16 l = __float2bfloat16(v - __bfloat162float(h));
        g_Xt_hi[((size_t)n * HW + p) * CC + c0 + tp] = h;
        g_Xt_lo[((size_t)n * HW + p) * CC + c0 + tp] = l;
    }
}
// H1t = H1^T split
__global__ void k_h1t() {
    __shared__ float sT[32][33];
    int n = blockIdx.z;
    int p0 = blockIdx.x * 32, c0 = blockIdx.y * 32;
    int tid = threadIdx.x;
    int tc = tid >> 5, tp = tid & 31;
#pragma unroll
    for (int r = 0; r < 4; r++) {
        int c = c0 + tc + r * 8;
        sT[tc + r * 8][tp] = g_H1[((size_t)n * OC + c) * HW + p0 + tp];
    }
    __syncthreads();
#pragma unroll
    for (int r = 0; r < 4; r++) {
        int p = p0 + tc + r * 8;
        float v = sT[tp][tc + r * 8];
        __nv_bfloat16 h = __float2bfloat16(v);
        __nv_bfloat16 l = __float2bfloat16(v - __bfloat162float(h));
        g_H1t_hi[((size_t)n * HW + p) * OC + c0 + tp] = h;
        g_H1t_lo[((size_t)n * HW + p) * OC + c0 + tp] = l;
    }
}

// ---------------- 15: conv via mma.sync bf16x3 (implicit GEMM) -------------------
// M=128 outputs x N=64 pixels per block. mode0: conv1 (K=4608 + 512 shortcut phase),
// mode1: conv2 (K=1152, + SC + relu).
__global__ __launch_bounds__(256) void k_conv_mma(int mode, const float* __restrict__ bias,
                                                  const float* __restrict__ bsc,
                                                  float* __restrict__ dout) {
    __shared__ __nv_bfloat16 sAh[128 * LDT], sAl[128 * LDT];
    __shared__ __nv_bfloat16 sBh[64 * LDT],  sBl[64 * LDT];
    int n = blockIdx.z;
    int p0 = blockIdx.x * 64;
    int tid = threadIdx.x, lane = tid & 31, wid = tid >> 5;
    int wm = wid & 3, wn = wid >> 2;          // warp tile 32 rows x 32 cols

    const __nv_bfloat16 *Ah, *Al, *Bh, *Bl;
    int K, Cin, nslab;
    if (mode == 0) {
        Ah = g_Wk1_hi + (size_t)n * OC * K1; Al = g_Wk1_lo + (size_t)n * OC * K1;
        Bh = g_Xt_hi + (size_t)n * HW * CC;  Bl = g_Xt_lo + (size_t)n * HW * CC;
        K = K1; Cin = CC; nslab = K1 / 32;
    } else {
        Ah = g_W2k_hi; Al = g_W2k_lo;
        Bh = g_H1t_hi + (size_t)n * HW * OC; Bl = g_H1t_lo + (size_t)n * HW * OC;
        K = K2; Cin = OC; nslab = K2 / 32;
    }
    int slabs_per_tap = Cin / 32;

    uint32_t uAh = smem_u32(sAh), uAl = smem_u32(sAl);
    uint32_t uBh = smem_u32(sBh), uBl = smem_u32(sBl);
    int alrow = tid >> 1, alk = (tid & 1) * 16;     // A loader
    int blrow = tid >> 2, blc = (tid & 3) * 8;      // B loader
    int bp = p0 + blrow;
    int bpx = bp % IMG, bpy = bp / IMG;
    int arow = (lane & 15), akoff = 8 * (lane >> 4);
    int brow = (lane & 7),  bkoff = 8 * ((lane >> 3) & 1);

    float c[2][4][4];
#pragma unroll
    for (int i = 0; i < 2; i++)
#pragma unroll
        for (int j = 0; j < 4; j++)
#pragma unroll
            for (int q = 0; q < 4; q++) c[i][j][q] = 0.f;

    for (int kb = 0; kb < nslab; kb++) {
        int t = kb / slabs_per_tap, c0 = (kb % slabs_per_tap) * 32;
        int dy = t / 3 - 1, dx = t % 3 - 1, off = dy * IMG + dx;
        bool valid = ((unsigned)(bpx + dx) < (unsigned)IMG) && ((unsigned)(bpy + dy) < (unsigned)IMG);
        // A tile
        {
            size_t gA = (size_t)alrow * K + kb * 32 + alk;
            uint32_t so = (uint32_t)(alrow * LDT + alk) * 2;
            *(uint4*)((char*)sAh + so)      = *(const uint4*)(Ah + gA);
            *(uint4*)((char*)sAh + so + 16) = *(const uint4*)(Ah + gA + 8);
            *(uint4*)((char*)sAl + so)      = *(const uint4*)(Al + gA);
            *(uint4*)((char*)sAl + so + 16) = *(const uint4*)(Al + gA + 8);
        }
        // B tile (shift + mask)
        {
            uint32_t so = (uint32_t)(blrow * LDT + blc) * 2;
            uint4 vh = make_uint4(0, 0, 0, 0), vl = make_uint4(0, 0, 0, 0);
            if (valid) {
                size_t gB = (size_t)(bp + off) * Cin + c0 + blc;
                vh = *(const uint4*)(Bh + gB);
                vl = *(const uint4*)(Bl + gB);
            }
            *(uint4*)((char*)sBh + so) = vh;
            *(uint4*)((char*)sBl + so) = vl;
        }
        __syncthreads();
#pragma unroll
        for (int kk = 0; kk < 32; kk += 16) {
            uint32_t ah[2][4], al[2][4];
#pragma unroll
            for (int i = 0; i < 2; i++) {
                uint32_t ao = (uint32_t)((32 * wm + 16 * i + arow) * LDT + kk + akoff) * 2;
                ldsm_x4(ah[i][0], ah[i][1], ah[i][2], ah[i][3], uAh + ao);
                ldsm_x4(al[i][0], al[i][1], al[i][2], al[i][3], uAl + ao);
            }
#pragma unroll
            for (int j = 0; j < 4; j++) {
                uint32_t bo = (uint32_t)((32 * wn + 8 * j + brow) * LDT + kk + bkoff) * 2;
                uint32_t bh0, bh1, bl0, bl1;
                ldsm_x2(bh0, bh1, uBh + bo);
                ldsm_x2(bl0, bl1, uBl + bo);
#pragma unroll
                for (int i = 0; i < 2; i++) {
                    hmma(c[i][j], ah[i], bh0, bh1);
                    hmma(c[i][j], ah[i], bl0, bl1);
                    hmma(c[i][j], al[i], bh0, bh1);
                }
            }
        }
        __syncthreads();
    }
    // epilogue phase 1
#pragma unroll
    for (int i = 0; i < 2; i++) {
        int rb = 32 * wm + 16 * i + (lane >> 2);
#pragma unroll
        for (int half = 0; half < 2; half++) {
            int o = rb + half * 8;
            float bo = bias[o];
#pragma unroll
            for (int j = 0; j < 4; j++) {
                int p = p0 + 32 * wn + 8 * j + (lane & 3) * 2;
                float v0 = c[i][j][half * 2] + bo, v1 = c[i][j][half * 2 + 1] + bo;
                if (mode == 0) {
                    *(float2*)&g_H1[((size_t)n * OC + o) * HW + p] =
                        make_float2(fmaxf(v0, 0.f), fmaxf(v1, 0.f));
                } else {
                    float2 sc = *(const float2*)&g_SC[((size_t)n * OC + o) * HW + p];
                    *(float2*)&dout[((size_t)n * OC + o) * HW + p] =
                        make_float2(fmaxf(v0 + sc.x, 0.f), fmaxf(v1 + sc.y, 0.f));
                }
            }
        }
    }
    if (mode != 0) return;

    // ---- phase 2: 1x1 shortcut (K=512, no shift/mask), reuse accumulators ----
#pragma unroll
    for (int i = 0; i < 2; i++)
#pragma unroll
        for (int j = 0; j < 4; j++)
#pragma unroll
            for (int q = 0; q < 4; q++) c[i][j][q] = 0.f;
    const __nv_bfloat16* Sh = g_Wsc_hi + (size_t)n * OC * CC;
    const __nv_bfloat16* Sl = g_Wsc_lo + (size_t)n * OC * CC;
    for (int kb = 0; kb < CC / 32; kb++) {
        {
            size_t gA = (size_t)alrow * CC + kb * 32 + alk;
            uint32_t so = (uint32_t)(alrow * LDT + alk) * 2;
            *(uint4*)((char*)sAh + so)      = *(const uint4*)(Sh + gA);
            *(uint4*)((char*)sAh + so + 16) = *(const uint4*)(Sh + gA + 8);
            *(uint4*)((char*)sAl + so)      = *(const uint4*)(Sl + gA);
            *(uint4*)((char*)sAl + so + 16) = *(const uint4*)(Sl + gA + 8);
        }
        {
            uint32_t so = (uint32_t)(blrow * LDT + blc) * 2;
            size_t gB = (size_t)bp * CC + kb * 32 + blc;
            *(uint4*)((char*)sBh + so) = *(const uint4*)(Bh + gB);
            *(uint4*)((char*)sBl + so) = *(const uint4*)(Bl + gB);
        }
        __syncthreads();
#pragma unroll
        for (int kk = 0; kk < 32; kk += 16) {
            uint32_t ah[2][4], al[2][4];
#pragma unroll
            for (int i = 0; i < 2; i++) {
                uint32_t ao = (uint32_t)((32 * wm + 16 * i + arow) * LDT + kk + akoff) * 2;
                ldsm_x4(ah[i][0], ah[i][1], ah[i][2], ah[i][3], uAh + ao);
                ldsm_x4(al[i][0], al[i][1], al[i][2], al[i][3], uAl + ao);
            }
#pragma unroll
            for (int j = 0; j < 4; j++) {
                uint32_t bo = (uint32_t)((32 * wn + 8 * j + brow) * LDT + kk + bkoff) * 2;
                uint32_t bh0, bh1, bl0, bl1;
                ldsm_x2(bh0, bh1, uBh + bo);
                ldsm_x2(bl0, bl1, uBl + bo);
#pragma unroll
                for (int i = 0; i < 2; i++) {
                    hmma(c[i][j], ah[i], bh0, bh1);
                    hmma(c[i][j], ah[i], bl0, bl1);
                    hmma(c[i][j], al[i], bh0, bh1);
                }
            }
        }
        __syncthreads();
    }
#pragma unroll
    for (int i = 0; i < 2; i++) {
        int rb = 32 * wm + 16 * i + (lane >> 2);
#pragma unroll
        for (int half = 0; half < 2; half++) {
            int o = rb + half * 8;
            float bo = bsc[o];
#pragma unroll
            for (int j = 0; j < 4; j++) {
                int p = p0 + 32 * wn + 8 * j + (lane & 3) * 2;
                *(float2*)&g_SC[((size_t)n * OC + o) * HW + p] =
                    make_float2(c[i][j][half * 2] + bo, c[i][j][half * 2 + 1] + bo);
            }
        }
    }
}

// ---------------- launch ----------------
extern "C" void kernel_launch(void* const* d_in, const int* in_sizes, int n_in,
                              void* d_out, int out_size) {
    const float *feats = nullptr, *sisms = nullptr, *w1 = nullptr, *w2 = nullptr, *ws = nullptr;
    const float *b1 = nullptr, *b2 = nullptr, *bs = nullptr;
    for (int i = 0; i < n_in; i++) {
        int s = in_sizes[i];
        const float* p = (const float*)d_in[i];
        if (s == NN * CC * HW) feats = p;
        else if (s == NN * HW) sisms = p;
        else if (s == OC * HW * 9) w1 = p;
        else if (s == OC * OC * 9) w2 = p;
        else if (s == OC * HW) ws = p;
        else if (s == OC) { if (!b1) b1 = p; else if (!b2) b2 = p; else bs = p; }
    }
    float* out = (float*)d_out;

    k_norm<<<dim3(25, NN), 256>>>(feats);
    k_siv_raw<<<NN * CC, 256>>>(sisms);
    k_siv_norm<<<NN, CC>>>();
    k_cm<<<dim3(25, NN), 256>>>();
    k_cm_norm<<<NN * NN, 256>>>();
    k_corr<<<NN * NN * NN, 256>>>();
    k_sv<<<1, 128>>>();
    k_softmax<<<1, 16>>>();
    k_csa<<<NN, 512>>>();
    k_sort<<<NN, 1024>>>();
    k_gather_split<<<NN * CC, 256>>>();
    k_wsplit<<<(MROWS * HW + 255) / 256, 256>>>(w1, ws);
    k_w2split<<<(OC * K2 + 255) / 256, 256>>>(w2);
    k_gemm_mma<<<dim3(MROWS / 128, CC / 128, NN), 256>>>();
    k_xt<<<dim3(50, CC / 32, NN), 256>>>();
    k_conv_mma<<<dim3(25, 1, NN), 256>>>(0, b1, bs, nullptr);
    k_h1t<<<dim3(50, OC / 32, NN), 256>>>();
    k_conv_mma<<<dim3(25, 1, NN), 256>>>(1, b2, nullptr, out);
    (void)out_size; (void)n_in;
}

// round 9
// speedup vs baseline: 3.4883x; 1.1276x over previous
#include <cuda_runtime.h>
#include <cuda_bf16.h>
#include <math.h>
#include <stdint.h>

#define NN 10
#define CC 512
#define HW 1600
#define OC 128
#define IMG 40
#define MROWS 1280   // 1152 folded-conv1 rows + 128 shortcut rows
#define K1 4608      // conv1 K = 9*512
#define K2 1152      // conv2 K = 9*128

// ---------------- scratch (device globals) ----------------
__device__ float g_NF[NN*CC*HW];
__device__ float g_SIVraw[NN*CC];
__device__ float g_SIV[NN*CC];
__device__ float g_cm[NN*NN*HW];
__device__ float g_corr[NN*NN*NN];
__device__ float g_sv[NN*NN];
__device__ float g_wv[NN*NN];
__device__ float g_CSA[NN*HW];
__device__ int   g_idx[NN*HW];
__device__ __align__(16) __nv_bfloat16 g_Wc_hi[MROWS*HW];
__device__ __align__(16) __nv_bfloat16 g_Wc_lo[MROWS*HW];
__device__ __align__(16) __nv_bfloat16 g_Ag_hi[NN*CC*HW];
__device__ __align__(16) __nv_bfloat16 g_Ag_lo[NN*CC*HW];
__device__ __align__(16) __nv_bfloat16 g_Wk1_hi[NN*OC*K1];  // folded conv1 w [n][o][t*512+c]
__device__ __align__(16) __nv_bfloat16 g_Wk1_lo[NN*OC*K1];
__device__ __align__(16) __nv_bfloat16 g_Wsc_hi[NN*OC*CC];  // folded shortcut w [n][o][c]
__device__ __align__(16) __nv_bfloat16 g_Wsc_lo[NN*OC*CC];
__device__ __align__(16) __nv_bfloat16 g_W2k_hi[OC*K2];     // w2 [o][t*128+c]
__device__ __align__(16) __nv_bfloat16 g_W2k_lo[OC*K2];
__device__ __align__(16) __nv_bfloat16 g_Xt_hi[NN*HW*CC];   // (NF*CSA)^T [n][p][c]
__device__ __align__(16) __nv_bfloat16 g_Xt_lo[NN*HW*CC];
__device__ __align__(16) __nv_bfloat16 g_H1t_hi[NN*HW*OC];  // H1^T [n][p][o]
__device__ __align__(16) __nv_bfloat16 g_H1t_lo[NN*HW*OC];
__device__ float g_H1[NN*OC*HW];
__device__ float g_SC[NN*OC*HW];

// ---------------- helpers ----------------
__device__ __forceinline__ double blockReduceSumD(double v) {
    __shared__ double sh[32];
    int lane = threadIdx.x & 31, wid = threadIdx.x >> 5;
#pragma unroll
    for (int o = 16; o > 0; o >>= 1) v += __shfl_down_sync(0xffffffffu, v, o);
    if (lane == 0) sh[wid] = v;
    __syncthreads();
    if (wid == 0) {
        int nw = blockDim.x >> 5;
        v = (lane < nw) ? sh[lane] : 0.0;
#pragma unroll
        for (int o = 16; o > 0; o >>= 1) v += __shfl_down_sync(0xffffffffu, v, o);
    }
    return v;
}
__device__ __forceinline__ void kadd(float& s, float& c, float p) {
    float y = __fsub_rn(p, c);
    float t = __fadd_rn(s, y);
    c = __fsub_rn(__fsub_rn(t, s), y);
    s = t;
}
__device__ __forceinline__ uint32_t smem_u32(const void* p) {
    uint32_t a;
    asm("{ .reg .u64 t; cvta.to.shared.u64 t, %1; cvt.u32.u64 %0, t; }" : "=r"(a) : "l"(p));
    return a;
}
__device__ __forceinline__ void ldsm_x4(uint32_t& r0, uint32_t& r1, uint32_t& r2, uint32_t& r3, uint32_t a) {
    asm volatile("ldmatrix.sync.aligned.m8n8.x4.shared.b16 {%0,%1,%2,%3}, [%4];"
                 : "=r"(r0), "=r"(r1), "=r"(r2), "=r"(r3) : "r"(a));
}
__device__ __forceinline__ void ldsm_x2(uint32_t& r0, uint32_t& r1, uint32_t a) {
    asm volatile("ldmatrix.sync.aligned.m8n8.x2.shared.b16 {%0,%1}, [%2];"
                 : "=r"(r0), "=r"(r1) : "r"(a));
}
__device__ __forceinline__ void hmma(float* c, const uint32_t* a, uint32_t b0, uint32_t b1) {
    asm volatile("mma.sync.aligned.m16n8k16.row.col.f32.bf16.bf16.f32 "
                 "{%0,%1,%2,%3},{%4,%5,%6,%7},{%8,%9},{%0,%1,%2,%3};"
                 : "+f"(c[0]), "+f"(c[1]), "+f"(c[2]), "+f"(c[3])
                 : "r"(a[0]), "r"(a[1]), "r"(a[2]), "r"(a[3]), "r"(b0), "r"(b1));
}
__device__ __forceinline__ uint32_t pack_hi2(float a, float b) {
    __nv_bfloat16 ha = __float2bfloat16(a), hb = __float2bfloat16(b);
    return (uint32_t)__bfloat16_as_ushort(ha) | ((uint32_t)__bfloat16_as_ushort(hb) << 16);
}
__device__ __forceinline__ uint32_t pack_lo2(float a, float b) {
    __nv_bfloat16 ha = __float2bfloat16(a), hb = __float2bfloat16(b);
    __nv_bfloat16 la = __float2bfloat16(a - __bfloat162float(ha));
    __nv_bfloat16 lb = __float2bfloat16(b - __bfloat162float(hb));
    return (uint32_t)__bfloat16_as_ushort(la) | ((uint32_t)__bfloat16_as_ushort(lb) << 16);
}

// ---------------- 1: per-pixel L2 norm over C ----------------
__global__ void k_norm(const float* __restrict__ feats) {
    int n = blockIdx.y;
    int tid = threadIdx.x;
    int cg = tid >> 6, kk = tid & 63;
    int hw = blockIdx.x * 64 + kk;
    const float* f = feats + (size_t)n * CC * HW + hw;
    float s = 0.f, comp = 0.f;
    for (int c = cg * 128; c < cg * 128 + 128; c++) {
        float v = f[(size_t)c * HW];
        kadd(s, comp, __fmul_rn(v, v));
    }
    __shared__ double sh[4][64];
    __shared__ float sd[64];
    sh[cg][kk] = (double)s + (double)comp;
    __syncthreads();
    if (tid < 64) {
        double S = sh[0][tid] + sh[1][tid] + sh[2][tid] + sh[3][tid];
        sd[tid] = fmaxf(sqrtf((float)S), 1e-12f);
    }
    __syncthreads();
    float d = sd[kk];
    float* o = g_NF + (size_t)n * CC * HW + hw;
    for (int c = cg * 128; c < cg * 128 + 128; c++)
        o[(size_t)c * HW] = f[(size_t)c * HW] / d;
}

// ---------------- 2: SIV raw ----------------
__global__ void k_siv_raw(const float* __restrict__ sisms) {
    int b = blockIdx.x;
    int n = b >> 9;
    double s = 0.0;
    for (int k = threadIdx.x; k < HW; k += 256) {
        float pm = g_NF[(size_t)b * HW + k] * sisms[n * HW + k];
        s += (double)pm;
    }
    s = blockReduceSumD(s);
    if (threadIdx.x == 0) g_SIVraw[b] = ((float)s) / 1600.0f;
}

// ---------------- 3: SIV l2 norm ----------------
__global__ void k_siv_norm() {
    int n = blockIdx.x, t = threadIdx.x;
    float v = g_SIVraw[n * CC + t];
    float sq = v * v;
    double s = blockReduceSumD((double)sq);
    __shared__ float s_d;
    if (t == 0) s_d = fmaxf(sqrtf((float)s), 1e-12f);
    __syncthreads();
    g_SIV[n * CC + t] = v / s_d;
}

// ---------------- 4: cm ----------------
__global__ void k_cm() {
    __shared__ float s_siv[NN * CC];
    __shared__ double sh[4][64][NN];
    int n = blockIdx.y;
    int tid = threadIdx.x;
    for (int q = tid; q < NN * CC; q += 256) s_siv[q] = g_SIV[q];
    int cg = tid >> 6, kk = tid & 63;
    int k = blockIdx.x * 64 + kk;
    const float* nfp = g_NF + (size_t)n * CC * HW + k;
    __syncthreads();
    float s[NN], comp[NN];
#pragma unroll
    for (int m = 0; m < NN; m++) { s[m] = 0.f; comp[m] = 0.f; }
    for (int c = cg * 128; c < cg * 128 + 128; c++) {
        float nf = nfp[(size_t)c * HW];
#pragma unroll
        for (int m = 0; m < NN; m++) kadd(s[m], comp[m], __fmul_rn(nf, s_siv[m * CC + c]));
    }
#pragma unroll
    for (int m = 0; m < NN; m++) sh[cg][kk][m] = (double)s[m] + (double)comp[m];
    __syncthreads();
    for (int e = tid; e < 64 * NN; e += 256) {
        int kk2 = e / NN, m = e % NN;
        double v = sh[0][kk2][m] + sh[1][kk2][m] + sh[2][kk2][m] + sh[3][kk2][m];
        g_cm[(size_t)(n * NN + m) * HW + blockIdx.x * 64 + kk2] = (float)v;
    }
}

// ---------------- 5: cm row norm ----------------
__global__ void k_cm_norm() {
    int row = blockIdx.x;
    size_t base = (size_t)row * HW;
    double ss = 0.0;
    for (int k = threadIdx.x; k < HW; k += 256) {
        float v = g_cm[base + k];
        float sq = v * v;
        ss += (double)sq;
    }
    ss = blockReduceSumD(ss);
    __shared__ float s_d;
    if (threadIdx.x == 0) s_d = fmaxf(sqrtf((float)ss), 1e-12f);
    __syncthreads();
    for (int k = threadIdx.x; k < HW; k += 256) g_cm[base + k] = g_cm[base + k] / s_d;
}

// ---------------- 6: corr ----------------
__global__ void k_corr() {
    int b = blockIdx.x;
    int p = b % NN;
    int m = (b / NN) % NN;
    int n = b / (NN * NN);
    double s = 0.0;
    for (int k = threadIdx.x; k < HW; k += 256)
        s += (double)g_cm[(size_t)(n * NN + m) * HW + k] * (double)g_cm[(size_t)(n * NN + p) * HW + k];
    s = blockReduceSumD(s);
    if (threadIdx.x == 0) g_corr[b] = (float)s;
}

// ---------------- 7: sv ----------------
__global__ void k_sv() {
    int t = threadIdx.x;
    if (t >= NN * NN) return;
    double s = 0.0;
#pragma unroll
    for (int p = 0; p < NN; p++) s += (double)g_corr[t * NN + p];
    g_sv[t] = (float)s;
}

// ---------------- 8: softmax ----------------
__global__ void k_softmax() {
    int n = threadIdx.x;
    if (n >= NN) return;
    float mx = -1e30f;
    for (int m = 0; m < NN; m++) mx = fmaxf(mx, g_sv[n * NN + m]);
    float e[NN];
    double sum = 0.0;
    for (int m = 0; m < NN; m++) {
        float t = g_sv[n * NN + m] - mx;
        e[m] = (float)exp((double)t);
        sum += (double)e[m];
    }
    float S = (float)sum;
    for (int m = 0; m < NN; m++) g_wv[n * NN + m] = e[m] / S;
}

// ---------------- 9: CSA ----------------
__global__ void k_csa() {
    int n = blockIdx.x, tid = threadIdx.x;
    __shared__ float s_wv[NN];
    __shared__ float sc[HW];
    __shared__ float red[512];
    if (tid < NN) s_wv[tid] = g_wv[n * NN + tid];
    __syncthreads();
    float lmin = 1e30f, lmax = -1e30f;
    for (int k = tid; k < HW; k += 512) {
        double a = 0.0;
#pragma unroll
        for (int m = 0; m < NN; m++) {
            float pm = g_cm[(size_t)(n * NN + m) * HW + k] * s_wv[m];
            a += (double)pm;
        }
        float raw = (float)a;
        sc[k] = raw;
        lmin = fminf(lmin, raw); lmax = fmaxf(lmax, raw);
    }
    red[tid] = lmin; __syncthreads();
    for (int s = 256; s > 0; s >>= 1) { if (tid < s) red[tid] = fminf(red[tid], red[tid + s]); __syncthreads(); }
    float mn = red[0]; __syncthreads();
    red[tid] = lmax; __syncthreads();
    for (int s = 256; s > 0; s >>= 1) { if (tid < s) red[tid] = fmaxf(red[tid], red[tid + s]); __syncthreads(); }
    float mx = red[0]; __syncthreads();
    float den = (mx - mn) + 1e-12f;
    for (int k = tid; k < HW; k += 512) {
        float num = sc[k] - mn;
        g_CSA[n * HW + k] = num / den;
    }
}

// ---------------- 10: argsort ----------------
__global__ void k_sort() {
    __shared__ float key[2048];
    __shared__ int   idv[2048];
    int n = blockIdx.x, tid = threadIdx.x;
    for (int e = tid; e < 2048; e += 1024) {
        if (e < HW) { key[e] = g_CSA[n * HW + e]; idv[e] = e; }
        else        { key[e] = -1e30f;            idv[e] = e; }
    }
    __syncthreads();
    for (int k = 2; k <= 2048; k <<= 1) {
        for (int j = k >> 1; j > 0; j >>= 1) {
            for (int e = tid; e < 2048; e += 1024) {
                int ix = e ^ j;
                if (ix > e) {
                    float ka = key[e], kb = key[ix];
                    int ia = idv[e], ib = idv[ix];
                    bool up = ((e & k) == 0);
                    bool b_before_a = (kb > ka) || (kb == ka && ib < ia);
                    bool dosw = up ? b_before_a : !b_before_a;
                    if (dosw) { key[e] = kb; key[ix] = ka; idv[e] = ib; idv[ix] = ia; }
                }
            }
            __syncthreads();
        }
    }
    for (int e = tid; e < HW; e += 1024) g_idx[n * HW + e] = idv[e];
}

// ---------------- 11: gather + bf16 split ----------------
__global__ void k_gather_split() {
    int b = blockIdx.x;
    int n = b >> 9;
    for (int i = threadIdx.x; i < HW; i += 256) {
        float v = g_NF[(size_t)b * HW + g_idx[n * HW + i]];
        __nv_bfloat16 h = __float2bfloat16(v);
        __nv_bfloat16 l = __float2bfloat16(v - __bfloat162float(h));
        g_Ag_hi[(size_t)b * HW + i] = h;
        g_Ag_lo[(size_t)b * HW + i] = l;
    }
}

// ---------------- 12: weight concat + split ----------------
__global__ void k_wsplit(const float* __restrict__ w1, const float* __restrict__ ws) {
    int q = blockIdx.x * 256 + threadIdx.x;
    if (q >= MROWS * HW) return;
    int i = q % HW, r = q / HW;
    float f;
    if (r < OC * 9) {
        int o = r / 9, t = r % 9;
        f = w1[(o * HW + i) * 9 + t];
    } else {
        f = ws[(r - OC * 9) * HW + i];
    }
    __nv_bfloat16 h = __float2bfloat16(f);
    __nv_bfloat16 l = __float2bfloat16(f - __bfloat162float(h));
    g_Wc_hi[q] = h;
    g_Wc_lo[q] = l;
}
__global__ void k_w2split(const float* __restrict__ w2) {
    int q = blockIdx.x * 256 + threadIdx.x;
    if (q >= OC * K2) return;
    int k = q % K2, o = q / K2;
    int t = k / OC, c = k % OC;
    float f = w2[(o * OC + c) * 9 + t];
    __nv_bfloat16 h = __float2bfloat16(f);
    __nv_bfloat16 l = __float2bfloat16(f - __bfloat162float(h));
    g_W2k_hi[q] = h;
    g_W2k_lo[q] = l;
}

// ---------------- 13: fold GEMM via mma.sync bf16x3 (register-prefetch) ----------
#define LDT 40

__global__ __launch_bounds__(256) void k_gemm_mma() {
    __shared__ __nv_bfloat16 sAh[128 * LDT], sAl[128 * LDT];
    __shared__ __nv_bfloat16 sBh[128 * LDT], sBl[128 * LDT];
    int n = blockIdx.z;
    int m0 = blockIdx.x * 128, n0 = blockIdx.y * 128;
    const __nv_bfloat16* Bh = g_Ag_hi + (size_t)n * CC * HW;
    const __nv_bfloat16* Bl = g_Ag_lo + (size_t)n * CC * HW;
    int tid = threadIdx.x, lane = tid & 31, wid = tid >> 5;
    int wm = wid & 3, wn = wid >> 2;

    float c[2][8][4];
#pragma unroll
    for (int i = 0; i < 2; i++)
#pragma unroll
        for (int j = 0; j < 8; j++)
#pragma unroll
            for (int q = 0; q < 4; q++) c[i][j][q] = 0.f;

    int lrow = tid >> 1, lk = (tid & 1) * 16;
    const __nv_bfloat16* pAh = g_Wc_hi + (size_t)(m0 + lrow) * HW + lk;
    const __nv_bfloat16* pAl = g_Wc_lo + (size_t)(m0 + lrow) * HW + lk;
    const __nv_bfloat16* pBh = Bh + (size_t)(n0 + lrow) * HW + lk;
    const __nv_bfloat16* pBl = Bl + (size_t)(n0 + lrow) * HW + lk;
    uint32_t so = (uint32_t)(lrow * LDT + lk) * 2;
    uint32_t uAh = smem_u32(sAh), uAl = smem_u32(sAl);
    uint32_t uBh = smem_u32(sBh), uBl = smem_u32(sBl);
    int arow = (lane & 15), akoff = 8 * (lane >> 4);
    int brow = (lane & 7),  bkoff = 8 * ((lane >> 3) & 1);

    uint4 r0, r1, r2, r3, r4, r5, r6, r7;
#define FLD(k0) do { \
    r0 = *(const uint4*)(pAh + (k0)); r1 = *(const uint4*)(pAh + (k0) + 8); \
    r2 = *(const uint4*)(pAl + (k0)); r3 = *(const uint4*)(pAl + (k0) + 8); \
    r4 = *(const uint4*)(pBh + (k0)); r5 = *(const uint4*)(pBh + (k0) + 8); \
    r6 = *(const uint4*)(pBl + (k0)); r7 = *(const uint4*)(pBl + (k0) + 8); } while (0)
#define FST() do { \
    *(uint4*)((char*)sAh + so) = r0; *(uint4*)((char*)sAh + so + 16) = r1; \
    *(uint4*)((char*)sAl + so) = r2; *(uint4*)((char*)sAl + so + 16) = r3; \
    *(uint4*)((char*)sBh + so) = r4; *(uint4*)((char*)sBh + so + 16) = r5; \
    *(uint4*)((char*)sBl + so) = r6; *(uint4*)((char*)sBl + so + 16) = r7; } while (0)

    FLD(0);
    FST();
    __syncthreads();
    for (int kb = 0; kb < 50; kb++) {
        bool more = (kb + 1 < 50);
        if (more) FLD((kb + 1) * 32);
#pragma unroll
        for (int kk = 0; kk < 32; kk += 16) {
            uint32_t ah[2][4], al[2][4];
#pragma unroll
            for (int i = 0; i < 2; i++) {
                uint32_t ao = (uint32_t)((32 * wm + 16 * i + arow) * LDT + kk + akoff) * 2;
                ldsm_x4(ah[i][0], ah[i][1], ah[i][2], ah[i][3], uAh + ao);
                ldsm_x4(al[i][0], al[i][1], al[i][2], al[i][3], uAl + ao);
            }
#pragma unroll
            for (int j = 0; j < 8; j++) {
                uint32_t bo = (uint32_t)((64 * wn + 8 * j + brow) * LDT + kk + bkoff) * 2;
                uint32_t bh0, bh1, bl0, bl1;
                ldsm_x2(bh0, bh1, uBh + bo);
                ldsm_x2(bl0, bl1, uBl + bo);
#pragma unroll
                for (int i = 0; i < 2; i++) {
                    hmma(c[i][j], ah[i], bh0, bh1);
                    hmma(c[i][j], ah[i], bl0, bl1);
                    hmma(c[i][j], al[i], bh0, bh1);
                }
            }
        }
        __syncthreads();
        if (more) {
            FST();
        }
        __syncthreads();
    }
#undef FLD
#undef FST
    // epilogue: split to bf16 hi/lo, route into conv-ready layouts
#pragma unroll
    for (int i = 0; i < 2; i++) {
        int rb = m0 + 32 * wm + 16 * i + (lane >> 2);
#pragma unroll
        for (int half = 0; half < 2; half++) {
            int r = rb + half * 8;
#pragma unroll
            for (int j = 0; j < 8; j++) {
                int col = n0 + 64 * wn + 8 * j + (lane & 3) * 2;
                float v0 = c[i][j][half * 2], v1 = c[i][j][half * 2 + 1];
                size_t off;
                __nv_bfloat16 *dh, *dl;
                if (r < OC * 9) {
                    int o = r / 9, t = r % 9;
                    off = ((size_t)n * OC + o) * K1 + t * CC + col;
                    dh = g_Wk1_hi; dl = g_Wk1_lo;
                } else {
                    int o = r - OC * 9;
                    off = ((size_t)n * OC + o) * CC + col;
                    dh = g_Wsc_hi; dl = g_Wsc_lo;
                }
                *(uint32_t*)(dh + off) = pack_hi2(v0, v1);
                *(uint32_t*)(dl + off) = pack_lo2(v0, v1);
            }
        }
    }
}

// ---------------- 14: Xt = (NF*CSA)^T split (tiled transpose) ----------------
__global__ void k_xt() {
    __shared__ float sT[32][33];
    int n = blockIdx.z;
    int p0 = blockIdx.x * 32, c0 = blockIdx.y * 32;
    int tid = threadIdx.x;
    int tc = tid >> 5, tp = tid & 31;
#pragma unroll
    for (int r = 0; r < 4; r++) {
        int c = c0 + tc + r * 8;
        sT[tc + r * 8][tp] = g_NF[((size_t)n * CC + c) * HW + p0 + tp] * g_CSA[n * HW + p0 + tp];
    }
    __syncthreads();
#pragma unroll
    for (int r = 0; r < 4; r++) {
        int p = p0 + tc + r * 8;
        float v = sT[tp][tc + r * 8];
        __nv_bfloat16 h = __float2bfloat16(v);
        __nv_bfloat16 l = __float2bfloat16(v - __bfloat162float(h));
        g_Xt_hi[((size_t)n * HW + p) * CC + c0 + tp] = h;
        g_Xt_lo[((size_t)n * HW + p) * CC + c0 + tp] = l;
    }
}
__global__ void k_h1t() {
    __shared__ float sT[32][33];
    int n = blockIdx.z;
    int p0 = blockIdx.x * 32, c0 = blockIdx.y * 32;
    int tid = threadIdx.x;
    int tc = tid >> 5, tp = tid & 31;
#pragma unroll
    for (int r = 0; r < 4; r++) {
        int c = c0 + tc + r * 8;
        sT[tc + r * 8][tp] = g_H1[((size_t)n * OC + c) * HW + p0 + tp];
    }
    __syncthreads();
#pragma unroll
    for (int r = 0; r < 4; r++) {
        int p = p0 + tc + r * 8;
        float v = sT[tp][tc + r * 8];
        __nv_bfloat16 h = __float2bfloat16(v);
        __nv_bfloat16 l = __float2bfloat16(v - __bfloat162float(h));
        g_H1t_hi[((size_t)n * HW + p) * OC + c0 + tp] = h;
        g_H1t_lo[((size_t)n * HW + p) * OC + c0 + tp] = l;
    }
}

// ---------------- 15: conv via mma.sync bf16x3 (implicit GEMM, prefetch) ---------
__global__ __launch_bounds__(256) void k_conv_mma(int mode, const float* __restrict__ bias,
                                                  const float* __restrict__ bsc,
                                                  float* __restrict__ dout) {
    __shared__ __nv_bfloat16 sAh[128 * LDT], sAl[128 * LDT];
    __shared__ __nv_bfloat16 sBh[64 * LDT],  sBl[64 * LDT];
    int n = blockIdx.z;
    int p0 = blockIdx.x * 64;
    int tid = threadIdx.x, lane = tid & 31, wid = tid >> 5;
    int wm = wid & 3, wn = wid >> 2;

    const __nv_bfloat16 *Ah, *Al, *Bh, *Bl;
    int K, Cin, nslab;
    if (mode == 0) {
        Ah = g_Wk1_hi + (size_t)n * OC * K1; Al = g_Wk1_lo + (size_t)n * OC * K1;
        Bh = g_Xt_hi + (size_t)n * HW * CC;  Bl = g_Xt_lo + (size_t)n * HW * CC;
        K = K1; Cin = CC; nslab = K1 / 32;
    } else {
        Ah = g_W2k_hi; Al = g_W2k_lo;
        Bh = g_H1t_hi + (size_t)n * HW * OC; Bl = g_H1t_lo + (size_t)n * HW * OC;
        K = K2; Cin = OC; nslab = K2 / 32;
    }
    int slabs_per_tap = Cin / 32;

    uint32_t uAh = smem_u32(sAh), uAl = smem_u32(sAl);
    uint32_t uBh = smem_u32(sBh), uBl = smem_u32(sBl);
    int alrow = tid >> 1, alk = (tid & 1) * 16;
    int blrow = tid >> 2, blc = (tid & 3) * 8;
    int bp = p0 + blrow;
    int bpx = bp % IMG, bpy = bp / IMG;
    int arow = (lane & 15), akoff = 8 * (lane >> 4);
    int brow = (lane & 7),  bkoff = 8 * ((lane >> 3) & 1);
    uint32_t soA = (uint32_t)(alrow * LDT + alk) * 2;
    uint32_t soB = (uint32_t)(blrow * LDT + blc) * 2;

    float c[2][4][4];
#pragma unroll
    for (int i = 0; i < 2; i++)
#pragma unroll
        for (int j = 0; j < 4; j++)
#pragma unroll
            for (int q = 0; q < 4; q++) c[i][j][q] = 0.f;

    uint4 ra0, ra1, ra2, ra3, rb0, rb1;
#define CLD(kb) do { \
    int t_ = (kb) / slabs_per_tap, c0_ = ((kb) % slabs_per_tap) * 32; \
    int dy_ = t_ / 3 - 1, dx_ = t_ % 3 - 1, off_ = dy_ * IMG + dx_; \
    bool valid_ = ((unsigned)(bpx + dx_) < (unsigned)IMG) && ((unsigned)(bpy + dy_) < (unsigned)IMG); \
    size_t gA_ = (size_t)alrow * K + (kb) * 32 + alk; \
    ra0 = *(const uint4*)(Ah + gA_); ra1 = *(const uint4*)(Ah + gA_ + 8); \
    ra2 = *(const uint4*)(Al + gA_); ra3 = *(const uint4*)(Al + gA_ + 8); \
    rb0 = make_uint4(0, 0, 0, 0); rb1 = make_uint4(0, 0, 0, 0); \
    if (valid_) { \
        size_t gB_ = (size_t)(bp + off_) * Cin + c0_ + blc; \
        rb0 = *(const uint4*)(Bh + gB_); rb1 = *(const uint4*)(Bl + gB_); \
    } } while (0)
#define CST() do { \
    *(uint4*)((char*)sAh + soA) = ra0; *(uint4*)((char*)sAh + soA + 16) = ra1; \
    *(uint4*)((char*)sAl + soA) = ra2; *(uint4*)((char*)sAl + soA + 16) = ra3; \
    *(uint4*)((char*)sBh + soB) = rb0; *(uint4*)((char*)sBl + soB) = rb1; } while (0)
#define CCOMPUTE() do { \
    _Pragma("unroll") \
    for (int kk = 0; kk < 32; kk += 16) { \
        uint32_t ah[2][4], al[2][4]; \
        _Pragma("unroll") \
        for (int i = 0; i < 2; i++) { \
            uint32_t ao = (uint32_t)((32 * wm + 16 * i + arow) * LDT + kk + akoff) * 2; \
            ldsm_x4(ah[i][0], ah[i][1], ah[i][2], ah[i][3], uAh + ao); \
            ldsm_x4(al[i][0], al[i][1], al[i][2], al[i][3], uAl + ao); \
        } \
        _Pragma("unroll") \
        for (int j = 0; j < 4; j++) { \
            uint32_t bo = (uint32_t)((32 * wn + 8 * j + brow) * LDT + kk + bkoff) * 2; \
            uint32_t bh0, bh1, bl0, bl1; \
            ldsm_x2(bh0, bh1, uBh + bo); \
            ldsm_x2(bl0, bl1, uBl + bo); \
            _Pragma("unroll") \
            for (int i = 0; i < 2; i++) { \
                hmma(c[i][j], ah[i], bh0, bh1); \
                hmma(c[i][j], ah[i], bl0, bl1); \
                hmma(c[i][j], al[i], bh0, bh1); \
            } \
        } \
    } } while (0)

    CLD(0);
    CST();
    __syncthreads();
    for (int kb = 0; kb < nslab; kb++) {
        bool more = (kb + 1 < nslab);
        if (more) CLD(kb + 1);
        CCOMPUTE();
        __syncthreads();
        if (more) {
            CST();
        }
        __syncthreads();
    }
    // epilogue phase 1
#pragma unroll
    for (int i = 0; i < 2; i++) {
        int rb = 32 * wm + 16 * i + (lane >> 2);
#pragma unroll
        for (int half = 0; half < 2; half++) {
            int o = rb + half * 8;
            float bo = bias[o];
#pragma unroll
            for (int j = 0; j < 4; j++) {
                int p = p0 + 32 * wn + 8 * j + (lane & 3) * 2;
                float v0 = c[i][j][half * 2] + bo, v1 = c[i][j][half * 2 + 1] + bo;
                if (mode == 0) {
                    *(float2*)&g_H1[((size_t)n * OC + o) * HW + p] =
                        make_float2(fmaxf(v0, 0.f), fmaxf(v1, 0.f));
                } else {
                    float2 sc = *(const float2*)&g_SC[((size_t)n * OC + o) * HW + p];
                    *(float2*)&dout[((size_t)n * OC + o) * HW + p] =
                        make_float2(fmaxf(v0 + sc.x, 0.f), fmaxf(v1 + sc.y, 0.f));
                }
            }
        }
    }
    if (mode != 0) return;

    // ---- phase 2: 1x1 shortcut (K=512), register-prefetched ----
#pragma unroll
    for (int i = 0; i < 2; i++)
#pragma unroll
        for (int j = 0; j < 4; j++)
#pragma unroll
            for (int q = 0; q < 4; q++) c[i][j][q] = 0.f;
    const __nv_bfloat16* Sh = g_Wsc_hi + (size_t)n * OC * CC;
    const __nv_bfloat16* Sl = g_Wsc_lo + (size_t)n * OC * CC;
#define SLD(kb) do { \
    size_t gA_ = (size_t)alrow * CC + (kb) * 32 + alk; \
    ra0 = *(const uint4*)(Sh + gA_); ra1 = *(const uint4*)(Sh + gA_ + 8); \
    ra2 = *(const uint4*)(Sl + gA_); ra3 = *(const uint4*)(Sl + gA_ + 8); \
    size_t gB_ = (size_t)bp * CC + (kb) * 32 + blc; \
    rb0 = *(const uint4*)(Bh + gB_); rb1 = *(const uint4*)(Bl + gB_); } while (0)

    SLD(0);
    CST();
    __syncthreads();
    for (int kb = 0; kb < CC / 32; kb++) {
        bool more = (kb + 1 < CC / 32);
        if (more) SLD(kb + 1);
        CCOMPUTE();
        __syncthreads();
        if (more) {
            CST();
        }
        __syncthreads();
    }
#undef SLD
#undef CLD
#undef CST
#undef CCOMPUTE
#pragma unroll
    for (int i = 0; i < 2; i++) {
        int rb = 32 * wm + 16 * i + (lane >> 2);
#pragma unroll
        for (int half = 0; half < 2; half++) {
            int o = rb + half * 8;
            float bo = bsc[o];
#pragma unroll
            for (int j = 0; j < 4; j++) {
                int p = p0 + 32 * wn + 8 * j + (lane & 3) * 2;
                *(float2*)&g_SC[((size_t)n * OC + o) * HW + p] =
                    make_float2(c[i][j][half * 2] + bo, c[i][j][half * 2 + 1] + bo);
            }
        }
    }
}

// ---------------- launch ----------------
extern "C" void kernel_launch(void* const* d_in, const int* in_sizes, int n_in,
                              void* d_out, int out_size) {
    const float *feats = nullptr, *sisms = nullptr, *w1 = nullptr, *w2 = nullptr, *ws = nullptr;
    const float *b1 = nullptr, *b2 = nullptr, *bs = nullptr;
    for (int i = 0; i < n_in; i++) {
        int s = in_sizes[i];
        const float* p = (const float*)d_in[i];
        if (s == NN * CC * HW) feats = p;
        else if (s == NN * HW) sisms = p;
        else if (s == OC * HW * 9) w1 = p;
        else if (s == OC * OC * 9) w2 = p;
        else if (s == OC * HW) ws = p;
        else if (s == OC) { if (!b1) b1 = p; else if (!b2) b2 = p; else bs = p; }
    }
    float* out = (float*)d_out;

    k_norm<<<dim3(25, NN), 256>>>(feats);
    k_siv_raw<<<NN * CC, 256>>>(sisms);
    k_siv_norm<<<NN, CC>>>();
    k_cm<<<dim3(25, NN), 256>>>();
    k_cm_norm<<<NN * NN, 256>>>();
    k_corr<<<NN * NN * NN, 256>>>();
    k_sv<<<1, 128>>>();
    k_softmax<<<1, 16>>>();
    k_csa<<<NN, 512>>>();
    k_sort<<<NN, 1024>>>();
    k_gather_split<<<NN * CC, 256>>>();
    k_wsplit<<<(MROWS * HW + 255) / 256, 256>>>(w1, ws);
    k_w2split<<<(OC * K2 + 255) / 256, 256>>>(w2);
    k_gemm_mma<<<dim3(MROWS / 128, CC / 128, NN), 256>>>();
    k_xt<<<dim3(50, CC / 32, NN), 256>>>();
    k_conv_mma<<<dim3(25, 1, NN), 256>>>(0, b1, bs, nullptr);
    k_h1t<<<dim3(50, OC / 32, NN), 256>>>();
    k_conv_mma<<<dim3(25, 1, NN), 256>>>(1, b2, nullptr, out);
    (void)out_size; (void)n_in;
}

// round 10
// speedup vs baseline: 3.5097x; 1.0061x over previous
#include <cuda_runtime.h>
#include <cuda_bf16.h>
#include <math.h>
#include <stdint.h>

#define NN 10
#define CC 512
#define HW 1600
#define OC 128
#define IMG 40
#define MROWS 1280   // 1152 folded-conv1 rows + 128 shortcut rows
#define K1 4608      // conv1 K = 9*512
#define K2 1152      // conv2 K = 9*128
#define LDT 40

// ---------------- scratch (device globals) ----------------
__device__ float g_NF[NN*CC*HW];
__device__ float g_SIVraw[NN*CC];
__device__ float g_SIV[NN*CC];
__device__ float g_cm[NN*NN*HW];
__device__ float g_corr[NN*NN*NN];
__device__ float g_sv[NN*NN];
__device__ float g_wv[NN*NN];
__device__ float g_CSA[NN*HW];
__device__ int   g_idx[NN*HW];
__device__ __align__(16) __nv_bfloat16 g_Wc_hi[MROWS*HW];
__device__ __align__(16) __nv_bfloat16 g_Wc_lo[MROWS*HW];
__device__ __align__(16) __nv_bfloat16 g_Ag_hi[NN*CC*HW];
__device__ __align__(16) __nv_bfloat16 g_Ag_lo[NN*CC*HW];
__device__ __align__(16) __nv_bfloat16 g_Wk1_hi[NN*OC*K1];
__device__ __align__(16) __nv_bfloat16 g_Wk1_lo[NN*OC*K1];
__device__ __align__(16) __nv_bfloat16 g_Wsc_hi[NN*OC*CC];
__device__ __align__(16) __nv_bfloat16 g_Wsc_lo[NN*OC*CC];
__device__ __align__(16) __nv_bfloat16 g_W2k_hi[OC*K2];
__device__ __align__(16) __nv_bfloat16 g_W2k_lo[OC*K2];
__device__ __align__(16) __nv_bfloat16 g_Xt_hi[NN*HW*CC];
__device__ __align__(16) __nv_bfloat16 g_Xt_lo[NN*HW*CC];
__device__ __align__(16) __nv_bfloat16 g_H1t_hi[NN*HW*OC];
__device__ __align__(16) __nv_bfloat16 g_H1t_lo[NN*HW*OC];
__device__ float g_SC[NN*OC*HW];

// ---------------- helpers ----------------
__device__ __forceinline__ double blockReduceSumD(double v) {
    __shared__ double sh[32];
    int lane = threadIdx.x & 31, wid = threadIdx.x >> 5;
#pragma unroll
    for (int o = 16; o > 0; o >>= 1) v += __shfl_down_sync(0xffffffffu, v, o);
    if (lane == 0) sh[wid] = v;
    __syncthreads();
    if (wid == 0) {
        int nw = blockDim.x >> 5;
        v = (lane < nw) ? sh[lane] : 0.0;
#pragma unroll
        for (int o = 16; o > 0; o >>= 1) v += __shfl_down_sync(0xffffffffu, v, o);
    }
    return v;
}
__device__ __forceinline__ void kadd(float& s, float& c, float p) {
    float y = __fsub_rn(p, c);
    float t = __fadd_rn(s, y);
    c = __fsub_rn(__fsub_rn(t, s), y);
    s = t;
}
__device__ __forceinline__ uint32_t smem_u32(const void* p) {
    uint32_t a;
    asm("{ .reg .u64 t; cvta.to.shared.u64 t, %1; cvt.u32.u64 %0, t; }" : "=r"(a) : "l"(p));
    return a;
}
__device__ __forceinline__ void ldsm_x4(uint32_t& r0, uint32_t& r1, uint32_t& r2, uint32_t& r3, uint32_t a) {
    asm volatile("ldmatrix.sync.aligned.m8n8.x4.shared.b16 {%0,%1,%2,%3}, [%4];"
                 : "=r"(r0), "=r"(r1), "=r"(r2), "=r"(r3) : "r"(a));
}
__device__ __forceinline__ void ldsm_x2(uint32_t& r0, uint32_t& r1, uint32_t a) {
    asm volatile("ldmatrix.sync.aligned.m8n8.x2.shared.b16 {%0,%1}, [%2];"
                 : "=r"(r0), "=r"(r1) : "r"(a));
}
__device__ __forceinline__ void hmma(float* c, const uint32_t* a, uint32_t b0, uint32_t b1) {
    asm volatile("mma.sync.aligned.m16n8k16.row.col.f32.bf16.bf16.f32 "
                 "{%0,%1,%2,%3},{%4,%5,%6,%7},{%8,%9},{%0,%1,%2,%3};"
                 : "+f"(c[0]), "+f"(c[1]), "+f"(c[2]), "+f"(c[3])
                 : "r"(a[0]), "r"(a[1]), "r"(a[2]), "r"(a[3]), "r"(b0), "r"(b1));
}
__device__ __forceinline__ uint32_t pack_hi2(float a, float b) {
    __nv_bfloat16 ha = __float2bfloat16(a), hb = __float2bfloat16(b);
    return (uint32_t)__bfloat16_as_ushort(ha) | ((uint32_t)__bfloat16_as_ushort(hb) << 16);
}
__device__ __forceinline__ uint32_t pack_lo2(float a, float b) {
    __nv_bfloat16 ha = __float2bfloat16(a), hb = __float2bfloat16(b);
    __nv_bfloat16 la = __float2bfloat16(a - __bfloat162float(ha));
    __nv_bfloat16 lb = __float2bfloat16(b - __bfloat162float(hb));
    return (uint32_t)__bfloat16_as_ushort(la) | ((uint32_t)__bfloat16_as_ushort(lb) << 16);
}

// ---------------- 1: per-pixel L2 norm over C ----------------
__global__ void k_norm(const float* __restrict__ feats) {
    int n = blockIdx.y;
    int tid = threadIdx.x;
    int cg = tid >> 6, kk = tid & 63;
    int hw = blockIdx.x * 64 + kk;
    const float* f = feats + (size_t)n * CC * HW + hw;
    float s = 0.f, comp = 0.f;
    for (int c = cg * 128; c < cg * 128 + 128; c++) {
        float v = f[(size_t)c * HW];
        kadd(s, comp, __fmul_rn(v, v));
    }
    __shared__ double sh[4][64];
    __shared__ float sd[64];
    sh[cg][kk] = (double)s + (double)comp;
    __syncthreads();
    if (tid < 64) {
        double S = sh[0][tid] + sh[1][tid] + sh[2][tid] + sh[3][tid];
        sd[tid] = fmaxf(sqrtf((float)S), 1e-12f);
    }
    __syncthreads();
    float d = sd[kk];
    float* o = g_NF + (size_t)n * CC * HW + hw;
    for (int c = cg * 128; c < cg * 128 + 128; c++)
        o[(size_t)c * HW] = f[(size_t)c * HW] / d;
}

// ---------------- 2: SIV raw ----------------
__global__ void k_siv_raw(const float* __restrict__ sisms) {
    int b = blockIdx.x;
    int n = b >> 9;
    double s = 0.0;
    for (int k = threadIdx.x; k < HW; k += 256) {
        float pm = g_NF[(size_t)b * HW + k] * sisms[n * HW + k];
        s += (double)pm;
    }
    s = blockReduceSumD(s);
    if (threadIdx.x == 0) g_SIVraw[b] = ((float)s) / 1600.0f;
}

// ---------------- 3: SIV l2 norm ----------------
__global__ void k_siv_norm() {
    int n = blockIdx.x, t = threadIdx.x;
    float v = g_SIVraw[n * CC + t];
    float sq = v * v;
    double s = blockReduceSumD((double)sq);
    __shared__ float s_d;
    if (t == 0) s_d = fmaxf(sqrtf((float)s), 1e-12f);
    __syncthreads();
    g_SIV[n * CC + t] = v / s_d;
}

// ---------------- 4: cm ----------------
__global__ void k_cm() {
    __shared__ float s_siv[NN * CC];
    __shared__ double sh[4][64][NN];
    int n = blockIdx.y;
    int tid = threadIdx.x;
    for (int q = tid; q < NN * CC; q += 256) s_siv[q] = g_SIV[q];
    int cg = tid >> 6, kk = tid & 63;
    int k = blockIdx.x * 64 + kk;
    const float* nfp = g_NF + (size_t)n * CC * HW + k;
    __syncthreads();
    float s[NN], comp[NN];
#pragma unroll
    for (int m = 0; m < NN; m++) { s[m] = 0.f; comp[m] = 0.f; }
    for (int c = cg * 128; c < cg * 128 + 128; c++) {
        float nf = nfp[(size_t)c * HW];
#pragma unroll
        for (int m = 0; m < NN; m++) kadd(s[m], comp[m], __fmul_rn(nf, s_siv[m * CC + c]));
    }
#pragma unroll
    for (int m = 0; m < NN; m++) sh[cg][kk][m] = (double)s[m] + (double)comp[m];
    __syncthreads();
    for (int e = tid; e < 64 * NN; e += 256) {
        int kk2 = e / NN, m = e % NN;
        double v = sh[0][kk2][m] + sh[1][kk2][m] + sh[2][kk2][m] + sh[3][kk2][m];
        g_cm[(size_t)(n * NN + m) * HW + blockIdx.x * 64 + kk2] = (float)v;
    }
}

// ---------------- 5: cm row norm ----------------
__global__ void k_cm_norm() {
    int row = blockIdx.x;
    size_t base = (size_t)row * HW;
    double ss = 0.0;
    for (int k = threadIdx.x; k < HW; k += 256) {
        float v = g_cm[base + k];
        float sq = v * v;
        ss += (double)sq;
    }
    ss = blockReduceSumD(ss);
    __shared__ float s_d;
    if (threadIdx.x == 0) s_d = fmaxf(sqrtf((float)ss), 1e-12f);
    __syncthreads();
    for (int k = threadIdx.x; k < HW; k += 256) g_cm[base + k] = g_cm[base + k] / s_d;
}

// ---------------- 6: corr ----------------
__global__ void k_corr() {
    int b = blockIdx.x;
    int p = b % NN;
    int m = (b / NN) % NN;
    int n = b / (NN * NN);
    double s = 0.0;
    for (int k = threadIdx.x; k < HW; k += 256)
        s += (double)g_cm[(size_t)(n * NN + m) * HW + k] * (double)g_cm[(size_t)(n * NN + p) * HW + k];
    s = blockReduceSumD(s);
    if (threadIdx.x == 0) g_corr[b] = (float)s;
}

// ---------------- 7+8: sv + softmax fused ----------------
__global__ void k_svsm() {
    int t = threadIdx.x;
    if (t < NN * NN) {
        double s = 0.0;
#pragma unroll
        for (int p = 0; p < NN; p++) s += (double)g_corr[t * NN + p];
        g_sv[t] = (float)s;
    }
    __syncthreads();
    int n = t;
    if (n >= NN) return;
    float mx = -1e30f;
    for (int m = 0; m < NN; m++) mx = fmaxf(mx, g_sv[n * NN + m]);
    float e[NN];
    double sum = 0.0;
    for (int m = 0; m < NN; m++) {
        float tt = g_sv[n * NN + m] - mx;
        e[m] = (float)exp((double)tt);
        sum += (double)e[m];
    }
    float S = (float)sum;
    for (int m = 0; m < NN; m++) g_wv[n * NN + m] = e[m] / S;
}

// ---------------- 9: CSA ----------------
__global__ void k_csa() {
    int n = blockIdx.x, tid = threadIdx.x;
    __shared__ float s_wv[NN];
    __shared__ float sc[HW];
    __shared__ float red[512];
    if (tid < NN) s_wv[tid] = g_wv[n * NN + tid];
    __syncthreads();
    float lmin = 1e30f, lmax = -1e30f;
    for (int k = tid; k < HW; k += 512) {
        double a = 0.0;
#pragma unroll
        for (int m = 0; m < NN; m++) {
            float pm = g_cm[(size_t)(n * NN + m) * HW + k] * s_wv[m];
            a += (double)pm;
        }
        float raw = (float)a;
        sc[k] = raw;
        lmin = fminf(lmin, raw); lmax = fmaxf(lmax, raw);
    }
    red[tid] = lmin; __syncthreads();
    for (int s = 256; s > 0; s >>= 1) { if (tid < s) red[tid] = fminf(red[tid], red[tid + s]); __syncthreads(); }
    float mn = red[0]; __syncthreads();
    red[tid] = lmax; __syncthreads();
    for (int s = 256; s > 0; s >>= 1) { if (tid < s) red[tid] = fmaxf(red[tid], red[tid + s]); __syncthreads(); }
    float mx = red[0]; __syncthreads();
    float den = (mx - mn) + 1e-12f;
    for (int k = tid; k < HW; k += 512) {
        float num = sc[k] - mn;
        g_CSA[n * HW + k] = num / den;
    }
}

// ---------------- 10: argsort ----------------
__global__ void k_sort() {
    __shared__ float key[2048];
    __shared__ int   idv[2048];
    int n = blockIdx.x, tid = threadIdx.x;
    for (int e = tid; e < 2048; e += 1024) {
        if (e < HW) { key[e] = g_CSA[n * HW + e]; idv[e] = e; }
        else        { key[e] = -1e30f;            idv[e] = e; }
    }
    __syncthreads();
    for (int k = 2; k <= 2048; k <<= 1) {
        for (int j = k >> 1; j > 0; j >>= 1) {
            for (int e = tid; e < 2048; e += 1024) {
                int ix = e ^ j;
                if (ix > e) {
                    float ka = key[e], kb = key[ix];
                    int ia = idv[e], ib = idv[ix];
                    bool up = ((e & k) == 0);
                    bool b_before_a = (kb > ka) || (kb == ka && ib < ia);
                    bool dosw = up ? b_before_a : !b_before_a;
                    if (dosw) { key[e] = kb; key[ix] = ka; idv[e] = ib; idv[ix] = ia; }
                }
            }
            __syncthreads();
        }
    }
    for (int e = tid; e < HW; e += 1024) g_idx[n * HW + e] = idv[e];
}

// ---------------- 11: gather + bf16 split ----------------
__global__ void k_gather_split() {
    int b = blockIdx.x;
    int n = b >> 9;
    for (int i = threadIdx.x; i < HW; i += 256) {
        float v = g_NF[(size_t)b * HW + g_idx[n * HW + i]];
        __nv_bfloat16 h = __float2bfloat16(v);
        __nv_bfloat16 l = __float2bfloat16(v - __bfloat162float(h));
        g_Ag_hi[(size_t)b * HW + i] = h;
        g_Ag_lo[(size_t)b * HW + i] = l;
    }
}

// ---------------- 12: weight concat + split ----------------
__global__ void k_wsplit(const float* __restrict__ w1, const float* __restrict__ ws) {
    int q = blockIdx.x * 256 + threadIdx.x;
    if (q >= MROWS * HW) return;
    int i = q % HW, r = q / HW;
    float f;
    if (r < OC * 9) {
        int o = r / 9, t = r % 9;
        f = w1[(o * HW + i) * 9 + t];
    } else {
        f = ws[(r - OC * 9) * HW + i];
    }
    __nv_bfloat16 h = __float2bfloat16(f);
    __nv_bfloat16 l = __float2bfloat16(f - __bfloat162float(h));
    g_Wc_hi[q] = h;
    g_Wc_lo[q] = l;
}
__global__ void k_w2split(const float* __restrict__ w2) {
    int q = blockIdx.x * 256 + threadIdx.x;
    if (q >= OC * K2) return;
    int k = q % K2, o = q / K2;
    int t = k / OC, c = k % OC;
    float f = w2[(o * OC + c) * 9 + t];
    __nv_bfloat16 h = __float2bfloat16(f);
    __nv_bfloat16 l = __float2bfloat16(f - __bfloat162float(h));
    g_W2k_hi[q] = h;
    g_W2k_lo[q] = l;
}

// ---------------- 13: fold GEMM, double-buffered ----------------
#define FBUF 10240                       // one 128xLDT bf16 buffer, bytes
#define FSTAGE (4 * FBUF)                // Ah Al Bh Bl

__global__ __launch_bounds__(256) void k_gemm_mma() {
    extern __shared__ __align__(16) char dsm[];
    uint32_t base = smem_u32(dsm);
    int n = blockIdx.z;
    int m0 = blockIdx.x * 128, n0 = blockIdx.y * 128;
    const __nv_bfloat16* Bh = g_Ag_hi + (size_t)n * CC * HW;
    const __nv_bfloat16* Bl = g_Ag_lo + (size_t)n * CC * HW;
    int tid = threadIdx.x, lane = tid & 31, wid = tid >> 5;
    int wm = wid & 3, wn = wid >> 2;

    float c[2][8][4];
#pragma unroll
    for (int i = 0; i < 2; i++)
#pragma unroll
        for (int j = 0; j < 8; j++)
#pragma unroll
            for (int q = 0; q < 4; q++) c[i][j][q] = 0.f;

    int lrow = tid >> 1, lk = (tid & 1) * 16;
    const __nv_bfloat16* pAh = g_Wc_hi + (size_t)(m0 + lrow) * HW + lk;
    const __nv_bfloat16* pAl = g_Wc_lo + (size_t)(m0 + lrow) * HW + lk;
    const __nv_bfloat16* pBh = Bh + (size_t)(n0 + lrow) * HW + lk;
    const __nv_bfloat16* pBl = Bl + (size_t)(n0 + lrow) * HW + lk;
    uint32_t so = (uint32_t)(lrow * LDT + lk) * 2;
    int arow = (lane & 15), akoff = 8 * (lane >> 4);
    int brow = (lane & 7),  bkoff = 8 * ((lane >> 3) & 1);

    uint4 r0, r1, r2, r3, r4, r5, r6, r7;
#define FLD(k0) do { \
    r0 = *(const uint4*)(pAh + (k0)); r1 = *(const uint4*)(pAh + (k0) + 8); \
    r2 = *(const uint4*)(pAl + (k0)); r3 = *(const uint4*)(pAl + (k0) + 8); \
    r4 = *(const uint4*)(pBh + (k0)); r5 = *(const uint4*)(pBh + (k0) + 8); \
    r6 = *(const uint4*)(pBl + (k0)); r7 = *(const uint4*)(pBl + (k0) + 8); } while (0)
#define FST(s) do { \
    char* sb_ = dsm + (s) * FSTAGE; \
    *(uint4*)(sb_ + so) = r0;            *(uint4*)(sb_ + so + 16) = r1; \
    *(uint4*)(sb_ + FBUF + so) = r2;     *(uint4*)(sb_ + FBUF + so + 16) = r3; \
    *(uint4*)(sb_ + 2*FBUF + so) = r4;   *(uint4*)(sb_ + 2*FBUF + so + 16) = r5; \
    *(uint4*)(sb_ + 3*FBUF + so) = r6;   *(uint4*)(sb_ + 3*FBUF + so + 16) = r7; } while (0)

    FLD(0);
    FST(0);
    __syncthreads();
    for (int kb = 0; kb < 50; kb++) {
        bool more = (kb + 1 < 50);
        if (more) FLD((kb + 1) * 32);
        uint32_t uAh = base + (kb & 1) * FSTAGE;
        uint32_t uAl = uAh + FBUF, uBh = uAh + 2 * FBUF, uBl = uAh + 3 * FBUF;
#pragma unroll
        for (int kk = 0; kk < 32; kk += 16) {
            uint32_t ah[2][4], al[2][4];
#pragma unroll
            for (int i = 0; i < 2; i++) {
                uint32_t ao = (uint32_t)((32 * wm + 16 * i + arow) * LDT + kk + akoff) * 2;
                ldsm_x4(ah[i][0], ah[i][1], ah[i][2], ah[i][3], uAh + ao);
                ldsm_x4(al[i][0], al[i][1], al[i][2], al[i][3], uAl + ao);
            }
#pragma unroll
            for (int j = 0; j < 8; j++) {
                uint32_t bo = (uint32_t)((64 * wn + 8 * j + brow) * LDT + kk + bkoff) * 2;
                uint32_t bh0, bh1, bl0, bl1;
                ldsm_x2(bh0, bh1, uBh + bo);
                ldsm_x2(bl0, bl1, uBl + bo);
#pragma unroll
                for (int i = 0; i < 2; i++) {
                    hmma(c[i][j], ah[i], bh0, bh1);
                    hmma(c[i][j], ah[i], bl0, bl1);
                    hmma(c[i][j], al[i], bh0, bh1);
                }
            }
        }
        if (more) FST((kb + 1) & 1);
        __syncthreads();
    }
#undef FLD
#undef FST
#pragma unroll
    for (int i = 0; i < 2; i++) {
        int rb = m0 + 32 * wm + 16 * i + (lane >> 2);
#pragma unroll
        for (int half = 0; half < 2; half++) {
            int r = rb + half * 8;
#pragma unroll
            for (int j = 0; j < 8; j++) {
                int col = n0 + 64 * wn + 8 * j + (lane & 3) * 2;
                float v0 = c[i][j][half * 2], v1 = c[i][j][half * 2 + 1];
                size_t off;
                __nv_bfloat16 *dh, *dl;
                if (r < OC * 9) {
                    int o = r / 9, t = r % 9;
                    off = ((size_t)n * OC + o) * K1 + t * CC + col;
                    dh = g_Wk1_hi; dl = g_Wk1_lo;
                } else {
                    int o = r - OC * 9;
                    off = ((size_t)n * OC + o) * CC + col;
                    dh = g_Wsc_hi; dl = g_Wsc_lo;
                }
                *(uint32_t*)(dh + off) = pack_hi2(v0, v1);
                *(uint32_t*)(dl + off) = pack_lo2(v0, v1);
            }
        }
    }
}

// ---------------- 14: Xt = (NF*CSA)^T split ----------------
__global__ void k_xt() {
    __shared__ float sT[32][33];
    int n = blockIdx.z;
    int p0 = blockIdx.x * 32, c0 = blockIdx.y * 32;
    int tid = threadIdx.x;
    int tc = tid >> 5, tp = tid & 31;
#pragma unroll
    for (int r = 0; r < 4; r++) {
        int c = c0 + tc + r * 8;
        sT[tc + r * 8][tp] = g_NF[((size_t)n * CC + c) * HW + p0 + tp] * g_CSA[n * HW + p0 + tp];
    }
    __syncthreads();
#pragma unroll
    for (int r = 0; r < 4; r++) {
        int p = p0 + tc + r * 8;
        float v = sT[tp][tc + r * 8];
        __nv_bfloat16 h = __float2bfloat16(v);
        __nv_bfloat16 l = __float2bfloat16(v - __bfloat162float(h));
        g_Xt_hi[((size_t)n * HW + p) * CC + c0 + tp] = h;
        g_Xt_lo[((size_t)n * HW + p) * CC + c0 + tp] = l;
    }
}

// ---------------- 15: conv via mma.sync bf16x3 (implicit GEMM, double-buffered) --
#define CABUF 10240
#define CBBUF 5120
#define CSTAGE (2 * CABUF + 2 * CBBUF)   // Ah Al Bh Bl

__global__ __launch_bounds__(256) void k_conv_mma(int mode, const float* __restrict__ bias,
                                                  const float* __restrict__ bsc,
                                                  float* __restrict__ dout) {
    extern __shared__ __align__(16) char dsm[];
    uint32_t base = smem_u32(dsm);
    int n = blockIdx.z;
    int p0 = blockIdx.x * 64;
    int tid = threadIdx.x, lane = tid & 31, wid = tid >> 5;
    int wm = wid & 3, wn = wid >> 2;

    const __nv_bfloat16 *Ah, *Al, *Bh, *Bl;
    int K, Cin, nslab;
    if (mode == 0) {
        Ah = g_Wk1_hi + (size_t)n * OC * K1; Al = g_Wk1_lo + (size_t)n * OC * K1;
        Bh = g_Xt_hi + (size_t)n * HW * CC;  Bl = g_Xt_lo + (size_t)n * HW * CC;
        K = K1; Cin = CC; nslab = K1 / 32;
    } else {
        Ah = g_W2k_hi; Al = g_W2k_lo;
        Bh = g_H1t_hi + (size_t)n * HW * OC; Bl = g_H1t_lo + (size_t)n * HW * OC;
        K = K2; Cin = OC; nslab = K2 / 32;
    }
    int slabs_per_tap = Cin / 32;

    int alrow = tid >> 1, alk = (tid & 1) * 16;
    int blrow = tid >> 2, blc = (tid & 3) * 8;
    int bp = p0 + blrow;
    int bpx = bp % IMG, bpy = bp / IMG;
    int arow = (lane & 15), akoff = 8 * (lane >> 4);
    int brow = (lane & 7),  bkoff = 8 * ((lane >> 3) & 1);
    uint32_t soA = (uint32_t)(alrow * LDT + alk) * 2;
    uint32_t soB = (uint32_t)(blrow * LDT + blc) * 2;

    float c[2][4][4];
#pragma unroll
    for (int i = 0; i < 2; i++)
#pragma unroll
        for (int j = 0; j < 4; j++)
#pragma unroll
            for (int q = 0; q < 4; q++) c[i][j][q] = 0.f;

    uint4 ra0, ra1, ra2, ra3, rb0, rb1;
#define CLD(kb) do { \
    int t_ = (kb) / slabs_per_tap, c0_ = ((kb) % slabs_per_tap) * 32; \
    int dy_ = t_ / 3 - 1, dx_ = t_ % 3 - 1, off_ = dy_ * IMG + dx_; \
    bool valid_ = ((unsigned)(bpx + dx_) < (unsigned)IMG) && ((unsigned)(bpy + dy_) < (unsigned)IMG); \
    size_t gA_ = (size_t)alrow * K + (kb) * 32 + alk; \
    ra0 = *(const uint4*)(Ah + gA_); ra1 = *(const uint4*)(Ah + gA_ + 8); \
    ra2 = *(const uint4*)(Al + gA_); ra3 = *(const uint4*)(Al + gA_ + 8); \
    rb0 = make_uint4(0, 0, 0, 0); rb1 = make_uint4(0, 0, 0, 0); \
    if (valid_) { \
        size_t gB_ = (size_t)(bp + off_) * Cin + c0_ + blc; \
        rb0 = *(const uint4*)(Bh + gB_); rb1 = *(const uint4*)(Bl + gB_); \
    } } while (0)
#define CST(s) do { \
    char* sb_ = dsm + (s) * CSTAGE; \
    *(uint4*)(sb_ + soA) = ra0;              *(uint4*)(sb_ + soA + 16) = ra1; \
    *(uint4*)(sb_ + CABUF + soA) = ra2;      *(uint4*)(sb_ + CABUF + soA + 16) = ra3; \
    *(uint4*)(sb_ + 2*CABUF + soB) = rb0;    *(uint4*)(sb_ + 2*CABUF + CBBUF + soB) = rb1; } while (0)
#define CCOMPUTE(s) do { \
    uint32_t uAh_ = base + (s) * CSTAGE; \
    uint32_t uAl_ = uAh_ + CABUF, uBh_ = uAh_ + 2*CABUF, uBl_ = uBh_ + CBBUF; \
    _Pragma("unroll") \
    for (int kk = 0; kk < 32; kk += 16) { \
        uint32_t ah[2][4], al[2][4]; \
        _Pragma("unroll") \
        for (int i = 0; i < 2; i++) { \
            uint32_t ao = (uint32_t)((32 * wm + 16 * i + arow) * LDT + kk + akoff) * 2; \
            ldsm_x4(ah[i][0], ah[i][1], ah[i][2], ah[i][3], uAh_ + ao); \
            ldsm_x4(al[i][0], al[i][1], al[i][2], al[i][3], uAl_ + ao); \
        } \
        _Pragma("unroll") \
        for (int j = 0; j < 4; j++) { \
            uint32_t bo = (uint32_t)((32 * wn + 8 * j + brow) * LDT + kk + bkoff) * 2; \
            uint32_t bh0, bh1, bl0, bl1; \
            ldsm_x2(bh0, bh1, uBh_ + bo); \
            ldsm_x2(bl0, bl1, uBl_ + bo); \
            _Pragma("unroll") \
            for (int i = 0; i < 2; i++) { \
                hmma(c[i][j], ah[i], bh0, bh1); \
                hmma(c[i][j], ah[i], bl0, bl1); \
                hmma(c[i][j], al[i], bh0, bh1); \
            } \
        } \
    } } while (0)

    CLD(0);
    CST(0);
    __syncthreads();
    for (int kb = 0; kb < nslab; kb++) {
        bool more = (kb + 1 < nslab);
        if (more) CLD(kb + 1);
        CCOMPUTE(kb & 1);
        if (more) CST((kb + 1) & 1);
        __syncthreads();
    }
    // epilogue phase 1
#pragma unroll
    for (int i = 0; i < 2; i++) {
        int rb = 32 * wm + 16 * i + (lane >> 2);
#pragma unroll
        for (int half = 0; half < 2; half++) {
            int o = rb + half * 8;
            float bo = bias[o];
#pragma unroll
            for (int j = 0; j < 4; j++) {
                int p = p0 + 32 * wn + 8 * j + (lane & 3) * 2;
                float v0 = c[i][j][half * 2] + bo, v1 = c[i][j][half * 2 + 1] + bo;
                if (mode == 0) {
                    // relu then bf16 split directly into H1t [p][o] (same values k_h1t produced)
                    float a = fmaxf(v0, 0.f), b2 = fmaxf(v1, 0.f);
                    __nv_bfloat16 ha = __float2bfloat16(a);
                    __nv_bfloat16 la = __float2bfloat16(a - __bfloat162float(ha));
                    __nv_bfloat16 hb = __float2bfloat16(b2);
                    __nv_bfloat16 lb = __float2bfloat16(b2 - __bfloat162float(hb));
                    size_t b0 = ((size_t)n * HW + p) * OC + o;
                    g_H1t_hi[b0] = ha; g_H1t_lo[b0] = la;
                    g_H1t_hi[b0 + OC] = hb; g_H1t_lo[b0 + OC] = lb;
                } else {
                    float2 sc = *(const float2*)&g_SC[((size_t)n * OC + o) * HW + p];
                    *(float2*)&dout[((size_t)n * OC + o) * HW + p] =
                        make_float2(fmaxf(v0 + sc.x, 0.f), fmaxf(v1 + sc.y, 0.f));
                }
            }
        }
    }
    if (mode != 0) return;

    // ---- phase 2: 1x1 shortcut (K=512), double-buffered ----
#pragma unroll
    for (int i = 0; i < 2; i++)
#pragma unroll
        for (int j = 0; j < 4; j++)
#pragma unroll
            for (int q = 0; q < 4; q++) c[i][j][q] = 0.f;
    const __nv_bfloat16* Sh = g_Wsc_hi + (size_t)n * OC * CC;
    const __nv_bfloat16* Sl = g_Wsc_lo + (size_t)n * OC * CC;
#define SLD(kb) do { \
    size_t gA_ = (size_t)alrow * CC + (kb) * 32 + alk; \
    ra0 = *(const uint4*)(Sh + gA_); ra1 = *(const uint4*)(Sh + gA_ + 8); \
    ra2 = *(const uint4*)(Sl + gA_); ra3 = *(const uint4*)(Sl + gA_ + 8); \
    size_t gB_ = (size_t)bp * CC + (kb) * 32 + blc; \
    rb0 = *(const uint4*)(Bh + gB_); rb1 = *(const uint4*)(Bl + gB_); } while (0)

    __syncthreads();   // ensure all warps done reading stage data from main loop
    SLD(0);
    CST(0);
    __syncthreads();
    for (int kb = 0; kb < CC / 32; kb++) {
        bool more = (kb + 1 < CC / 32);
        if (more) SLD(kb + 1);
        CCOMPUTE(kb & 1);
        if (more) CST((kb + 1) & 1);
        __syncthreads();
    }
#undef SLD
#undef CLD
#undef CST
#undef CCOMPUTE
#pragma unroll
    for (int i = 0; i < 2; i++) {
        int rb = 32 * wm + 16 * i + (lane >> 2);
#pragma unroll
        for (int half = 0; half < 2; half++) {
            int o = rb + half * 8;
            float bo = bsc[o];
#pragma unroll
            for (int j = 0; j < 4; j++) {
                int p = p0 + 32 * wn + 8 * j + (lane & 3) * 2;
                *(float2*)&g_SC[((size_t)n * OC + o) * HW + p] =
                    make_float2(c[i][j][half * 2] + bo, c[i][j][half * 2 + 1] + bo);
            }
        }
    }
}

// ---------------- launch ----------------
extern "C" void kernel_launch(void* const* d_in, const int* in_sizes, int n_in,
                              void* d_out, int out_size) {
    const float *feats = nullptr, *sisms = nullptr, *w1 = nullptr, *w2 = nullptr, *ws = nullptr;
    const float *b1 = nullptr, *b2 = nullptr, *bs = nullptr;
    for (int i = 0; i < n_in; i++) {
        int s = in_sizes[i];
        const float* p = (const float*)d_in[i];
        if (s == NN * CC * HW) feats = p;
        else if (s == NN * HW) sisms = p;
        else if (s == OC * HW * 9) w1 = p;
        else if (s == OC * OC * 9) w2 = p;
        else if (s == OC * HW) ws = p;
        else if (s == OC) { if (!b1) b1 = p; else if (!b2) b2 = p; else bs = p; }
    }
    float* out = (float*)d_out;

    static int attr_set = 0;
    if (!attr_set) {
        cudaFuncSetAttribute(k_gemm_mma, cudaFuncAttributeMaxDynamicSharedMemorySize, 2 * FSTAGE);
        cudaFuncSetAttribute(k_conv_mma, cudaFuncAttributeMaxDynamicSharedMemorySize, 2 * CSTAGE);
        attr_set = 1;
    }

    k_norm<<<dim3(25, NN), 256>>>(feats);
    k_siv_raw<<<NN * CC, 256>>>(sisms);
    k_siv_norm<<<NN, CC>>>();
    k_cm<<<dim3(25, NN), 256>>>();
    k_cm_norm<<<NN * NN, 256>>>();
    k_corr<<<NN * NN * NN, 256>>>();
    k_svsm<<<1, 128>>>();
    k_csa<<<NN, 512>>>();
    k_sort<<<NN, 1024>>>();
    k_gather_split<<<NN * CC, 256>>>();
    k_wsplit<<<(MROWS * HW + 255) / 256, 256>>>(w1, ws);
    k_w2split<<<(OC * K2 + 255) / 256, 256>>>(w2);
    k_gemm_mma<<<dim3(MROWS / 128, CC / 128, NN), 256, 2 * FSTAGE>>>();
    k_xt<<<dim3(50, CC / 32, NN), 256>>>();
    k_conv_mma<<<dim3(25, 1, NN), 256, 2 * CSTAGE>>>(0, b1, bs, nullptr);
    k_conv_mma<<<dim3(25, 1, NN), 256, 2 * CSTAGE>>>(1, b2, nullptr, out);
    (void)out_size; (void)n_in;
}

// round 11
// speedup vs baseline: 3.7559x; 1.0701x over previous
#include <cuda_runtime.h>
#include <cuda_bf16.h>
#include <math.h>
#include <stdint.h>

#define NN 10
#define CC 512
#define HW 1600
#define OC 128
#define IMG 40
#define MROWS 1280   // 1152 folded-conv1 rows + 128 shortcut rows
#define K1 4608      // conv1 K = 9*512
#define K2 1152      // conv2 K = 9*128
#define LDT 40

// ---------------- scratch (device globals) ----------------
__device__ float g_NF[NN*CC*HW];
__device__ float g_SIVraw[NN*CC];
__device__ float g_SIV[NN*CC];
__device__ float g_cm[NN*NN*HW];
__device__ float g_corr[NN*NN*NN];
__device__ float g_sv[NN*NN];
__device__ float g_wv[NN*NN];
__device__ float g_CSA[NN*HW];
__device__ int   g_idx[NN*HW];
__device__ __align__(16) __nv_bfloat16 g_Wc_hi[MROWS*HW];
__device__ __align__(16) __nv_bfloat16 g_Wc_lo[MROWS*HW];
__device__ __align__(16) __nv_bfloat16 g_Ag_hi[NN*CC*HW];
__device__ __align__(16) __nv_bfloat16 g_Ag_lo[NN*CC*HW];
__device__ __align__(16) __nv_bfloat16 g_Wk1_hi[NN*OC*K1];
__device__ __align__(16) __nv_bfloat16 g_Wk1_lo[NN*OC*K1];
__device__ __align__(16) __nv_bfloat16 g_Wsc_hi[NN*OC*CC];
__device__ __align__(16) __nv_bfloat16 g_Wsc_lo[NN*OC*CC];
__device__ __align__(16) __nv_bfloat16 g_W2k_hi[OC*K2];
__device__ __align__(16) __nv_bfloat16 g_W2k_lo[OC*K2];
__device__ __align__(16) __nv_bfloat16 g_Xt_hi[NN*HW*CC];
__device__ __align__(16) __nv_bfloat16 g_Xt_lo[NN*HW*CC];
__device__ __align__(16) __nv_bfloat16 g_H1t_hi[NN*HW*OC];
__device__ __align__(16) __nv_bfloat16 g_H1t_lo[NN*HW*OC];
__device__ float g_SC[NN*OC*HW];

// ---------------- helpers ----------------
__device__ __forceinline__ double blockReduceSumD(double v) {
    __shared__ double sh[32];
    int lane = threadIdx.x & 31, wid = threadIdx.x >> 5;
#pragma unroll
    for (int o = 16; o > 0; o >>= 1) v += __shfl_down_sync(0xffffffffu, v, o);
    if (lane == 0) sh[wid] = v;
    __syncthreads();
    if (wid == 0) {
        int nw = blockDim.x >> 5;
        v = (lane < nw) ? sh[lane] : 0.0;
#pragma unroll
        for (int o = 16; o > 0; o >>= 1) v += __shfl_down_sync(0xffffffffu, v, o);
    }
    return v;
}
__device__ __forceinline__ void kadd(float& s, float& c, float p) {
    float y = __fsub_rn(p, c);
    float t = __fadd_rn(s, y);
    c = __fsub_rn(__fsub_rn(t, s), y);
    s = t;
}
__device__ __forceinline__ uint32_t smem_u32(const void* p) {
    uint32_t a;
    asm("{ .reg .u64 t; cvta.to.shared.u64 t, %1; cvt.u32.u64 %0, t; }" : "=r"(a) : "l"(p));
    return a;
}
__device__ __forceinline__ void ldsm_x4(uint32_t& r0, uint32_t& r1, uint32_t& r2, uint32_t& r3, uint32_t a) {
    asm volatile("ldmatrix.sync.aligned.m8n8.x4.shared.b16 {%0,%1,%2,%3}, [%4];"
                 : "=r"(r0), "=r"(r1), "=r"(r2), "=r"(r3) : "r"(a));
}
__device__ __forceinline__ void ldsm_x2(uint32_t& r0, uint32_t& r1, uint32_t a) {
    asm volatile("ldmatrix.sync.aligned.m8n8.x2.shared.b16 {%0,%1}, [%2];"
                 : "=r"(r0), "=r"(r1) : "r"(a));
}
__device__ __forceinline__ void hmma(float* c, const uint32_t* a, uint32_t b0, uint32_t b1) {
    asm volatile("mma.sync.aligned.m16n8k16.row.col.f32.bf16.bf16.f32 "
                 "{%0,%1,%2,%3},{%4,%5,%6,%7},{%8,%9},{%0,%1,%2,%3};"
                 : "+f"(c[0]), "+f"(c[1]), "+f"(c[2]), "+f"(c[3])
                 : "r"(a[0]), "r"(a[1]), "r"(a[2]), "r"(a[3]), "r"(b0), "r"(b1));
}
__device__ __forceinline__ uint32_t pack_hi2(float a, float b) {
    __nv_bfloat16 ha = __float2bfloat16(a), hb = __float2bfloat16(b);
    return (uint32_t)__bfloat16_as_ushort(ha) | ((uint32_t)__bfloat16_as_ushort(hb) << 16);
}
__device__ __forceinline__ uint32_t pack_lo2(float a, float b) {
    __nv_bfloat16 ha = __float2bfloat16(a), hb = __float2bfloat16(b);
    __nv_bfloat16 la = __float2bfloat16(a - __bfloat162float(ha));
    __nv_bfloat16 lb = __float2bfloat16(b - __bfloat162float(hb));
    return (uint32_t)__bfloat16_as_ushort(la) | ((uint32_t)__bfloat16_as_ushort(lb) << 16);
}

// ---------------- 1: per-pixel L2 norm (8 c-groups x 32 hw) ----------------
__global__ void k_norm(const float* __restrict__ feats) {
    int n = blockIdx.y;
    int tid = threadIdx.x;
    int cg = tid >> 5, kk = tid & 31;
    int hw = blockIdx.x * 32 + kk;
    const float* f = feats + (size_t)n * CC * HW + hw;
    float s = 0.f, comp = 0.f;
    for (int c = cg * 64; c < cg * 64 + 64; c++) {
        float v = f[(size_t)c * HW];
        kadd(s, comp, __fmul_rn(v, v));
    }
    __shared__ double sh[8][32];
    __shared__ float sd[32];
    sh[cg][kk] = (double)s + (double)comp;
    __syncthreads();
    if (tid < 32) {
        double S = 0.0;
#pragma unroll
        for (int g = 0; g < 8; g++) S += sh[g][tid];
        sd[tid] = fmaxf(sqrtf((float)S), 1e-12f);
    }
    __syncthreads();
    float d = sd[kk];
    float* o = g_NF + (size_t)n * CC * HW + hw;
    for (int c = cg * 64; c < cg * 64 + 64; c++)
        o[(size_t)c * HW] = f[(size_t)c * HW] / d;
}

// ---------------- 2: SIV raw ----------------
__global__ void k_siv_raw(const float* __restrict__ sisms) {
    int b = blockIdx.x;
    int n = b >> 9;
    double s = 0.0;
    for (int k = threadIdx.x; k < HW; k += 256) {
        float pm = g_NF[(size_t)b * HW + k] * sisms[n * HW + k];
        s += (double)pm;
    }
    s = blockReduceSumD(s);
    if (threadIdx.x == 0) g_SIVraw[b] = ((float)s) / 1600.0f;
}

// ---------------- 3: SIV l2 norm ----------------
__global__ void k_siv_norm() {
    int n = blockIdx.x, t = threadIdx.x;
    float v = g_SIVraw[n * CC + t];
    float sq = v * v;
    double s = blockReduceSumD((double)sq);
    __shared__ float s_d;
    if (t == 0) s_d = fmaxf(sqrtf((float)s), 1e-12f);
    __syncthreads();
    g_SIV[n * CC + t] = v / s_d;
}

// ---------------- 4: cm (8 c-groups x 32 k) ----------------
__global__ void k_cm() {
    __shared__ float s_siv[NN * CC];
    __shared__ double sh[8][32][NN];
    int n = blockIdx.y;
    int tid = threadIdx.x;
    for (int q = tid; q < NN * CC; q += 256) s_siv[q] = g_SIV[q];
    int cg = tid >> 5, kk = tid & 31;
    int k = blockIdx.x * 32 + kk;
    const float* nfp = g_NF + (size_t)n * CC * HW + k;
    __syncthreads();
    float s[NN], comp[NN];
#pragma unroll
    for (int m = 0; m < NN; m++) { s[m] = 0.f; comp[m] = 0.f; }
    for (int c = cg * 64; c < cg * 64 + 64; c++) {
        float nf = nfp[(size_t)c * HW];
#pragma unroll
        for (int m = 0; m < NN; m++) kadd(s[m], comp[m], __fmul_rn(nf, s_siv[m * CC + c]));
    }
#pragma unroll
    for (int m = 0; m < NN; m++) sh[cg][kk][m] = (double)s[m] + (double)comp[m];
    __syncthreads();
    for (int e = tid; e < 32 * NN; e += 256) {
        int kk2 = e / NN, m = e % NN;
        double v = 0.0;
#pragma unroll
        for (int g = 0; g < 8; g++) v += sh[g][kk2][m];
        g_cm[(size_t)(n * NN + m) * HW + blockIdx.x * 32 + kk2] = (float)v;
    }
}

// ---------------- 5: cm row norm ----------------
__global__ void k_cm_norm() {
    int row = blockIdx.x;
    size_t base = (size_t)row * HW;
    double ss = 0.0;
    for (int k = threadIdx.x; k < HW; k += 256) {
        float v = g_cm[base + k];
        float sq = v * v;
        ss += (double)sq;
    }
    ss = blockReduceSumD(ss);
    __shared__ float s_d;
    if (threadIdx.x == 0) s_d = fmaxf(sqrtf((float)ss), 1e-12f);
    __syncthreads();
    for (int k = threadIdx.x; k < HW; k += 256) g_cm[base + k] = g_cm[base + k] / s_d;
}

// ---------------- 6: corr ----------------
__global__ void k_corr() {
    int b = blockIdx.x;
    int p = b % NN;
    int m = (b / NN) % NN;
    int n = b / (NN * NN);
    double s = 0.0;
    for (int k = threadIdx.x; k < HW; k += 256)
        s += (double)g_cm[(size_t)(n * NN + m) * HW + k] * (double)g_cm[(size_t)(n * NN + p) * HW + k];
    s = blockReduceSumD(s);
    if (threadIdx.x == 0) g_corr[b] = (float)s;
}

// ---------------- 7+8: sv + softmax fused ----------------
__global__ void k_svsm() {
    int t = threadIdx.x;
    if (t < NN * NN) {
        double s = 0.0;
#pragma unroll
        for (int p = 0; p < NN; p++) s += (double)g_corr[t * NN + p];
        g_sv[t] = (float)s;
    }
    __syncthreads();
    int n = t;
    if (n >= NN) return;
    float mx = -1e30f;
    for (int m = 0; m < NN; m++) mx = fmaxf(mx, g_sv[n * NN + m]);
    float e[NN];
    double sum = 0.0;
    for (int m = 0; m < NN; m++) {
        float tt = g_sv[n * NN + m] - mx;
        e[m] = (float)exp((double)tt);
        sum += (double)e[m];
    }
    float S = (float)sum;
    for (int m = 0; m < NN; m++) g_wv[n * NN + m] = e[m] / S;
}

// ---------------- 9: CSA ----------------
__global__ void k_csa() {
    int n = blockIdx.x, tid = threadIdx.x;
    __shared__ float s_wv[NN];
    __shared__ float sc[HW];
    __shared__ float red[512];
    if (tid < NN) s_wv[tid] = g_wv[n * NN + tid];
    __syncthreads();
    float lmin = 1e30f, lmax = -1e30f;
    for (int k = tid; k < HW; k += 512) {
        double a = 0.0;
#pragma unroll
        for (int m = 0; m < NN; m++) {
            float pm = g_cm[(size_t)(n * NN + m) * HW + k] * s_wv[m];
            a += (double)pm;
        }
        float raw = (float)a;
        sc[k] = raw;
        lmin = fminf(lmin, raw); lmax = fmaxf(lmax, raw);
    }
    red[tid] = lmin; __syncthreads();
    for (int s = 256; s > 0; s >>= 1) { if (tid < s) red[tid] = fminf(red[tid], red[tid + s]); __syncthreads(); }
    float mn = red[0]; __syncthreads();
    red[tid] = lmax; __syncthreads();
    for (int s = 256; s > 0; s >>= 1) { if (tid < s) red[tid] = fmaxf(red[tid], red[tid + s]); __syncthreads(); }
    float mx = red[0]; __syncthreads();
    float den = (mx - mn) + 1e-12f;
    for (int k = tid; k < HW; k += 512) {
        float num = sc[k] - mn;
        g_CSA[n * HW + k] = num / den;
    }
}

// ---------------- 10: argsort ----------------
__global__ void k_sort() {
    __shared__ float key[2048];
    __shared__ int   idv[2048];
    int n = blockIdx.x, tid = threadIdx.x;
    for (int e = tid; e < 2048; e += 1024) {
        if (e < HW) { key[e] = g_CSA[n * HW + e]; idv[e] = e; }
        else        { key[e] = -1e30f;            idv[e] = e; }
    }
    __syncthreads();
    for (int k = 2; k <= 2048; k <<= 1) {
        for (int j = k >> 1; j > 0; j >>= 1) {
            for (int e = tid; e < 2048; e += 1024) {
                int ix = e ^ j;
                if (ix > e) {
                    float ka = key[e], kb = key[ix];
                    int ia = idv[e], ib = idv[ix];
                    bool up = ((e & k) == 0);
                    bool b_before_a = (kb > ka) || (kb == ka && ib < ia);
                    bool dosw = up ? b_before_a : !b_before_a;
                    if (dosw) { key[e] = kb; key[ix] = ka; idv[e] = ib; idv[ix] = ia; }
                }
            }
            __syncthreads();
        }
    }
    for (int e = tid; e < HW; e += 1024) g_idx[n * HW + e] = idv[e];
}

// ---------------- 11: gather + bf16 split ----------------
__global__ void k_gather_split() {
    int b = blockIdx.x;
    int n = b >> 9;
    for (int i = threadIdx.x; i < HW; i += 256) {
        float v = g_NF[(size_t)b * HW + g_idx[n * HW + i]];
        __nv_bfloat16 h = __float2bfloat16(v);
        __nv_bfloat16 l = __float2bfloat16(v - __bfloat162float(h));
        g_Ag_hi[(size_t)b * HW + i] = h;
        g_Ag_lo[(size_t)b * HW + i] = l;
    }
}

// ---------------- 12: weight concat + split ----------------
__global__ void k_wsplit(const float* __restrict__ w1, const float* __restrict__ ws) {
    int q = blockIdx.x * 256 + threadIdx.x;
    if (q >= MROWS * HW) return;
    int i = q % HW, r = q / HW;
    float f;
    if (r < OC * 9) {
        int o = r / 9, t = r % 9;
        f = w1[(o * HW + i) * 9 + t];
    } else {
        f = ws[(r - OC * 9) * HW + i];
    }
    __nv_bfloat16 h = __float2bfloat16(f);
    __nv_bfloat16 l = __float2bfloat16(f - __bfloat162float(h));
    g_Wc_hi[q] = h;
    g_Wc_lo[q] = l;
}
__global__ void k_w2split(const float* __restrict__ w2) {
    int q = blockIdx.x * 256 + threadIdx.x;
    if (q >= OC * K2) return;
    int k = q % K2, o = q / K2;
    int t = k / OC, c = k % OC;
    float f = w2[(o * OC + c) * 9 + t];
    __nv_bfloat16 h = __float2bfloat16(f);
    __nv_bfloat16 l = __float2bfloat16(f - __bfloat162float(h));
    g_W2k_hi[q] = h;
    g_W2k_lo[q] = l;
}

// ---------------- 13: fold GEMM, double-buffered ----------------
#define FBUF 10240
#define FSTAGE (4 * FBUF)

__global__ __launch_bounds__(256) void k_gemm_mma() {
    extern __shared__ __align__(16) char dsm[];
    uint32_t base = smem_u32(dsm);
    int n = blockIdx.z;
    int m0 = blockIdx.x * 128, n0 = blockIdx.y * 128;
    const __nv_bfloat16* Bh = g_Ag_hi + (size_t)n * CC * HW;
    const __nv_bfloat16* Bl = g_Ag_lo + (size_t)n * CC * HW;
    int tid = threadIdx.x, lane = tid & 31, wid = tid >> 5;
    int wm = wid & 3, wn = wid >> 2;

    float c[2][8][4];
#pragma unroll
    for (int i = 0; i < 2; i++)
#pragma unroll
        for (int j = 0; j < 8; j++)
#pragma unroll
            for (int q = 0; q < 4; q++) c[i][j][q] = 0.f;

    int lrow = tid >> 1, lk = (tid & 1) * 16;
    const __nv_bfloat16* pAh = g_Wc_hi + (size_t)(m0 + lrow) * HW + lk;
    const __nv_bfloat16* pAl = g_Wc_lo + (size_t)(m0 + lrow) * HW + lk;
    const __nv_bfloat16* pBh = Bh + (size_t)(n0 + lrow) * HW + lk;
    const __nv_bfloat16* pBl = Bl + (size_t)(n0 + lrow) * HW + lk;
    uint32_t so = (uint32_t)(lrow * LDT + lk) * 2;
    int arow = (lane & 15), akoff = 8 * (lane >> 4);
    int brow = (lane & 7),  bkoff = 8 * ((lane >> 3) & 1);

    uint4 r0, r1, r2, r3, r4, r5, r6, r7;
#define FLD(k0) do { \
    r0 = *(const uint4*)(pAh + (k0)); r1 = *(const uint4*)(pAh + (k0) + 8); \
    r2 = *(const uint4*)(pAl + (k0)); r3 = *(const uint4*)(pAl + (k0) + 8); \
    r4 = *(const uint4*)(pBh + (k0)); r5 = *(const uint4*)(pBh + (k0) + 8); \
    r6 = *(const uint4*)(pBl + (k0)); r7 = *(const uint4*)(pBl + (k0) + 8); } while (0)
#define FST(s) do { \
    char* sb_ = dsm + (s) * FSTAGE; \
    *(uint4*)(sb_ + so) = r0;            *(uint4*)(sb_ + so + 16) = r1; \
    *(uint4*)(sb_ + FBUF + so) = r2;     *(uint4*)(sb_ + FBUF + so + 16) = r3; \
    *(uint4*)(sb_ + 2*FBUF + so) = r4;   *(uint4*)(sb_ + 2*FBUF + so + 16) = r5; \
    *(uint4*)(sb_ + 3*FBUF + so) = r6;   *(uint4*)(sb_ + 3*FBUF + so + 16) = r7; } while (0)

    FLD(0);
    FST(0);
    __syncthreads();
    for (int kb = 0; kb < 50; kb++) {
        bool more = (kb + 1 < 50);
        if (more) FLD((kb + 1) * 32);
        uint32_t uAh = base + (kb & 1) * FSTAGE;
        uint32_t uAl = uAh + FBUF, uBh = uAh + 2 * FBUF, uBl = uAh + 3 * FBUF;
#pragma unroll
        for (int kk = 0; kk < 32; kk += 16) {
            uint32_t ah[2][4], al[2][4];
#pragma unroll
            for (int i = 0; i < 2; i++) {
                uint32_t ao = (uint32_t)((32 * wm + 16 * i + arow) * LDT + kk + akoff) * 2;
                ldsm_x4(ah[i][0], ah[i][1], ah[i][2], ah[i][3], uAh + ao);
                ldsm_x4(al[i][0], al[i][1], al[i][2], al[i][3], uAl + ao);
            }
#pragma unroll
            for (int j = 0; j < 8; j++) {
                uint32_t bo = (uint32_t)((64 * wn + 8 * j + brow) * LDT + kk + bkoff) * 2;
                uint32_t bh0, bh1, bl0, bl1;
                ldsm_x2(bh0, bh1, uBh + bo);
                ldsm_x2(bl0, bl1, uBl + bo);
#pragma unroll
                for (int i = 0; i < 2; i++) {
                    hmma(c[i][j], ah[i], bh0, bh1);
                    hmma(c[i][j], ah[i], bl0, bl1);
                    hmma(c[i][j], al[i], bh0, bh1);
                }
            }
        }
        if (more) FST((kb + 1) & 1);
        __syncthreads();
    }
#undef FLD
#undef FST
#pragma unroll
    for (int i = 0; i < 2; i++) {
        int rb = m0 + 32 * wm + 16 * i + (lane >> 2);
#pragma unroll
        for (int half = 0; half < 2; half++) {
            int r = rb + half * 8;
#pragma unroll
            for (int j = 0; j < 8; j++) {
                int col = n0 + 64 * wn + 8 * j + (lane & 3) * 2;
                float v0 = c[i][j][half * 2], v1 = c[i][j][half * 2 + 1];
                size_t off;
                __nv_bfloat16 *dh, *dl;
                if (r < OC * 9) {
                    int o = r / 9, t = r % 9;
                    off = ((size_t)n * OC + o) * K1 + t * CC + col;
                    dh = g_Wk1_hi; dl = g_Wk1_lo;
                } else {
                    int o = r - OC * 9;
                    off = ((size_t)n * OC + o) * CC + col;
                    dh = g_Wsc_hi; dl = g_Wsc_lo;
                }
                *(uint32_t*)(dh + off) = pack_hi2(v0, v1);
                *(uint32_t*)(dl + off) = pack_lo2(v0, v1);
            }
        }
    }
}

// ---------------- 14: Xt = (NF*CSA)^T split ----------------
__global__ void k_xt() {
    __shared__ float sT[32][33];
    int n = blockIdx.z;
    int p0 = blockIdx.x * 32, c0 = blockIdx.y * 32;
    int tid = threadIdx.x;
    int tc = tid >> 5, tp = tid & 31;
#pragma unroll
    for (int r = 0; r < 4; r++) {
        int c = c0 + tc + r * 8;
        sT[tc + r * 8][tp] = g_NF[((size_t)n * CC + c) * HW + p0 + tp] * g_CSA[n * HW + p0 + tp];
    }
    __syncthreads();
#pragma unroll
    for (int r = 0; r < 4; r++) {
        int p = p0 + tc + r * 8;
        float v = sT[tp][tc + r * 8];
        __nv_bfloat16 h = __float2bfloat16(v);
        __nv_bfloat16 l = __float2bfloat16(v - __bfloat162float(h));
        g_Xt_hi[((size_t)n * HW + p) * CC + c0 + tp] = h;
        g_Xt_lo[((size_t)n * HW + p) * CC + c0 + tp] = l;
    }
}

// ---------------- 15: conv via mma.sync bf16x3 (128 outs x 128 pixels) ----------
#define CBUF 10240
#define CSTG (4 * CBUF)   // Ah Al Bh Bl

__global__ __launch_bounds__(256) void k_conv_mma(int mode, const float* __restrict__ bias,
                                                  const float* __restrict__ bsc,
                                                  float* __restrict__ dout) {
    extern __shared__ __align__(16) char dsm[];
    uint32_t base = smem_u32(dsm);
    int n = blockIdx.z;
    int p0 = blockIdx.x * 128;
    int tid = threadIdx.x, lane = tid & 31, wid = tid >> 5;
    int wm = wid & 3, wn = wid >> 2;       // warp tile 32 o x 64 p

    const __nv_bfloat16 *Ah, *Al, *Bh, *Bl;
    int K, Cin, nslab;
    if (mode == 0) {
        Ah = g_Wk1_hi + (size_t)n * OC * K1; Al = g_Wk1_lo + (size_t)n * OC * K1;
        Bh = g_Xt_hi + (size_t)n * HW * CC;  Bl = g_Xt_lo + (size_t)n * HW * CC;
        K = K1; Cin = CC; nslab = K1 / 32;
    } else {
        Ah = g_W2k_hi; Al = g_W2k_lo;
        Bh = g_H1t_hi + (size_t)n * HW * OC; Bl = g_H1t_lo + (size_t)n * HW * OC;
        K = K2; Cin = OC; nslab = K2 / 32;
    }
    int slabs_per_tap = Cin / 32;

    int lrow = tid >> 1, lk = (tid & 1) * 16;     // both A and B loaders: 128 rows x 16k
    int bp = p0 + lrow;
    bool prow = (bp < HW);
    int bpx = bp % IMG, bpy = bp / IMG;
    int arow = (lane & 15), akoff = 8 * (lane >> 4);
    int brow = (lane & 7),  bkoff = 8 * ((lane >> 3) & 1);
    uint32_t so = (uint32_t)(lrow * LDT + lk) * 2;

    float c[2][8][4];
#pragma unroll
    for (int i = 0; i < 2; i++)
#pragma unroll
        for (int j = 0; j < 8; j++)
#pragma unroll
            for (int q = 0; q < 4; q++) c[i][j][q] = 0.f;

    uint4 ra0, ra1, ra2, ra3, rb0, rb1, rb2, rb3;
#define CLD(kb) do { \
    int t_ = (kb) / slabs_per_tap, c0_ = ((kb) % slabs_per_tap) * 32; \
    int dy_ = t_ / 3 - 1, dx_ = t_ % 3 - 1, off_ = dy_ * IMG + dx_; \
    bool valid_ = prow && ((unsigned)(bpx + dx_) < (unsigned)IMG) && ((unsigned)(bpy + dy_) < (unsigned)IMG); \
    size_t gA_ = (size_t)lrow * K + (kb) * 32 + lk; \
    ra0 = *(const uint4*)(Ah + gA_); ra1 = *(const uint4*)(Ah + gA_ + 8); \
    ra2 = *(const uint4*)(Al + gA_); ra3 = *(const uint4*)(Al + gA_ + 8); \
    rb0 = make_uint4(0,0,0,0); rb1 = rb0; rb2 = rb0; rb3 = rb0; \
    if (valid_) { \
        size_t gB_ = (size_t)(bp + off_) * Cin + c0_ + lk; \
        rb0 = *(const uint4*)(Bh + gB_); rb1 = *(const uint4*)(Bh + gB_ + 8); \
        rb2 = *(const uint4*)(Bl + gB_); rb3 = *(const uint4*)(Bl + gB_ + 8); \
    } } while (0)
#define CST(s) do { \
    char* sb_ = dsm + (s) * CSTG; \
    *(uint4*)(sb_ + so) = ra0;            *(uint4*)(sb_ + so + 16) = ra1; \
    *(uint4*)(sb_ + CBUF + so) = ra2;     *(uint4*)(sb_ + CBUF + so + 16) = ra3; \
    *(uint4*)(sb_ + 2*CBUF + so) = rb0;   *(uint4*)(sb_ + 2*CBUF + so + 16) = rb1; \
    *(uint4*)(sb_ + 3*CBUF + so) = rb2;   *(uint4*)(sb_ + 3*CBUF + so + 16) = rb3; } while (0)
#define CCOMPUTE(s) do { \
    uint32_t uAh_ = base + (s) * CSTG; \
    uint32_t uAl_ = uAh_ + CBUF, uBh_ = uAh_ + 2*CBUF, uBl_ = uAh_ + 3*CBUF; \
    _Pragma("unroll") \
    for (int kk = 0; kk < 32; kk += 16) { \
        uint32_t ah[2][4], al[2][4]; \
        _Pragma("unroll") \
        for (int i = 0; i < 2; i++) { \
            uint32_t ao = (uint32_t)((32 * wm + 16 * i + arow) * LDT + kk + akoff) * 2; \
            ldsm_x4(ah[i][0], ah[i][1], ah[i][2], ah[i][3], uAh_ + ao); \
            ldsm_x4(al[i][0], al[i][1], al[i][2], al[i][3], uAl_ + ao); \
        } \
        _Pragma("unroll") \
        for (int j = 0; j < 8; j++) { \
            uint32_t bo = (uint32_t)((64 * wn + 8 * j + brow) * LDT + kk + bkoff) * 2; \
            uint32_t bh0, bh1, bl0, bl1; \
            ldsm_x2(bh0, bh1, uBh_ + bo); \
            ldsm_x2(bl0, bl1, uBl_ + bo); \
            _Pragma("unroll") \
            for (int i = 0; i < 2; i++) { \
                hmma(c[i][j], ah[i], bh0, bh1); \
                hmma(c[i][j], ah[i], bl0, bl1); \
                hmma(c[i][j], al[i], bh0, bh1); \
            } \
        } \
    } } while (0)

    CLD(0);
    CST(0);
    __syncthreads();
    for (int kb = 0; kb < nslab; kb++) {
        bool more = (kb + 1 < nslab);
        if (more) CLD(kb + 1);
        CCOMPUTE(kb & 1);
        if (more) CST((kb + 1) & 1);
        __syncthreads();
    }
    // epilogue phase 1
#pragma unroll
    for (int i = 0; i < 2; i++) {
        int rb = 32 * wm + 16 * i + (lane >> 2);
#pragma unroll
        for (int half = 0; half < 2; half++) {
            int o = rb + half * 8;
            float bo = bias[o];
#pragma unroll
            for (int j = 0; j < 8; j++) {
                int p = p0 + 64 * wn + 8 * j + (lane & 3) * 2;
                if (p >= HW) continue;
                float v0 = c[i][j][half * 2] + bo, v1 = c[i][j][half * 2 + 1] + bo;
                if (mode == 0) {
                    float a = fmaxf(v0, 0.f), b2 = fmaxf(v1, 0.f);
                    __nv_bfloat16 ha = __float2bfloat16(a);
                    __nv_bfloat16 la = __float2bfloat16(a - __bfloat162float(ha));
                    __nv_bfloat16 hb = __float2bfloat16(b2);
                    __nv_bfloat16 lb = __float2bfloat16(b2 - __bfloat162float(hb));
                    size_t b0 = ((size_t)n * HW + p) * OC + o;
                    g_H1t_hi[b0] = ha; g_H1t_lo[b0] = la;
                    g_H1t_hi[b0 + OC] = hb; g_H1t_lo[b0 + OC] = lb;
                } else {
                    float2 sc = *(const float2*)&g_SC[((size_t)n * OC + o) * HW + p];
                    *(float2*)&dout[((size_t)n * OC + o) * HW + p] =
                        make_float2(fmaxf(v0 + sc.x, 0.f), fmaxf(v1 + sc.y, 0.f));
                }
            }
        }
    }
    if (mode != 0) return;

    // ---- phase 2: 1x1 shortcut (K=512) ----
#pragma unroll
    for (int i = 0; i < 2; i++)
#pragma unroll
        for (int j = 0; j < 8; j++)
#pragma unroll
            for (int q = 0; q < 4; q++) c[i][j][q] = 0.f;
    const __nv_bfloat16* Sh = g_Wsc_hi + (size_t)n * OC * CC;
    const __nv_bfloat16* Sl = g_Wsc_lo + (size_t)n * OC * CC;
#define SLD(kb) do { \
    size_t gA_ = (size_t)lrow * CC + (kb) * 32 + lk; \
    ra0 = *(const uint4*)(Sh + gA_); ra1 = *(const uint4*)(Sh + gA_ + 8); \
    ra2 = *(const uint4*)(Sl + gA_); ra3 = *(const uint4*)(Sl + gA_ + 8); \
    rb0 = make_uint4(0,0,0,0); rb1 = rb0; rb2 = rb0; rb3 = rb0; \
    if (prow) { \
        size_t gB_ = (size_t)bp * CC + (kb) * 32 + lk; \
        rb0 = *(const uint4*)(Bh + gB_); rb1 = *(const uint4*)(Bh + gB_ + 8); \
        rb2 = *(const uint4*)(Bl + gB_); rb3 = *(const uint4*)(Bl + gB_ + 8); \
    } } while (0)

    __syncthreads();
    SLD(0);
    CST(0);
    __syncthreads();
    for (int kb = 0; kb < CC / 32; kb++) {
        bool more = (kb + 1 < CC / 32);
        if (more) SLD(kb + 1);
        CCOMPUTE(kb & 1);
        if (more) CST((kb + 1) & 1);
        __syncthreads();
    }
#undef SLD
#undef CLD
#undef CST
#undef CCOMPUTE
#pragma unroll
    for (int i = 0; i < 2; i++) {
        int rb = 32 * wm + 16 * i + (lane >> 2);
#pragma unroll
        for (int half = 0; half < 2; half++) {
            int o = rb + half * 8;
            float bo = bsc[o];
#pragma unroll
            for (int j = 0; j < 8; j++) {
                int p = p0 + 64 * wn + 8 * j + (lane & 3) * 2;
                if (p >= HW) continue;
                *(float2*)&g_SC[((size_t)n * OC + o) * HW + p] =
                    make_float2(c[i][j][half * 2] + bo, c[i][j][half * 2 + 1] + bo);
            }
        }
    }
}

// ---------------- launch ----------------
extern "C" void kernel_launch(void* const* d_in, const int* in_sizes, int n_in,
                              void* d_out, int out_size) {
    const float *feats = nullptr, *sisms = nullptr, *w1 = nullptr, *w2 = nullptr, *ws = nullptr;
    const float *b1 = nullptr, *b2 = nullptr, *bs = nullptr;
    for (int i = 0; i < n_in; i++) {
        int s = in_sizes[i];
        const float* p = (const float*)d_in[i];
        if (s == NN * CC * HW) feats = p;
        else if (s == NN * HW) sisms = p;
        else if (s == OC * HW * 9) w1 = p;
        else if (s == OC * OC * 9) w2 = p;
        else if (s == OC * HW) ws = p;
        else if (s == OC) { if (!b1) b1 = p; else if (!b2) b2 = p; else bs = p; }
    }
    float* out = (float*)d_out;

    static int attr_set = 0;
    if (!attr_set) {
        cudaFuncSetAttribute(k_gemm_mma, cudaFuncAttributeMaxDynamicSharedMemorySize, 2 * FSTAGE);
        cudaFuncSetAttribute(k_conv_mma, cudaFuncAttributeMaxDynamicSharedMemorySize, 2 * CSTG);
        attr_set = 1;
    }

    k_norm<<<dim3(50, NN), 256>>>(feats);
    k_siv_raw<<<NN * CC, 256>>>(sisms);
    k_siv_norm<<<NN, CC>>>();
    k_cm<<<dim3(50, NN), 256>>>();
    k_cm_norm<<<NN * NN, 256>>>();
    k_corr<<<NN * NN * NN, 256>>>();
    k_svsm<<<1, 128>>>();
    k_csa<<<NN, 512>>>();
    k_sort<<<NN, 1024>>>();
    k_gather_split<<<NN * CC, 256>>>();
    k_wsplit<<<(MROWS * HW + 255) / 256, 256>>>(w1, ws);
    k_w2split<<<(OC * K2 + 255) / 256, 256>>>(w2);
    k_gemm_mma<<<dim3(MROWS / 128, CC / 128, NN), 256, 2 * FSTAGE>>>();
    k_xt<<<dim3(50, CC / 32, NN), 256>>>();
    k_conv_mma<<<dim3(13, 1, NN), 256, 2 * CSTG>>>(0, b1, bs, nullptr);
    k_conv_mma<<<dim3(13, 1, NN), 256, 2 * CSTG>>>(1, b2, nullptr, out);
    (void)out_size; (void)n_in;
}

// round 12
// speedup vs baseline: 3.8370x; 1.0216x over previous
#include <cuda_runtime.h>
#include <cuda_bf16.h>
#include <math.h>
#include <stdint.h>

#define NN 10
#define CC 512
#define HW 1600
#define OC 128
#define IMG 40
#define MROWS 1280   // 1152 folded-conv1 rows + 128 shortcut rows
#define K1 4608      // conv1 K = 9*512
#define K2 1152      // conv2 K = 9*128
#define LDT 40

// ---------------- scratch (device globals) ----------------
__device__ float g_NF[NN*CC*HW];
__device__ float g_SIVraw[NN*CC];
__device__ float g_SIV[NN*CC];
__device__ float g_cm[NN*NN*HW];
__device__ float g_corr[NN*NN*NN];
__device__ float g_sv[NN*NN];
__device__ float g_wv[NN*NN];
__device__ float g_CSA[NN*HW];
__device__ int   g_idx[NN*HW];
__device__ __align__(16) __nv_bfloat16 g_Wc_hi[MROWS*HW];
__device__ __align__(16) __nv_bfloat16 g_Wc_lo[MROWS*HW];
__device__ __align__(16) __nv_bfloat16 g_Ag_hi[NN*CC*HW];
__device__ __align__(16) __nv_bfloat16 g_Ag_lo[NN*CC*HW];
__device__ __align__(16) __nv_bfloat16 g_Wk1_hi[NN*OC*K1];
__device__ __align__(16) __nv_bfloat16 g_Wk1_lo[NN*OC*K1];
__device__ __align__(16) __nv_bfloat16 g_Wsc_hi[NN*OC*CC];
__device__ __align__(16) __nv_bfloat16 g_Wsc_lo[NN*OC*CC];
__device__ __align__(16) __nv_bfloat16 g_W2k_hi[OC*K2];
__device__ __align__(16) __nv_bfloat16 g_W2k_lo[OC*K2];
__device__ __align__(16) __nv_bfloat16 g_Xt_hi[NN*HW*CC];
__device__ __align__(16) __nv_bfloat16 g_Xt_lo[NN*HW*CC];
__device__ __align__(16) __nv_bfloat16 g_H1t_hi[NN*HW*OC];
__device__ __align__(16) __nv_bfloat16 g_H1t_lo[NN*HW*OC];
__device__ float g_SC[NN*OC*HW];

// ---------------- helpers ----------------
__device__ __forceinline__ double blockReduceSumD(double v) {
    __shared__ double sh[32];
    int lane = threadIdx.x & 31, wid = threadIdx.x >> 5;
#pragma unroll
    for (int o = 16; o > 0; o >>= 1) v += __shfl_down_sync(0xffffffffu, v, o);
    if (lane == 0) sh[wid] = v;
    __syncthreads();
    if (wid == 0) {
        int nw = blockDim.x >> 5;
        v = (lane < nw) ? sh[lane] : 0.0;
#pragma unroll
        for (int o = 16; o > 0; o >>= 1) v += __shfl_down_sync(0xffffffffu, v, o);
    }
    return v;
}
__device__ __forceinline__ void kadd(float& s, float& c, float p) {
    float y = __fsub_rn(p, c);
    float t = __fadd_rn(s, y);
    c = __fsub_rn(__fsub_rn(t, s), y);
    s = t;
}
__device__ __forceinline__ uint32_t smem_u32(const void* p) {
    uint32_t a;
    asm("{ .reg .u64 t; cvta.to.shared.u64 t, %1; cvt.u32.u64 %0, t; }" : "=r"(a) : "l"(p));
    return a;
}
__device__ __forceinline__ void ldsm_x4(uint32_t& r0, uint32_t& r1, uint32_t& r2, uint32_t& r3, uint32_t a) {
    asm volatile("ldmatrix.sync.aligned.m8n8.x4.shared.b16 {%0,%1,%2,%3}, [%4];"
                 : "=r"(r0), "=r"(r1), "=r"(r2), "=r"(r3) : "r"(a));
}
__device__ __forceinline__ void hmma(float* c, const uint32_t* a, uint32_t b0, uint32_t b1) {
    asm volatile("mma.sync.aligned.m16n8k16.row.col.f32.bf16.bf16.f32 "
                 "{%0,%1,%2,%3},{%4,%5,%6,%7},{%8,%9},{%0,%1,%2,%3};"
                 : "+f"(c[0]), "+f"(c[1]), "+f"(c[2]), "+f"(c[3])
                 : "r"(a[0]), "r"(a[1]), "r"(a[2]), "r"(a[3]), "r"(b0), "r"(b1));
}
__device__ __forceinline__ uint32_t pack_hi2(float a, float b) {
    __nv_bfloat16 ha = __float2bfloat16(a), hb = __float2bfloat16(b);
    return (uint32_t)__bfloat16_as_ushort(ha) | ((uint32_t)__bfloat16_as_ushort(hb) << 16);
}
__device__ __forceinline__ uint32_t pack_lo2(float a, float b) {
    __nv_bfloat16 ha = __float2bfloat16(a), hb = __float2bfloat16(b);
    __nv_bfloat16 la = __float2bfloat16(a - __bfloat162float(ha));
    __nv_bfloat16 lb = __float2bfloat16(b - __bfloat162float(hb));
    return (uint32_t)__bfloat16_as_ushort(la) | ((uint32_t)__bfloat16_as_ushort(lb) << 16);
}

// ---------------- 1: per-pixel L2 norm (8 c-groups x 32 hw) ----------------
__global__ void k_norm(const float* __restrict__ feats) {
    int n = blockIdx.y;
    int tid = threadIdx.x;
    int cg = tid >> 5, kk = tid & 31;
    int hw = blockIdx.x * 32 + kk;
    const float* f = feats + (size_t)n * CC * HW + hw;
    float s = 0.f, comp = 0.f;
    for (int c = cg * 64; c < cg * 64 + 64; c++) {
        float v = f[(size_t)c * HW];
        kadd(s, comp, __fmul_rn(v, v));
    }
    __shared__ double sh[8][32];
    __shared__ float sd[32];
    sh[cg][kk] = (double)s + (double)comp;
    __syncthreads();
    if (tid < 32) {
        double S = 0.0;
#pragma unroll
        for (int g = 0; g < 8; g++) S += sh[g][tid];
        sd[tid] = fmaxf(sqrtf((float)S), 1e-12f);
    }
    __syncthreads();
    float d = sd[kk];
    float* o = g_NF + (size_t)n * CC * HW + hw;
    for (int c = cg * 64; c < cg * 64 + 64; c++)
        o[(size_t)c * HW] = f[(size_t)c * HW] / d;
}

// ---------------- 2: SIV raw ----------------
__global__ void k_siv_raw(const float* __restrict__ sisms) {
    int b = blockIdx.x;
    int n = b >> 9;
    double s = 0.0;
    for (int k = threadIdx.x; k < HW; k += 256) {
        float pm = g_NF[(size_t)b * HW + k] * sisms[n * HW + k];
        s += (double)pm;
    }
    s = blockReduceSumD(s);
    if (threadIdx.x == 0) g_SIVraw[b] = ((float)s) / 1600.0f;
}

// ---------------- 3: SIV l2 norm ----------------
__global__ void k_siv_norm() {
    int n = blockIdx.x, t = threadIdx.x;
    float v = g_SIVraw[n * CC + t];
    float sq = v * v;
    double s = blockReduceSumD((double)sq);
    __shared__ float s_d;
    if (t == 0) s_d = fmaxf(sqrtf((float)s), 1e-12f);
    __syncthreads();
    g_SIV[n * CC + t] = v / s_d;
}

// ---------------- 4: cm (8 c-groups x 32 k) ----------------
__global__ void k_cm() {
    __shared__ float s_siv[NN * CC];
    __shared__ double sh[8][32][NN];
    int n = blockIdx.y;
    int tid = threadIdx.x;
    for (int q = tid; q < NN * CC; q += 256) s_siv[q] = g_SIV[q];
    int cg = tid >> 5, kk = tid & 31;
    int k = blockIdx.x * 32 + kk;
    const float* nfp = g_NF + (size_t)n * CC * HW + k;
    __syncthreads();
    float s[NN], comp[NN];
#pragma unroll
    for (int m = 0; m < NN; m++) { s[m] = 0.f; comp[m] = 0.f; }
    for (int c = cg * 64; c < cg * 64 + 64; c++) {
        float nf = nfp[(size_t)c * HW];
#pragma unroll
        for (int m = 0; m < NN; m++) kadd(s[m], comp[m], __fmul_rn(nf, s_siv[m * CC + c]));
    }
#pragma unroll
    for (int m = 0; m < NN; m++) sh[cg][kk][m] = (double)s[m] + (double)comp[m];
    __syncthreads();
    for (int e = tid; e < 32 * NN; e += 256) {
        int kk2 = e / NN, m = e % NN;
        double v = 0.0;
#pragma unroll
        for (int g = 0; g < 8; g++) v += sh[g][kk2][m];
        g_cm[(size_t)(n * NN + m) * HW + blockIdx.x * 32 + kk2] = (float)v;
    }
}

// ---------------- 5: cm row norm ----------------
__global__ void k_cm_norm() {
    int row = blockIdx.x;
    size_t base = (size_t)row * HW;
    double ss = 0.0;
    for (int k = threadIdx.x; k < HW; k += 256) {
        float v = g_cm[base + k];
        float sq = v * v;
        ss += (double)sq;
    }
    ss = blockReduceSumD(ss);
    __shared__ float s_d;
    if (threadIdx.x == 0) s_d = fmaxf(sqrtf((float)ss), 1e-12f);
    __syncthreads();
    for (int k = threadIdx.x; k < HW; k += 256) g_cm[base + k] = g_cm[base + k] / s_d;
}

// ---------------- 6: corr ----------------
__global__ void k_corr() {
    int b = blockIdx.x;
    int p = b % NN;
    int m = (b / NN) % NN;
    int n = b / (NN * NN);
    double s = 0.0;
    for (int k = threadIdx.x; k < HW; k += 256)
        s += (double)g_cm[(size_t)(n * NN + m) * HW + k] * (double)g_cm[(size_t)(n * NN + p) * HW + k];
    s = blockReduceSumD(s);
    if (threadIdx.x == 0) g_corr[b] = (float)s;
}

// ---------------- 7+8: sv + softmax fused ----------------
__global__ void k_svsm() {
    int t = threadIdx.x;
    if (t < NN * NN) {
        double s = 0.0;
#pragma unroll
        for (int p = 0; p < NN; p++) s += (double)g_corr[t * NN + p];
        g_sv[t] = (float)s;
    }
    __syncthreads();
    int n = t;
    if (n >= NN) return;
    float mx = -1e30f;
    for (int m = 0; m < NN; m++) mx = fmaxf(mx, g_sv[n * NN + m]);
    float e[NN];
    double sum = 0.0;
    for (int m = 0; m < NN; m++) {
        float tt = g_sv[n * NN + m] - mx;
        e[m] = (float)exp((double)tt);
        sum += (double)e[m];
    }
    float S = (float)sum;
    for (int m = 0; m < NN; m++) g_wv[n * NN + m] = e[m] / S;
}

// ---------------- 9: CSA ----------------
__global__ void k_csa() {
    int n = blockIdx.x, tid = threadIdx.x;
    __shared__ float s_wv[NN];
    __shared__ float sc[HW];
    __shared__ float red[512];
    if (tid < NN) s_wv[tid] = g_wv[n * NN + tid];
    __syncthreads();
    float lmin = 1e30f, lmax = -1e30f;
    for (int k = tid; k < HW; k += 512) {
        double a = 0.0;
#pragma unroll
        for (int m = 0; m < NN; m++) {
            float pm = g_cm[(size_t)(n * NN + m) * HW + k] * s_wv[m];
            a += (double)pm;
        }
        float raw = (float)a;
        sc[k] = raw;
        lmin = fminf(lmin, raw); lmax = fmaxf(lmax, raw);
    }
    red[tid] = lmin; __syncthreads();
    for (int s = 256; s > 0; s >>= 1) { if (tid < s) red[tid] = fminf(red[tid], red[tid + s]); __syncthreads(); }
    float mn = red[0]; __syncthreads();
    red[tid] = lmax; __syncthreads();
    for (int s = 256; s > 0; s >>= 1) { if (tid < s) red[tid] = fmaxf(red[tid], red[tid + s]); __syncthreads(); }
    float mx = red[0]; __syncthreads();
    float den = (mx - mn) + 1e-12f;
    for (int k = tid; k < HW; k += 512) {
        float num = sc[k] - mn;
        g_CSA[n * HW + k] = num / den;
    }
}

// ---------------- 10: argsort ----------------
__global__ void k_sort() {
    __shared__ float key[2048];
    __shared__ int   idv[2048];
    int n = blockIdx.x, tid = threadIdx.x;
    for (int e = tid; e < 2048; e += 1024) {
        if (e < HW) { key[e] = g_CSA[n * HW + e]; idv[e] = e; }
        else        { key[e] = -1e30f;            idv[e] = e; }
    }
    __syncthreads();
    for (int k = 2; k <= 2048; k <<= 1) {
        for (int j = k >> 1; j > 0; j >>= 1) {
            for (int e = tid; e < 2048; e += 1024) {
                int ix = e ^ j;
                if (ix > e) {
                    float ka = key[e], kb = key[ix];
                    int ia = idv[e], ib = idv[ix];
                    bool up = ((e & k) == 0);
                    bool b_before_a = (kb > ka) || (kb == ka && ib < ia);
                    bool dosw = up ? b_before_a : !b_before_a;
                    if (dosw) { key[e] = kb; key[ix] = ka; idv[e] = ib; idv[ix] = ia; }
                }
            }
            __syncthreads();
        }
    }
    for (int e = tid; e < HW; e += 1024) g_idx[n * HW + e] = idv[e];
}

// ---------------- 11: gather + bf16 split ----------------
__global__ void k_gather_split() {
    int b = blockIdx.x;
    int n = b >> 9;
    for (int i = threadIdx.x; i < HW; i += 256) {
        float v = g_NF[(size_t)b * HW + g_idx[n * HW + i]];
        __nv_bfloat16 h = __float2bfloat16(v);
        __nv_bfloat16 l = __float2bfloat16(v - __bfloat162float(h));
        g_Ag_hi[(size_t)b * HW + i] = h;
        g_Ag_lo[(size_t)b * HW + i] = l;
    }
}

// ---------------- 12: weight concat + split ----------------
__global__ void k_wsplit(const float* __restrict__ w1, const float* __restrict__ ws) {
    int q = blockIdx.x * 256 + threadIdx.x;
    if (q >= MROWS * HW) return;
    int i = q % HW, r = q / HW;
    float f;
    if (r < OC * 9) {
        int o = r / 9, t = r % 9;
        f = w1[(o * HW + i) * 9 + t];
    } else {
        f = ws[(r - OC * 9) * HW + i];
    }
    __nv_bfloat16 h = __float2bfloat16(f);
    __nv_bfloat16 l = __float2bfloat16(f - __bfloat162float(h));
    g_Wc_hi[q] = h;
    g_Wc_lo[q] = l;
}
__global__ void k_w2split(const float* __restrict__ w2) {
    int q = blockIdx.x * 256 + threadIdx.x;
    if (q >= OC * K2) return;
    int k = q % K2, o = q / K2;
    int t = k / OC, c = k % OC;
    float f = w2[(o * OC + c) * 9 + t];
    __nv_bfloat16 h = __float2bfloat16(f);
    __nv_bfloat16 l = __float2bfloat16(f - __bfloat162float(h));
    g_W2k_hi[q] = h;
    g_W2k_lo[q] = l;
}

// ---------------- 13: fold GEMM, double-buffered, x4 B-fragments ----------------
#define FBUF 10240
#define FSTAGE (4 * FBUF)

__global__ __launch_bounds__(256) void k_gemm_mma() {
    extern __shared__ __align__(16) char dsm[];
    uint32_t base = smem_u32(dsm);
    int n = blockIdx.z;
    int m0 = blockIdx.x * 128, n0 = blockIdx.y * 128;
    const __nv_bfloat16* Bh = g_Ag_hi + (size_t)n * CC * HW;
    const __nv_bfloat16* Bl = g_Ag_lo + (size_t)n * CC * HW;
    int tid = threadIdx.x, lane = tid & 31, wid = tid >> 5;
    int wm = wid & 3, wn = wid >> 2;

    float c[2][8][4];
#pragma unroll
    for (int i = 0; i < 2; i++)
#pragma unroll
        for (int j = 0; j < 8; j++)
#pragma unroll
            for (int q = 0; q < 4; q++) c[i][j][q] = 0.f;

    int lrow = tid >> 1, lk = (tid & 1) * 16;
    const __nv_bfloat16* pAh = g_Wc_hi + (size_t)(m0 + lrow) * HW + lk;
    const __nv_bfloat16* pAl = g_Wc_lo + (size_t)(m0 + lrow) * HW + lk;
    const __nv_bfloat16* pBh = Bh + (size_t)(n0 + lrow) * HW + lk;
    const __nv_bfloat16* pBl = Bl + (size_t)(n0 + lrow) * HW + lk;
    uint32_t so = (uint32_t)(lrow * LDT + lk) * 2;
    int arow = (lane & 15), akoff = 8 * (lane >> 4);
    // B x4 lane addressing: lanes 0-7 -> col group 0 k-low, 8-15 -> col group 0 k-high,
    //                       16-23 -> col group 1 k-low, 24-31 -> col group 1 k-high
    int bcol = 8 * ((lane >> 4) & 1) + (lane & 7);
    int bko  = 8 * ((lane >> 3) & 1);

    uint4 r0, r1, r2, r3, r4, r5, r6, r7;
#define FLD(k0) do { \
    r0 = *(const uint4*)(pAh + (k0)); r1 = *(const uint4*)(pAh + (k0) + 8); \
    r2 = *(const uint4*)(pAl + (k0)); r3 = *(const uint4*)(pAl + (k0) + 8); \
    r4 = *(const uint4*)(pBh + (k0)); r5 = *(const uint4*)(pBh + (k0) + 8); \
    r6 = *(const uint4*)(pBl + (k0)); r7 = *(const uint4*)(pBl + (k0) + 8); } while (0)
#define FST(s) do { \
    char* sb_ = dsm + (s) * FSTAGE; \
    *(uint4*)(sb_ + so) = r0;            *(uint4*)(sb_ + so + 16) = r1; \
    *(uint4*)(sb_ + FBUF + so) = r2;     *(uint4*)(sb_ + FBUF + so + 16) = r3; \
    *(uint4*)(sb_ + 2*FBUF + so) = r4;   *(uint4*)(sb_ + 2*FBUF + so + 16) = r5; \
    *(uint4*)(sb_ + 3*FBUF + so) = r6;   *(uint4*)(sb_ + 3*FBUF + so + 16) = r7; } while (0)

    FLD(0);
    FST(0);
    __syncthreads();
    for (int kb = 0; kb < 50; kb++) {
        bool more = (kb + 1 < 50);
        if (more) FLD((kb + 1) * 32);
        uint32_t uAh = base + (kb & 1) * FSTAGE;
        uint32_t uAl = uAh + FBUF, uBh = uAh + 2 * FBUF, uBl = uAh + 3 * FBUF;
#pragma unroll
        for (int kk = 0; kk < 32; kk += 16) {
            uint32_t ah[2][4], al[2][4];
#pragma unroll
            for (int i = 0; i < 2; i++) {
                uint32_t ao = (uint32_t)((32 * wm + 16 * i + arow) * LDT + kk + akoff) * 2;
                ldsm_x4(ah[i][0], ah[i][1], ah[i][2], ah[i][3], uAh + ao);
                ldsm_x4(al[i][0], al[i][1], al[i][2], al[i][3], uAl + ao);
            }
#pragma unroll
            for (int jp = 0; jp < 8; jp += 2) {
                uint32_t bo = (uint32_t)((64 * wn + 8 * jp + bcol) * LDT + kk + bko) * 2;
                uint32_t bh0, bh1, bh2, bh3, bl0, bl1, bl2, bl3;
                ldsm_x4(bh0, bh1, bh2, bh3, uBh + bo);
                ldsm_x4(bl0, bl1, bl2, bl3, uBl + bo);
#pragma unroll
                for (int i = 0; i < 2; i++) {
                    hmma(c[i][jp], ah[i], bh0, bh1);
                    hmma(c[i][jp], ah[i], bl0, bl1);
                    hmma(c[i][jp], al[i], bh0, bh1);
                    hmma(c[i][jp + 1], ah[i], bh2, bh3);
                    hmma(c[i][jp + 1], ah[i], bl2, bl3);
                    hmma(c[i][jp + 1], al[i], bh2, bh3);
                }
            }
        }
        if (more) FST((kb + 1) & 1);
        __syncthreads();
    }
#undef FLD
#undef FST
#pragma unroll
    for (int i = 0; i < 2; i++) {
        int rb = m0 + 32 * wm + 16 * i + (lane >> 2);
#pragma unroll
        for (int half = 0; half < 2; half++) {
            int r = rb + half * 8;
#pragma unroll
            for (int j = 0; j < 8; j++) {
                int col = n0 + 64 * wn + 8 * j + (lane & 3) * 2;
                float v0 = c[i][j][half * 2], v1 = c[i][j][half * 2 + 1];
                size_t off;
                __nv_bfloat16 *dh, *dl;
                if (r < OC * 9) {
                    int o = r / 9, t = r % 9;
                    off = ((size_t)n * OC + o) * K1 + t * CC + col;
                    dh = g_Wk1_hi; dl = g_Wk1_lo;
                } else {
                    int o = r - OC * 9;
                    off = ((size_t)n * OC + o) * CC + col;
                    dh = g_Wsc_hi; dl = g_Wsc_lo;
                }
                *(uint32_t*)(dh + off) = pack_hi2(v0, v1);
                *(uint32_t*)(dl + off) = pack_lo2(v0, v1);
            }
        }
    }
}

// ---------------- 14: Xt = (NF*CSA)^T split ----------------
__global__ void k_xt() {
    __shared__ float sT[32][33];
    int n = blockIdx.z;
    int p0 = blockIdx.x * 32, c0 = blockIdx.y * 32;
    int tid = threadIdx.x;
    int tc = tid >> 5, tp = tid & 31;
#pragma unroll
    for (int r = 0; r < 4; r++) {
        int c = c0 + tc + r * 8;
        sT[tc + r * 8][tp] = g_NF[((size_t)n * CC + c) * HW + p0 + tp] * g_CSA[n * HW + p0 + tp];
    }
    __syncthreads();
#pragma unroll
    for (int r = 0; r < 4; r++) {
        int p = p0 + tc + r * 8;
        float v = sT[tp][tc + r * 8];
        __nv_bfloat16 h = __float2bfloat16(v);
        __nv_bfloat16 l = __float2bfloat16(v - __bfloat162float(h));
        g_Xt_hi[((size_t)n * HW + p) * CC + c0 + tp] = h;
        g_Xt_lo[((size_t)n * HW + p) * CC + c0 + tp] = l;
    }
}

// ---------------- 15: conv via mma.sync bf16x3 (128x128, x4 B-fragments) --------
#define CBUF 10240
#define CSTG (4 * CBUF)   // Ah Al Bh Bl

__global__ __launch_bounds__(256) void k_conv_mma(int mode, const float* __restrict__ bias,
                                                  const float* __restrict__ bsc,
                                                  float* __restrict__ dout) {
    extern __shared__ __align__(16) char dsm[];
    uint32_t base = smem_u32(dsm);
    int n = blockIdx.z;
    int p0 = blockIdx.x * 128;
    int tid = threadIdx.x, lane = tid & 31, wid = tid >> 5;
    int wm = wid & 3, wn = wid >> 2;       // warp tile 32 o x 64 p

    const __nv_bfloat16 *Ah, *Al, *Bh, *Bl;
    int K, Cin, nslab;
    if (mode == 0) {
        Ah = g_Wk1_hi + (size_t)n * OC * K1; Al = g_Wk1_lo + (size_t)n * OC * K1;
        Bh = g_Xt_hi + (size_t)n * HW * CC;  Bl = g_Xt_lo + (size_t)n * HW * CC;
        K = K1; Cin = CC; nslab = K1 / 32;
    } else {
        Ah = g_W2k_hi; Al = g_W2k_lo;
        Bh = g_H1t_hi + (size_t)n * HW * OC; Bl = g_H1t_lo + (size_t)n * HW * OC;
        K = K2; Cin = OC; nslab = K2 / 32;
    }
    int slabs_per_tap = Cin / 32;

    int lrow = tid >> 1, lk = (tid & 1) * 16;
    int bp = p0 + lrow;
    bool prow = (bp < HW);
    int bpx = bp % IMG, bpy = bp / IMG;
    int arow = (lane & 15), akoff = 8 * (lane >> 4);
    int bcol = 8 * ((lane >> 4) & 1) + (lane & 7);
    int bko  = 8 * ((lane >> 3) & 1);
    uint32_t so = (uint32_t)(lrow * LDT + lk) * 2;

    float c[2][8][4];
#pragma unroll
    for (int i = 0; i < 2; i++)
#pragma unroll
        for (int j = 0; j < 8; j++)
#pragma unroll
            for (int q = 0; q < 4; q++) c[i][j][q] = 0.f;

    uint4 ra0, ra1, ra2, ra3, rb0, rb1, rb2, rb3;
#define CLD(kb) do { \
    int t_ = (kb) / slabs_per_tap, c0_ = ((kb) % slabs_per_tap) * 32; \
    int dy_ = t_ / 3 - 1, dx_ = t_ % 3 - 1, off_ = dy_ * IMG + dx_; \
    bool valid_ = prow && ((unsigned)(bpx + dx_) < (unsigned)IMG) && ((unsigned)(bpy + dy_) < (unsigned)IMG); \
    size_t gA_ = (size_t)lrow * K + (kb) * 32 + lk; \
    ra0 = *(const uint4*)(Ah + gA_); ra1 = *(const uint4*)(Ah + gA_ + 8); \
    ra2 = *(const uint4*)(Al + gA_); ra3 = *(const uint4*)(Al + gA_ + 8); \
    rb0 = make_uint4(0,0,0,0); rb1 = rb0; rb2 = rb0; rb3 = rb0; \
    if (valid_) { \
        size_t gB_ = (size_t)(bp + off_) * Cin + c0_ + lk; \
        rb0 = *(const uint4*)(Bh + gB_); rb1 = *(const uint4*)(Bh + gB_ + 8); \
        rb2 = *(const uint4*)(Bl + gB_); rb3 = *(const uint4*)(Bl + gB_ + 8); \
    } } while (0)
#define CST(s) do { \
    char* sb_ = dsm + (s) * CSTG; \
    *(uint4*)(sb_ + so) = ra0;            *(uint4*)(sb_ + so + 16) = ra1; \
    *(uint4*)(sb_ + CBUF + so) = ra2;     *(uint4*)(sb_ + CBUF + so + 16) = ra3; \
    *(uint4*)(sb_ + 2*CBUF + so) = rb0;   *(uint4*)(sb_ + 2*CBUF + so + 16) = rb1; \
    *(uint4*)(sb_ + 3*CBUF + so) = rb2;   *(uint4*)(sb_ + 3*CBUF + so + 16) = rb3; } while (0)
#define CCOMPUTE(s) do { \
    uint32_t uAh_ = base + (s) * CSTG; \
    uint32_t uAl_ = uAh_ + CBUF, uBh_ = uAh_ + 2*CBUF, uBl_ = uAh_ + 3*CBUF; \
    _Pragma("unroll") \
    for (int kk = 0; kk < 32; kk += 16) { \
        uint32_t ah[2][4], al[2][4]; \
        _Pragma("unroll") \
        for (int i = 0; i < 2; i++) { \
            uint32_t ao = (uint32_t)((32 * wm + 16 * i + arow) * LDT + kk + akoff) * 2; \
            ldsm_x4(ah[i][0], ah[i][1], ah[i][2], ah[i][3], uAh_ + ao); \
            ldsm_x4(al[i][0], al[i][1], al[i][2], al[i][3], uAl_ + ao); \
        } \
        _Pragma("unroll") \
        for (int jp = 0; jp < 8; jp += 2) { \
            uint32_t bo = (uint32_t)((64 * wn + 8 * jp + bcol) * LDT + kk + bko) * 2; \
            uint32_t bh0, bh1, bh2, bh3, bl0, bl1, bl2, bl3; \
            ldsm_x4(bh0, bh1, bh2, bh3, uBh_ + bo); \
            ldsm_x4(bl0, bl1, bl2, bl3, uBl_ + bo); \
            _Pragma("unroll") \
            for (int i = 0; i < 2; i++) { \
                hmma(c[i][jp], ah[i], bh0, bh1); \
                hmma(c[i][jp], ah[i], bl0, bl1); \
                hmma(c[i][jp], al[i], bh0, bh1); \
                hmma(c[i][jp + 1], ah[i], bh2, bh3); \
                hmma(c[i][jp + 1], ah[i], bl2, bl3); \
                hmma(c[i][jp + 1], al[i], bh2, bh3); \
            } \
        } \
    } } while (0)

    CLD(0);
    CST(0);
    __syncthreads();
    for (int kb = 0; kb < nslab; kb++) {
        bool more = (kb + 1 < nslab);
        if (more) CLD(kb + 1);
        CCOMPUTE(kb & 1);
        if (more) CST((kb + 1) & 1);
        __syncthreads();
    }
    // epilogue phase 1
#pragma unroll
    for (int i = 0; i < 2; i++) {
        int rb = 32 * wm + 16 * i + (lane >> 2);
#pragma unroll
        for (int half = 0; half < 2; half++) {
            int o = rb + half * 8;
            float bo = bias[o];
#pragma unroll
            for (int j = 0; j < 8; j++) {
                int p = p0 + 64 * wn + 8 * j + (lane & 3) * 2;
                if (p >= HW) continue;
                float v0 = c[i][j][half * 2] + bo, v1 = c[i][j][half * 2 + 1] + bo;
                if (mode == 0) {
                    float a = fmaxf(v0, 0.f), b2 = fmaxf(v1, 0.f);
                    __nv_bfloat16 ha = __float2bfloat16(a);
                    __nv_bfloat16 la = __float2bfloat16(a - __bfloat162float(ha));
                    __nv_bfloat16 hb = __float2bfloat16(b2);
                    __nv_bfloat16 lb = __float2bfloat16(b2 - __bfloat162float(hb));
                    size_t b0 = ((size_t)n * HW + p) * OC + o;
                    g_H1t_hi[b0] = ha; g_H1t_lo[b0] = la;
                    g_H1t_hi[b0 + OC] = hb; g_H1t_lo[b0 + OC] = lb;
                } else {
                    float2 sc = *(const float2*)&g_SC[((size_t)n * OC + o) * HW + p];
                    *(float2*)&dout[((size_t)n * OC + o) * HW + p] =
                        make_float2(fmaxf(v0 + sc.x, 0.f), fmaxf(v1 + sc.y, 0.f));
                }
            }
        }
    }
    if (mode != 0) return;

    // ---- phase 2: 1x1 shortcut (K=512) ----
#pragma unroll
    for (int i = 0; i < 2; i++)
#pragma unroll
        for (int j = 0; j < 8; j++)
#pragma unroll
            for (int q = 0; q < 4; q++) c[i][j][q] = 0.f;
    const __nv_bfloat16* Sh = g_Wsc_hi + (size_t)n * OC * CC;
    const __nv_bfloat16* Sl = g_Wsc_lo + (size_t)n * OC * CC;
#define SLD(kb) do { \
    size_t gA_ = (size_t)lrow * CC + (kb) * 32 + lk; \
    ra0 = *(const uint4*)(Sh + gA_); ra1 = *(const uint4*)(Sh + gA_ + 8); \
    ra2 = *(const uint4*)(Sl + gA_); ra3 = *(const uint4*)(Sl + gA_ + 8); \
    rb0 = make_uint4(0,0,0,0); rb1 = rb0; rb2 = rb0; rb3 = rb0; \
    if (prow) { \
        size_t gB_ = (size_t)bp * CC + (kb) * 32 + lk; \
        rb0 = *(const uint4*)(Bh + gB_); rb1 = *(const uint4*)(Bh + gB_ + 8); \
        rb2 = *(const uint4*)(Bl + gB_); rb3 = *(const uint4*)(Bl + gB_ + 8); \
    } } while (0)

    __syncthreads();
    SLD(0);
    CST(0);
    __syncthreads();
    for (int kb = 0; kb < CC / 32; kb++) {
        bool more = (kb + 1 < CC / 32);
        if (more) SLD(kb + 1);
        CCOMPUTE(kb & 1);
        if (more) CST((kb + 1) & 1);
        __syncthreads();
    }
#undef SLD
#undef CLD
#undef CST
#undef CCOMPUTE
#pragma unroll
    for (int i = 0; i < 2; i++) {
        int rb = 32 * wm + 16 * i + (lane >> 2);
#pragma unroll
        for (int half = 0; half < 2; half++) {
            int o = rb + half * 8;
            float bo = bsc[o];
#pragma unroll
            for (int j = 0; j < 8; j++) {
                int p = p0 + 64 * wn + 8 * j + (lane & 3) * 2;
                if (p >= HW) continue;
                *(float2*)&g_SC[((size_t)n * OC + o) * HW + p] =
                    make_float2(c[i][j][half * 2] + bo, c[i][j][half * 2 + 1] + bo);
            }
        }
    }
}

// ---------------- launch ----------------
extern "C" void kernel_launch(void* const* d_in, const int* in_sizes, int n_in,
                              void* d_out, int out_size) {
    const float *feats = nullptr, *sisms = nullptr, *w1 = nullptr, *w2 = nullptr, *ws = nullptr;
    const float *b1 = nullptr, *b2 = nullptr, *bs = nullptr;
    for (int i = 0; i < n_in; i++) {
        int s = in_sizes[i];
        const float* p = (const float*)d_in[i];
        if (s == NN * CC * HW) feats = p;
        else if (s == NN * HW) sisms = p;
        else if (s == OC * HW * 9) w1 = p;
        else if (s == OC * OC * 9) w2 = p;
        else if (s == OC * HW) ws = p;
        else if (s == OC) { if (!b1) b1 = p; else if (!b2) b2 = p; else bs = p; }
    }
    float* out = (float*)d_out;

    static int attr_set = 0;
    if (!attr_set) {
        cudaFuncSetAttribute(k_gemm_mma, cudaFuncAttributeMaxDynamicSharedMemorySize, 2 * FSTAGE);
        cudaFuncSetAttribute(k_conv_mma, cudaFuncAttributeMaxDynamicSharedMemorySize, 2 * CSTG);
        attr_set = 1;
    }

    k_norm<<<dim3(50, NN), 256>>>(feats);
    k_siv_raw<<<NN * CC, 256>>>(sisms);
    k_siv_norm<<<NN, CC>>>();
    k_cm<<<dim3(50, NN), 256>>>();
    k_cm_norm<<<NN * NN, 256>>>();
    k_corr<<<NN * NN * NN, 256>>>();
    k_svsm<<<1, 128>>>();
    k_csa<<<NN, 512>>>();
    k_sort<<<NN, 1024>>>();
    k_gather_split<<<NN * CC, 256>>>();
    k_wsplit<<<(MROWS * HW + 255) / 256, 256>>>(w1, ws);
    k_w2split<<<(OC * K2 + 255) / 256, 256>>>(w2);
    k_gemm_mma<<<dim3(MROWS / 128, CC / 128, NN), 256, 2 * FSTAGE>>>();
    k_xt<<<dim3(50, CC / 32, NN), 256>>>();
    k_conv_mma<<<dim3(13, 1, NN), 256, 2 * CSTG>>>(0, b1, bs, nullptr);
    k_conv_mma<<<dim3(13, 1, NN), 256, 2 * CSTG>>>(1, b2, nullptr, out);
    (void)out_size; (void)n_in;
}